// round 1
// baseline (speedup 1.0000x reference)
#include <cuda_runtime.h>
#include <math.h>

#define NN     20000
#define INC    512
#define HID1   512      // H1*HID = 8*64
#define OUTC   256
#define NE     320000
#define NTOT   (NE + NN)   // edges + self loops = 340000
#define NEGS   0.2f

// ---------------- scratch (device globals: no allocation allowed) ----------------
__device__ float g_h1[(size_t)NN * HID1];     // x @ W1
__device__ float g_out1[(size_t)NN * HID1];   // layer1 output (post bias+elu)
__device__ float g_h2[(size_t)NN * OUTC];     // out1 @ W2
__device__ float g_as1[NN * 8];
__device__ float g_ad1[NN * 8];
__device__ float g_as2[NN];
__device__ float g_ad2[NN];
__device__ int   g_deg[NN];
__device__ int   g_offs[NN + 1];
__device__ int   g_cursor[NN];
__device__ int   g_csr[NTOT];

// ---------------- helpers ----------------
__device__ __forceinline__ float warp_sum(float v) {
#pragma unroll
    for (int o = 16; o; o >>= 1) v += __shfl_xor_sync(0xffffffffu, v, o);
    return v;
}
__device__ __forceinline__ float warp_max(float v) {
#pragma unroll
    for (int o = 16; o; o >>= 1) v = fmaxf(v, __shfl_xor_sync(0xffffffffu, v, o));
    return v;
}
// monotonic float<->uint encoding for atomicMax
__device__ __forceinline__ unsigned fenc(float f) {
    unsigned u = __float_as_uint(f);
    return (u >> 31) ? ~u : (u | 0x80000000u);
}
__device__ __forceinline__ float fdec(unsigned u) {
    return __uint_as_float((u >> 31) ? (u & 0x7fffffffu) : ~u);
}
__device__ __forceinline__ float lrelu(float a) { return a > 0.f ? a : NEGS * a; }

// ---------------- CSR build ----------------
__global__ void zero_deg_kernel() {
    int i = blockIdx.x * blockDim.x + threadIdx.x;
    if (i < NN) g_deg[i] = 0;
}
__global__ void deg_kernel(const int* __restrict__ ei) {
    int i = blockIdx.x * blockDim.x + threadIdx.x;
    if (i < NTOT) {
        int d = (i < NE) ? ei[NE + i] : (i - NE);
        atomicAdd(&g_deg[d], 1);
    }
}
__global__ void scan_kernel() {
    __shared__ int s[1024];
    __shared__ int carry;
    if (threadIdx.x == 0) { carry = 0; g_offs[0] = 0; }
    __syncthreads();
    for (int base = 0; base < NN; base += 1024) {
        int i = base + threadIdx.x;
        int v = (i < NN) ? g_deg[i] : 0;
        s[threadIdx.x] = v;
        __syncthreads();
#pragma unroll
        for (int off = 1; off < 1024; off <<= 1) {
            int t = 0;
            if (threadIdx.x >= off) t = s[threadIdx.x - off];
            __syncthreads();
            if (threadIdx.x >= off) s[threadIdx.x] += t;
            __syncthreads();
        }
        int cur = carry;
        if (i < NN) g_offs[i + 1] = cur + s[threadIdx.x];
        __syncthreads();
        if (threadIdx.x == 0) carry = cur + s[1023];
        __syncthreads();
    }
}
__global__ void cursor_kernel() {
    int i = blockIdx.x * blockDim.x + threadIdx.x;
    if (i < NN) g_cursor[i] = g_offs[i];
}
__global__ void scatter_kernel(const int* __restrict__ ei) {
    int i = blockIdx.x * blockDim.x + threadIdx.x;
    if (i < NTOT) {
        int s, d;
        if (i < NE) { s = ei[i]; d = ei[NE + i]; }
        else        { s = d = i - NE; }
        int p = atomicAdd(&g_cursor[d], 1);
        g_csr[p] = s;
    }
}

// ---------------- fp32 tiled GEMM: C[M,N] = A[M,K] @ B[K,N] ----------------
// 64x64 block tile, BK=16, 256 threads, 4x4 per-thread microtile.
// Requires N%64==0, K%16==0, K%4==0, N%4==0. M guarded.
__global__ void gemm_kernel(const float* __restrict__ A, const float* __restrict__ B,
                            float* __restrict__ C, int M, int N, int K) {
    __shared__ float As[16][64];
    __shared__ float Bs[16][64];
    int tid = threadIdx.x;
    int tx = tid & 15, ty = tid >> 4;
    int rowBase = blockIdx.y * 64;
    int colBase = blockIdx.x * 64;
    int aRow = tid >> 2;           // 0..63
    int aCol = (tid & 3) << 2;     // 0,4,8,12
    int bRow = tid >> 4;           // 0..15
    int bCol = (tid & 15) << 2;    // 0..60
    float acc[4][4] = {};
    for (int k0 = 0; k0 < K; k0 += 16) {
        float4 av = make_float4(0.f, 0.f, 0.f, 0.f);
        int gr = rowBase + aRow;
        if (gr < M) av = *(const float4*)(A + (size_t)gr * K + k0 + aCol);
        As[aCol + 0][aRow] = av.x;
        As[aCol + 1][aRow] = av.y;
        As[aCol + 2][aRow] = av.z;
        As[aCol + 3][aRow] = av.w;
        float4 bv = *(const float4*)(B + (size_t)(k0 + bRow) * N + colBase + bCol);
        *(float4*)&Bs[bRow][bCol] = bv;
        __syncthreads();
#pragma unroll
        for (int kk = 0; kk < 16; kk++) {
            float4 a = *(const float4*)&As[kk][ty << 2];
            float4 b = *(const float4*)&Bs[kk][tx << 2];
            acc[0][0] += a.x * b.x; acc[0][1] += a.x * b.y; acc[0][2] += a.x * b.z; acc[0][3] += a.x * b.w;
            acc[1][0] += a.y * b.x; acc[1][1] += a.y * b.y; acc[1][2] += a.y * b.z; acc[1][3] += a.y * b.w;
            acc[2][0] += a.z * b.x; acc[2][1] += a.z * b.y; acc[2][2] += a.z * b.z; acc[2][3] += a.z * b.w;
            acc[3][0] += a.w * b.x; acc[3][1] += a.w * b.y; acc[3][2] += a.w * b.z; acc[3][3] += a.w * b.w;
        }
        __syncthreads();
    }
#pragma unroll
    for (int i = 0; i < 4; i++) {
        int r = rowBase + (ty << 2) + i;
        if (r < M) {
            float4 o = make_float4(acc[i][0], acc[i][1], acc[i][2], acc[i][3]);
            *(float4*)(C + (size_t)r * N + colBase + (tx << 2)) = o;
        }
    }
}

// ---------------- per-node attention logits ----------------
// layer1: warp per node, 8 heads of 64 channels
__global__ void alpha1_kernel(const float* __restrict__ asrc, const float* __restrict__ adst) {
    int gw = (blockIdx.x * blockDim.x + threadIdx.x) >> 5;
    int lane = threadIdx.x & 31;
    if (gw >= NN) return;
    const float* hr = g_h1 + (size_t)gw * HID1;
#pragma unroll
    for (int hd = 0; hd < 8; hd++) {
        int c0 = hd * 64 + lane, c1 = c0 + 32;
        float h0 = hr[c0], h1v = hr[c1];
        float vs = h0 * asrc[c0] + h1v * asrc[c1];
        float vd = h0 * adst[c0] + h1v * adst[c1];
        vs = warp_sum(vs);
        vd = warp_sum(vd);
        if (lane == 0) { g_as1[gw * 8 + hd] = vs; g_ad1[gw * 8 + hd] = vd; }
    }
}
// layer2: warp per node, single head of 256 channels
__global__ void alpha2_kernel(const float* __restrict__ asrc, const float* __restrict__ adst) {
    int gw = (blockIdx.x * blockDim.x + threadIdx.x) >> 5;
    int lane = threadIdx.x & 31;
    if (gw >= NN) return;
    const float* hr = g_h2 + (size_t)gw * OUTC;
    float vs = 0.f, vd = 0.f;
#pragma unroll
    for (int c = 0; c < OUTC; c += 32) {
        float hv = hr[c + lane];
        vs += hv * asrc[c + lane];
        vd += hv * adst[c + lane];
    }
    vs = warp_sum(vs);
    vd = warp_sum(vd);
    if (lane == 0) { g_as2[gw] = vs; g_ad2[gw] = vd; }
}

// ---------------- layer1 aggregation: fused segment softmax + gather + bias + elu ----------------
// one block (256 thr) per dst node; each thread owns channels tid and tid+256
__global__ void agg1_kernel(const float* __restrict__ bias) {
    int n = blockIdx.x;
    int tid = threadIdx.x;
    int beg = g_offs[n], end = g_offs[n + 1];

    __shared__ float s_ad[8];
    __shared__ unsigned s_maxi[8];
    __shared__ float s_max[8];
    __shared__ float s_sum[8];
    __shared__ int   s_src[32];
    __shared__ float s_coef[32][8];

    if (tid < 8) {
        s_ad[tid] = g_ad1[n * 8 + tid];
        s_maxi[tid] = 0x007FFFFFu;   // fenc(-inf)
        s_sum[tid] = 0.f;
    }
    __syncthreads();

    // pass 1: per-head max of leaky_relu(as[src]+ad[dst])
    float lmax[8];
#pragma unroll
    for (int h = 0; h < 8; h++) lmax[h] = -INFINITY;
    for (int e = beg + tid; e < end; e += 256) {
        int s = g_csr[e];
#pragma unroll
        for (int h = 0; h < 8; h++) {
            float a = lrelu(g_as1[s * 8 + h] + s_ad[h]);
            lmax[h] = fmaxf(lmax[h], a);
        }
    }
#pragma unroll
    for (int h = 0; h < 8; h++) atomicMax(&s_maxi[h], fenc(lmax[h]));
    __syncthreads();
    if (tid < 8) s_max[tid] = fdec(s_maxi[tid]);
    __syncthreads();

    // pass 2: per-head sum of exp(a - max)
    float lsum[8];
#pragma unroll
    for (int h = 0; h < 8; h++) lsum[h] = 0.f;
    for (int e = beg + tid; e < end; e += 256) {
        int s = g_csr[e];
#pragma unroll
        for (int h = 0; h < 8; h++) {
            float a = lrelu(g_as1[s * 8 + h] + s_ad[h]);
            lsum[h] += expf(a - s_max[h]);
        }
    }
#pragma unroll
    for (int h = 0; h < 8; h++) atomicAdd(&s_sum[h], lsum[h]);
    __syncthreads();
    if (tid < 8) s_sum[tid] = 1.f / (s_sum[tid] + 1e-16f);
    __syncthreads();

    // pass 3: weighted gather-sum, chunked coefficient staging
    float acc0 = 0.f, acc1 = 0.f;
    int c0 = tid, c1 = tid + 256;
    int h0 = c0 >> 6, h1 = c1 >> 6;
    for (int cb = beg; cb < end; cb += 32) {
        int cn = end - cb; if (cn > 32) cn = 32;
        int el = tid >> 3, hh = tid & 7;
        if (el < cn) {
            int s = g_csr[cb + el];
            float a = lrelu(g_as1[s * 8 + hh] + s_ad[hh]);
            s_coef[el][hh] = expf(a - s_max[hh]) * s_sum[hh];
            if (hh == 0) s_src[el] = s;
        }
        __syncthreads();
        for (int e = 0; e < cn; e++) {
            const float* row = g_h1 + (size_t)s_src[e] * HID1;
            acc0 += row[c0] * s_coef[e][h0];
            acc1 += row[c1] * s_coef[e][h1];
        }
        __syncthreads();
    }
    float o0 = acc0 + bias[c0];
    float o1 = acc1 + bias[c1];
    g_out1[(size_t)n * HID1 + c0] = o0 > 0.f ? o0 : expm1f(o0);
    g_out1[(size_t)n * HID1 + c1] = o1 > 0.f ? o1 : expm1f(o1);
}

// ---------------- layer2 aggregation: single head, 256 channels ----------------
__global__ void agg2_kernel(const float* __restrict__ bias, float* __restrict__ out) {
    int n = blockIdx.x;
    int tid = threadIdx.x;
    int beg = g_offs[n], end = g_offs[n + 1];

    __shared__ float s_ad;
    __shared__ unsigned s_maxi;
    __shared__ float s_max;
    __shared__ float s_sum;
    __shared__ int   s_src[64];
    __shared__ float s_coef[64];

    if (tid == 0) {
        s_ad = g_ad2[n];
        s_maxi = 0x007FFFFFu;
        s_sum = 0.f;
    }
    __syncthreads();

    float lmax = -INFINITY;
    for (int e = beg + tid; e < end; e += 256) {
        float a = lrelu(g_as2[g_csr[e]] + s_ad);
        lmax = fmaxf(lmax, a);
    }
    atomicMax(&s_maxi, fenc(lmax));
    __syncthreads();
    if (tid == 0) s_max = fdec(s_maxi);
    __syncthreads();

    float lsum = 0.f;
    for (int e = beg + tid; e < end; e += 256) {
        float a = lrelu(g_as2[g_csr[e]] + s_ad);
        lsum += expf(a - s_max);
    }
    atomicAdd(&s_sum, lsum);
    __syncthreads();
    if (tid == 0) s_sum = 1.f / (s_sum + 1e-16f);
    __syncthreads();

    float acc = 0.f;
    for (int cb = beg; cb < end; cb += 64) {
        int cn = end - cb; if (cn > 64) cn = 64;
        if (tid < cn) {
            int s = g_csr[cb + tid];
            float a = lrelu(g_as2[s] + s_ad);
            s_coef[tid] = expf(a - s_max) * s_sum;
            s_src[tid] = s;
        }
        __syncthreads();
        for (int e = 0; e < cn; e++) {
            acc += g_h2[(size_t)s_src[e] * OUTC + tid] * s_coef[e];
        }
        __syncthreads();
    }
    out[(size_t)n * OUTC + tid] = acc + bias[tid];
}

// ---------------- log softmax over rows of [NN, 256] (in-place) ----------------
__global__ void logsoftmax_kernel(float* __restrict__ out) {
    int n = blockIdx.x, tid = threadIdx.x;
    __shared__ float shm[8];
    __shared__ float shs[8];
    float v = out[(size_t)n * OUTC + tid];
    float wm = warp_max(v);
    if ((tid & 31) == 0) shm[tid >> 5] = wm;
    __syncthreads();
    float m = shm[0];
#pragma unroll
    for (int i = 1; i < 8; i++) m = fmaxf(m, shm[i]);
    float ex = expf(v - m);
    float ws = warp_sum(ex);
    if ((tid & 31) == 0) shs[tid >> 5] = ws;
    __syncthreads();
    float s = 0.f;
#pragma unroll
    for (int i = 0; i < 8; i++) s += shs[i];
    out[(size_t)n * OUTC + tid] = v - m - logf(s);
}

// ---------------- launch ----------------
extern "C" void kernel_launch(void* const* d_in, const int* in_sizes, int n_in,
                              void* d_out, int out_size) {
    const float* x    = (const float*)d_in[0];
    const int*   ei   = (const int*)d_in[1];
    const float* W1   = (const float*)d_in[2];
    const float* as1  = (const float*)d_in[3];
    const float* ad1  = (const float*)d_in[4];
    const float* b1   = (const float*)d_in[5];
    const float* W2   = (const float*)d_in[6];
    const float* as2  = (const float*)d_in[7];
    const float* ad2  = (const float*)d_in[8];
    const float* b2   = (const float*)d_in[9];
    float* out = (float*)d_out;

    float *p_h1, *p_out1, *p_h2;
    cudaGetSymbolAddress((void**)&p_h1, g_h1);
    cudaGetSymbolAddress((void**)&p_out1, g_out1);
    cudaGetSymbolAddress((void**)&p_h2, g_h2);

    // CSR build (edges change each call in principle; rebuild every launch)
    zero_deg_kernel<<<(NN + 255) / 256, 256>>>();
    deg_kernel<<<(NTOT + 255) / 256, 256>>>(ei);
    scan_kernel<<<1, 1024>>>();
    cursor_kernel<<<(NN + 255) / 256, 256>>>();
    scatter_kernel<<<(NTOT + 255) / 256, 256>>>(ei);

    // layer 1
    gemm_kernel<<<dim3(HID1 / 64, (NN + 63) / 64), 256>>>(x, W1, p_h1, NN, HID1, INC);
    alpha1_kernel<<<(NN + 7) / 8, 256>>>(as1, ad1);
    agg1_kernel<<<NN, 256>>>(b1);

    // layer 2
    gemm_kernel<<<dim3(OUTC / 64, (NN + 63) / 64), 256>>>(p_out1, W2, p_h2, NN, OUTC, HID1);
    alpha2_kernel<<<(NN + 7) / 8, 256>>>(as2, ad2);
    agg2_kernel<<<NN, 256>>>(b2, out);

    // log softmax
    logsoftmax_kernel<<<NN, 256>>>(out);
}

// round 2
// speedup vs baseline: 1.1641x; 1.1641x over previous
#include <cuda_runtime.h>
#include <cuda_bf16.h>
#include <math.h>
#include <stdint.h>

#define NN     20000
#define INC    512
#define HID1   512      // H1*HID = 8*64
#define OUTC   256
#define NE     320000
#define NTOT   (NE + NN)   // edges + self loops = 340000
#define NEGS   0.2f
#define KSPLIT 1536        // 3 * 512 (hi | lo | hi blocks along K)

// ---------------- scratch (device globals: no allocation allowed) ----------------
__device__ float g_h1[(size_t)NN * HID1];     // layer1 GEMM output (fp32)
__device__ float g_out1[(size_t)NN * HID1];   // layer1 output (post bias+elu)
__device__ float g_h2[(size_t)NN * OUTC];     // layer2 GEMM output
__device__ __nv_bfloat16 g_xs[(size_t)NN * KSPLIT];    // split(x)      [M][3K]
__device__ __nv_bfloat16 g_o1s[(size_t)NN * KSPLIT];   // split(out1)   [M][3K]
__device__ __nv_bfloat16 g_w1t[(size_t)HID1 * KSPLIT]; // split(W1)^T   [N][3K]
__device__ __nv_bfloat16 g_w2t[(size_t)OUTC * KSPLIT]; // split(W2)^T   [N][3K]
__device__ float g_as1[NN * 8];
__device__ float g_ad1[NN * 8];
__device__ float g_as2[NN];
__device__ float g_ad2[NN];
__device__ int   g_deg[NN];
__device__ int   g_offs[NN + 1];
__device__ int   g_cursor[NN];
__device__ int   g_csr[NTOT];

// ---------------- helpers ----------------
__device__ __forceinline__ float warp_sum(float v) {
#pragma unroll
    for (int o = 16; o; o >>= 1) v += __shfl_xor_sync(0xffffffffu, v, o);
    return v;
}
__device__ __forceinline__ float warp_max(float v) {
#pragma unroll
    for (int o = 16; o; o >>= 1) v = fmaxf(v, __shfl_xor_sync(0xffffffffu, v, o));
    return v;
}
__device__ __forceinline__ unsigned fenc(float f) {
    unsigned u = __float_as_uint(f);
    return (u >> 31) ? ~u : (u | 0x80000000u);
}
__device__ __forceinline__ float fdec(unsigned u) {
    return __uint_as_float((u >> 31) ? (u & 0x7fffffffu) : ~u);
}
__device__ __forceinline__ float lrelu(float a) { return a > 0.f ? a : NEGS * a; }

// ---------------- CSR build ----------------
__global__ void zero_deg_kernel() {
    int i = blockIdx.x * blockDim.x + threadIdx.x;
    if (i < NN) g_deg[i] = 0;
}
__global__ void deg_kernel(const int* __restrict__ ei) {
    int i = blockIdx.x * blockDim.x + threadIdx.x;
    if (i < NTOT) {
        int d = (i < NE) ? ei[NE + i] : (i - NE);
        atomicAdd(&g_deg[d], 1);
    }
}
__global__ void scan_kernel() {
    __shared__ int s[1024];
    __shared__ int carry;
    if (threadIdx.x == 0) { carry = 0; g_offs[0] = 0; }
    __syncthreads();
    for (int base = 0; base < NN; base += 1024) {
        int i = base + threadIdx.x;
        int v = (i < NN) ? g_deg[i] : 0;
        s[threadIdx.x] = v;
        __syncthreads();
#pragma unroll
        for (int off = 1; off < 1024; off <<= 1) {
            int t = 0;
            if (threadIdx.x >= off) t = s[threadIdx.x - off];
            __syncthreads();
            if (threadIdx.x >= off) s[threadIdx.x] += t;
            __syncthreads();
        }
        int cur = carry;
        if (i < NN) g_offs[i + 1] = cur + s[threadIdx.x];
        __syncthreads();
        if (threadIdx.x == 0) carry = cur + s[1023];
        __syncthreads();
    }
}
__global__ void cursor_kernel() {
    int i = blockIdx.x * blockDim.x + threadIdx.x;
    if (i < NN) g_cursor[i] = g_offs[i];
}
__global__ void scatter_kernel(const int* __restrict__ ei) {
    int i = blockIdx.x * blockDim.x + threadIdx.x;
    if (i < NTOT) {
        int s, d;
        if (i < NE) { s = ei[i]; d = ei[NE + i]; }
        else        { s = d = i - NE; }
        int p = atomicAdd(&g_cursor[d], 1);
        g_csr[p] = s;
    }
}

// ---------------- bf16 split conversions ----------------
// activations: fp32 [M][512] -> bf16 [M][1536] blocks [hi | lo | hi]
__global__ void split_act_kernel(const float* __restrict__ in, __nv_bfloat16* __restrict__ out, int M) {
    int idx = blockIdx.x * blockDim.x + threadIdx.x;
    int total = M * (INC / 4);
    if (idx >= total) return;
    int n = idx / (INC / 4);
    int c4 = (idx % (INC / 4)) * 4;
    float4 v = *(const float4*)(in + (size_t)n * INC + c4);
    float vv[4] = {v.x, v.y, v.z, v.w};
    unsigned short hs[4], ls[4];
#pragma unroll
    for (int i = 0; i < 4; i++) {
        __nv_bfloat16 h = __float2bfloat16(vv[i]);
        __nv_bfloat16 l = __float2bfloat16(vv[i] - __bfloat162float(h));
        hs[i] = *(unsigned short*)&h;
        ls[i] = *(unsigned short*)&l;
    }
    __nv_bfloat16* row = out + (size_t)n * KSPLIT;
    ushort4 hv = make_ushort4(hs[0], hs[1], hs[2], hs[3]);
    ushort4 lv = make_ushort4(ls[0], ls[1], ls[2], ls[3]);
    *(ushort4*)(row + c4)            = hv;
    *(ushort4*)(row + INC + c4)      = lv;
    *(ushort4*)(row + 2 * INC + c4)  = hv;
}
// weights: fp32 [K=512][Nw] -> bf16 [Nw][1536] blocks [hi ; hi ; lo] (transposed)
__global__ void split_w_kernel(const float* __restrict__ in, __nv_bfloat16* __restrict__ out, int Nw) {
    int idx = blockIdx.x * blockDim.x + threadIdx.x;
    if (idx >= INC * Nw) return;
    int k = idx / Nw, n = idx % Nw;
    float v = in[(size_t)k * Nw + n];
    __nv_bfloat16 h = __float2bfloat16(v);
    __nv_bfloat16 l = __float2bfloat16(v - __bfloat162float(h));
    __nv_bfloat16* row = out + (size_t)n * KSPLIT;
    row[k] = h;
    row[INC + k] = h;
    row[2 * INC + k] = l;
}

// ---------------- bf16 tensor-core GEMM (NT): C[M][Nc] = A[M][K] * Bt[Nc][K]^T ----------------
// BM=128, BN=128, BK=32, 256 threads (8 warps, 4x2), warp tile 32x64, mma m16n8k16.
#define BM 128
#define BN 128
#define BK 32
#define APAD 40   // smem row stride in bf16 elements (80B: conflict-free, 16B aligned)

__global__ __launch_bounds__(256, 2) void mma_gemm_kernel(
    const __nv_bfloat16* __restrict__ A, const __nv_bfloat16* __restrict__ Bt,
    float* __restrict__ C, int M, int Nc, int K)
{
    __shared__ __nv_bfloat16 As[2][BM][APAD];
    __shared__ __nv_bfloat16 Bs[2][BN][APAD];

    int tid = threadIdx.x;
    int warp = tid >> 5, lane = tid & 31;
    int wm = (warp & 3) * 32;
    int wn = (warp >> 2) * 64;
    int m0 = blockIdx.y * BM, n0 = blockIdx.x * BN;
    int g = lane >> 2, t4 = lane & 3;

    float acc[2][8][4];
#pragma unroll
    for (int mi = 0; mi < 2; mi++)
#pragma unroll
        for (int ni = 0; ni < 8; ni++)
#pragma unroll
            for (int j = 0; j < 4; j++) acc[mi][ni][j] = 0.f;

    uint4 ra[2], rb[2];
    int nk = K / BK;

#define LOADG(KT) {                                                              \
        int k0 = (KT) * BK;                                                      \
        _Pragma("unroll")                                                        \
        for (int i = 0; i < 2; i++) {                                            \
            int uu = tid + i * 256; int r = uu >> 2; int cq = (uu & 3) * 8;      \
            int gr = m0 + r;                                                     \
            ra[i] = (gr < M) ? *(const uint4*)(A + (size_t)gr * K + k0 + cq)     \
                             : make_uint4(0u, 0u, 0u, 0u);                       \
            rb[i] = *(const uint4*)(Bt + (size_t)(n0 + r) * K + k0 + cq);        \
        } }
#define STORES(BUF) {                                                            \
        _Pragma("unroll")                                                        \
        for (int i = 0; i < 2; i++) {                                            \
            int uu = tid + i * 256; int r = uu >> 2; int cq = (uu & 3) * 8;      \
            *(uint4*)&As[BUF][r][cq] = ra[i];                                    \
            *(uint4*)&Bs[BUF][r][cq] = rb[i];                                    \
        } }

    LOADG(0); STORES(0); __syncthreads();

    for (int kt = 0; kt < nk; kt++) {
        int buf = kt & 1;
        if (kt + 1 < nk) LOADG(kt + 1);
#pragma unroll
        for (int kk = 0; kk < 2; kk++) {
            int kb = kk * 16;
            uint32_t af[2][4];
            uint32_t bfrag[8][2];
#pragma unroll
            for (int mi = 0; mi < 2; mi++) {
                int r = wm + mi * 16;
                af[mi][0] = *(const uint32_t*)&As[buf][r + g][kb + 2 * t4];
                af[mi][1] = *(const uint32_t*)&As[buf][r + g + 8][kb + 2 * t4];
                af[mi][2] = *(const uint32_t*)&As[buf][r + g][kb + 2 * t4 + 8];
                af[mi][3] = *(const uint32_t*)&As[buf][r + g + 8][kb + 2 * t4 + 8];
            }
#pragma unroll
            for (int ni = 0; ni < 8; ni++) {
                int c = wn + ni * 8 + g;
                bfrag[ni][0] = *(const uint32_t*)&Bs[buf][c][kb + 2 * t4];
                bfrag[ni][1] = *(const uint32_t*)&Bs[buf][c][kb + 2 * t4 + 8];
            }
#pragma unroll
            for (int mi = 0; mi < 2; mi++)
#pragma unroll
                for (int ni = 0; ni < 8; ni++) {
                    asm volatile(
                        "mma.sync.aligned.m16n8k16.row.col.f32.bf16.bf16.f32 "
                        "{%0,%1,%2,%3}, {%4,%5,%6,%7}, {%8,%9}, {%0,%1,%2,%3};\n"
                        : "+f"(acc[mi][ni][0]), "+f"(acc[mi][ni][1]),
                          "+f"(acc[mi][ni][2]), "+f"(acc[mi][ni][3])
                        : "r"(af[mi][0]), "r"(af[mi][1]), "r"(af[mi][2]), "r"(af[mi][3]),
                          "r"(bfrag[ni][0]), "r"(bfrag[ni][1]));
                }
        }
        if (kt + 1 < nk) STORES((kt + 1) & 1);
        __syncthreads();
    }

    // epilogue
#pragma unroll
    for (int mi = 0; mi < 2; mi++) {
        int r = m0 + wm + mi * 16;
#pragma unroll
        for (int ni = 0; ni < 8; ni++) {
            int c = n0 + wn + ni * 8 + 2 * t4;
            if (r + g < M) {
                float2 v0 = make_float2(acc[mi][ni][0], acc[mi][ni][1]);
                *(float2*)(C + (size_t)(r + g) * Nc + c) = v0;
            }
            if (r + g + 8 < M) {
                float2 v1 = make_float2(acc[mi][ni][2], acc[mi][ni][3]);
                *(float2*)(C + (size_t)(r + g + 8) * Nc + c) = v1;
            }
        }
    }
#undef LOADG
#undef STORES
}

// ---------------- per-node attention logits ----------------
__global__ void alpha1_kernel(const float* __restrict__ asrc, const float* __restrict__ adst) {
    int gw = (blockIdx.x * blockDim.x + threadIdx.x) >> 5;
    int lane = threadIdx.x & 31;
    if (gw >= NN) return;
    const float* hr = g_h1 + (size_t)gw * HID1;
#pragma unroll
    for (int hd = 0; hd < 8; hd++) {
        int c0 = hd * 64 + lane, c1 = c0 + 32;
        float h0 = hr[c0], h1v = hr[c1];
        float vs = h0 * asrc[c0] + h1v * asrc[c1];
        float vd = h0 * adst[c0] + h1v * adst[c1];
        vs = warp_sum(vs);
        vd = warp_sum(vd);
        if (lane == 0) { g_as1[gw * 8 + hd] = vs; g_ad1[gw * 8 + hd] = vd; }
    }
}
__global__ void alpha2_kernel(const float* __restrict__ asrc, const float* __restrict__ adst) {
    int gw = (blockIdx.x * blockDim.x + threadIdx.x) >> 5;
    int lane = threadIdx.x & 31;
    if (gw >= NN) return;
    const float* hr = g_h2 + (size_t)gw * OUTC;
    float vs = 0.f, vd = 0.f;
#pragma unroll
    for (int c = 0; c < OUTC; c += 32) {
        float hv = hr[c + lane];
        vs += hv * asrc[c + lane];
        vd += hv * adst[c + lane];
    }
    vs = warp_sum(vs);
    vd = warp_sum(vd);
    if (lane == 0) { g_as2[gw] = vs; g_ad2[gw] = vd; }
}

// ---------------- layer1 aggregation: fused segment softmax + gather + bias + elu ----------------
__global__ void agg1_kernel(const float* __restrict__ bias) {
    int n = blockIdx.x;
    int tid = threadIdx.x;
    int beg = g_offs[n], end = g_offs[n + 1];

    __shared__ float s_ad[8];
    __shared__ unsigned s_maxi[8];
    __shared__ float s_max[8];
    __shared__ float s_sum[8];
    __shared__ int   s_src[32];
    __shared__ float s_coef[32][8];

    if (tid < 8) {
        s_ad[tid] = g_ad1[n * 8 + tid];
        s_maxi[tid] = 0x007FFFFFu;
        s_sum[tid] = 0.f;
    }
    __syncthreads();

    float lmax[8];
#pragma unroll
    for (int h = 0; h < 8; h++) lmax[h] = -INFINITY;
    for (int e = beg + tid; e < end; e += 256) {
        int s = g_csr[e];
#pragma unroll
        for (int h = 0; h < 8; h++) {
            float a = lrelu(g_as1[s * 8 + h] + s_ad[h]);
            lmax[h] = fmaxf(lmax[h], a);
        }
    }
#pragma unroll
    for (int h = 0; h < 8; h++) atomicMax(&s_maxi[h], fenc(lmax[h]));
    __syncthreads();
    if (tid < 8) s_max[tid] = fdec(s_maxi[tid]);
    __syncthreads();

    float lsum[8];
#pragma unroll
    for (int h = 0; h < 8; h++) lsum[h] = 0.f;
    for (int e = beg + tid; e < end; e += 256) {
        int s = g_csr[e];
#pragma unroll
        for (int h = 0; h < 8; h++) {
            float a = lrelu(g_as1[s * 8 + h] + s_ad[h]);
            lsum[h] += expf(a - s_max[h]);
        }
    }
#pragma unroll
    for (int h = 0; h < 8; h++) atomicAdd(&s_sum[h], lsum[h]);
    __syncthreads();
    if (tid < 8) s_sum[tid] = 1.f / (s_sum[tid] + 1e-16f);
    __syncthreads();

    float acc0 = 0.f, acc1 = 0.f;
    int c0 = tid, c1 = tid + 256;
    int h0 = c0 >> 6, h1 = c1 >> 6;
    for (int cb = beg; cb < end; cb += 32) {
        int cn = end - cb; if (cn > 32) cn = 32;
        int el = tid >> 3, hh = tid & 7;
        if (el < cn) {
            int s = g_csr[cb + el];
            float a = lrelu(g_as1[s * 8 + hh] + s_ad[hh]);
            s_coef[el][hh] = expf(a - s_max[hh]) * s_sum[hh];
            if (hh == 0) s_src[el] = s;
        }
        __syncthreads();
        for (int e = 0; e < cn; e++) {
            const float* row = g_h1 + (size_t)s_src[e] * HID1;
            acc0 += row[c0] * s_coef[e][h0];
            acc1 += row[c1] * s_coef[e][h1];
        }
        __syncthreads();
    }
    float o0 = acc0 + bias[c0];
    float o1 = acc1 + bias[c1];
    g_out1[(size_t)n * HID1 + c0] = o0 > 0.f ? o0 : expm1f(o0);
    g_out1[(size_t)n * HID1 + c1] = o1 > 0.f ? o1 : expm1f(o1);
}

// ---------------- layer2 aggregation ----------------
__global__ void agg2_kernel(const float* __restrict__ bias, float* __restrict__ out) {
    int n = blockIdx.x;
    int tid = threadIdx.x;
    int beg = g_offs[n], end = g_offs[n + 1];

    __shared__ float s_ad;
    __shared__ unsigned s_maxi;
    __shared__ float s_max;
    __shared__ float s_sum;
    __shared__ int   s_src[64];
    __shared__ float s_coef[64];

    if (tid == 0) {
        s_ad = g_ad2[n];
        s_maxi = 0x007FFFFFu;
        s_sum = 0.f;
    }
    __syncthreads();

    float lmax = -INFINITY;
    for (int e = beg + tid; e < end; e += 256) {
        float a = lrelu(g_as2[g_csr[e]] + s_ad);
        lmax = fmaxf(lmax, a);
    }
    atomicMax(&s_maxi, fenc(lmax));
    __syncthreads();
    if (tid == 0) s_max = fdec(s_maxi);
    __syncthreads();

    float lsum = 0.f;
    for (int e = beg + tid; e < end; e += 256) {
        float a = lrelu(g_as2[g_csr[e]] + s_ad);
        lsum += expf(a - s_max);
    }
    atomicAdd(&s_sum, lsum);
    __syncthreads();
    if (tid == 0) s_sum = 1.f / (s_sum + 1e-16f);
    __syncthreads();

    float acc = 0.f;
    for (int cb = beg; cb < end; cb += 64) {
        int cn = end - cb; if (cn > 64) cn = 64;
        if (tid < cn) {
            int s = g_csr[cb + tid];
            float a = lrelu(g_as2[s] + s_ad);
            s_coef[tid] = expf(a - s_max) * s_sum;
            s_src[tid] = s;
        }
        __syncthreads();
        for (int e = 0; e < cn; e++) {
            acc += g_h2[(size_t)s_src[e] * OUTC + tid] * s_coef[e];
        }
        __syncthreads();
    }
    out[(size_t)n * OUTC + tid] = acc + bias[tid];
}

// ---------------- log softmax over rows of [NN, 256] (in-place) ----------------
__global__ void logsoftmax_kernel(float* __restrict__ out) {
    int n = blockIdx.x, tid = threadIdx.x;
    __shared__ float shm[8];
    __shared__ float shs[8];
    float v = out[(size_t)n * OUTC + tid];
    float wm = warp_max(v);
    if ((tid & 31) == 0) shm[tid >> 5] = wm;
    __syncthreads();
    float m = shm[0];
#pragma unroll
    for (int i = 1; i < 8; i++) m = fmaxf(m, shm[i]);
    float ex = expf(v - m);
    float ws = warp_sum(ex);
    if ((tid & 31) == 0) shs[tid >> 5] = ws;
    __syncthreads();
    float s = 0.f;
#pragma unroll
    for (int i = 0; i < 8; i++) s += shs[i];
    out[(size_t)n * OUTC + tid] = v - m - logf(s);
}

// ---------------- launch ----------------
extern "C" void kernel_launch(void* const* d_in, const int* in_sizes, int n_in,
                              void* d_out, int out_size) {
    const float* x    = (const float*)d_in[0];
    const int*   ei   = (const int*)d_in[1];
    const float* W1   = (const float*)d_in[2];
    const float* as1  = (const float*)d_in[3];
    const float* ad1  = (const float*)d_in[4];
    const float* b1   = (const float*)d_in[5];
    const float* W2   = (const float*)d_in[6];
    const float* as2  = (const float*)d_in[7];
    const float* ad2  = (const float*)d_in[8];
    const float* b2   = (const float*)d_in[9];
    float* out = (float*)d_out;

    float *p_h1, *p_out1, *p_h2;
    __nv_bfloat16 *p_xs, *p_o1s, *p_w1t, *p_w2t;
    cudaGetSymbolAddress((void**)&p_h1, g_h1);
    cudaGetSymbolAddress((void**)&p_out1, g_out1);
    cudaGetSymbolAddress((void**)&p_h2, g_h2);
    cudaGetSymbolAddress((void**)&p_xs, g_xs);
    cudaGetSymbolAddress((void**)&p_o1s, g_o1s);
    cudaGetSymbolAddress((void**)&p_w1t, g_w1t);
    cudaGetSymbolAddress((void**)&p_w2t, g_w2t);

    // CSR build
    zero_deg_kernel<<<(NN + 255) / 256, 256>>>();
    deg_kernel<<<(NTOT + 255) / 256, 256>>>(ei);
    scan_kernel<<<1, 1024>>>();
    cursor_kernel<<<(NN + 255) / 256, 256>>>();
    scatter_kernel<<<(NTOT + 255) / 256, 256>>>(ei);

    // weight splits (overlaps with CSR in-stream order; cheap)
    split_w_kernel<<<(INC * HID1 + 255) / 256, 256>>>(W1, p_w1t, HID1);
    split_w_kernel<<<(INC * OUTC + 255) / 256, 256>>>(W2, p_w2t, OUTC);

    // layer 1
    split_act_kernel<<<(NN * (INC / 4) + 255) / 256, 256>>>(x, p_xs, NN);
    mma_gemm_kernel<<<dim3(HID1 / BN, (NN + BM - 1) / BM), 256>>>(p_xs, p_w1t, p_h1, NN, HID1, KSPLIT);
    alpha1_kernel<<<(NN + 7) / 8, 256>>>(as1, ad1);
    agg1_kernel<<<NN, 256>>>(b1);

    // layer 2
    split_act_kernel<<<(NN * (INC / 4) + 255) / 256, 256>>>(p_out1, p_o1s, NN);
    mma_gemm_kernel<<<dim3(OUTC / BN, (NN + BM - 1) / BM), 256>>>(p_o1s, p_w2t, p_h2, NN, OUTC, KSPLIT);
    alpha2_kernel<<<(NN + 7) / 8, 256>>>(as2, ad2);
    agg2_kernel<<<NN, 256>>>(b2, out);

    // log softmax
    logsoftmax_kernel<<<NN, 256>>>(out);
}

// round 3
// speedup vs baseline: 1.1718x; 1.0065x over previous
#include <cuda_runtime.h>
#include <cuda_bf16.h>
#include <math.h>
#include <stdint.h>

#define NN     20000
#define INC    512
#define HID1   512      // H1*HID = 8*64
#define OUTC   256
#define NE     320000
#define NTOT   (NE + NN)   // edges + self loops = 340000
#define NEGS   0.2f
#define KSPLIT 1536        // 3 * 512 (hi | lo | hi blocks along K)

// ---------------- scratch (device globals: no allocation allowed) ----------------
__device__ float g_h1[(size_t)NN * HID1];     // layer1 GEMM output (fp32)
__device__ float g_h2[(size_t)NN * OUTC];     // layer2 GEMM output
__device__ __nv_bfloat16 g_xs[(size_t)NN * KSPLIT];    // split(x)       [M][3K]
__device__ __nv_bfloat16 g_o1s[(size_t)NN * KSPLIT];   // split(elu out1)[M][3K]
__device__ __nv_bfloat16 g_w1t[(size_t)HID1 * KSPLIT]; // split(W1)^T    [N][3K]
__device__ __nv_bfloat16 g_w2t[(size_t)OUTC * KSPLIT]; // split(W2)^T    [N][3K]
__device__ float g_as1[NN * 8];
__device__ float g_ad1[NN * 8];
__device__ float g_as2[NN];
__device__ float g_ad2[NN];
__device__ int   g_deg[NN];
__device__ int   g_offs[NN + 1];
__device__ int   g_cursor[NN];
__device__ int   g_csr[NTOT];

// ---------------- helpers ----------------
__device__ __forceinline__ float warp_sum(float v) {
#pragma unroll
    for (int o = 16; o; o >>= 1) v += __shfl_xor_sync(0xffffffffu, v, o);
    return v;
}
__device__ __forceinline__ float warp_max(float v) {
#pragma unroll
    for (int o = 16; o; o >>= 1) v = fmaxf(v, __shfl_xor_sync(0xffffffffu, v, o));
    return v;
}
__device__ __forceinline__ unsigned fenc(float f) {
    unsigned u = __float_as_uint(f);
    return (u >> 31) ? ~u : (u | 0x80000000u);
}
__device__ __forceinline__ float fdec(unsigned u) {
    return __uint_as_float((u >> 31) ? (u & 0x7fffffffu) : ~u);
}
__device__ __forceinline__ float lrelu(float a) { return a > 0.f ? a : NEGS * a; }

__device__ __forceinline__ uint32_t smem_u32(const void* p) {
    return (uint32_t)__cvta_generic_to_shared(p);
}
__device__ __forceinline__ void ldsm_x4(uint32_t& r0, uint32_t& r1, uint32_t& r2, uint32_t& r3, uint32_t addr) {
    asm volatile("ldmatrix.sync.aligned.m8n8.x4.shared.b16 {%0,%1,%2,%3}, [%4];\n"
                 : "=r"(r0), "=r"(r1), "=r"(r2), "=r"(r3) : "r"(addr));
}

// ---------------- CSR build ----------------
__global__ void zero_deg_kernel() {
    int i = blockIdx.x * blockDim.x + threadIdx.x;
    if (i < NN) g_deg[i] = 0;
}
__global__ void deg_kernel(const int* __restrict__ ei) {
    int i = blockIdx.x * blockDim.x + threadIdx.x;
    if (i < NTOT) {
        int d = (i < NE) ? ei[NE + i] : (i - NE);
        atomicAdd(&g_deg[d], 1);
    }
}
// inclusive scan over degrees; writes g_offs[1..NN] and g_cursor[i]=g_offs[i]
__global__ void scan_kernel() {
    __shared__ int s[1024];
    __shared__ int carry;
    if (threadIdx.x == 0) { carry = 0; g_offs[0] = 0; }
    __syncthreads();
    for (int base = 0; base < NN; base += 1024) {
        int i = base + threadIdx.x;
        int v = (i < NN) ? g_deg[i] : 0;
        s[threadIdx.x] = v;
        __syncthreads();
#pragma unroll
        for (int off = 1; off < 1024; off <<= 1) {
            int t = 0;
            if (threadIdx.x >= off) t = s[threadIdx.x - off];
            __syncthreads();
            if (threadIdx.x >= off) s[threadIdx.x] += t;
            __syncthreads();
        }
        int cur = carry;
        if (i < NN) {
            int incl = cur + s[threadIdx.x];
            g_offs[i + 1] = incl;
            g_cursor[i] = incl - v;
        }
        __syncthreads();
        if (threadIdx.x == 0) carry = cur + s[1023];
        __syncthreads();
    }
}
__global__ void scatter_kernel(const int* __restrict__ ei) {
    int i = blockIdx.x * blockDim.x + threadIdx.x;
    if (i < NTOT) {
        int s, d;
        if (i < NE) { s = ei[i]; d = ei[NE + i]; }
        else        { s = d = i - NE; }
        int p = atomicAdd(&g_cursor[d], 1);
        g_csr[p] = s;
    }
}

// ---------------- bf16 split conversions ----------------
__global__ void split_act_kernel(const float* __restrict__ in, __nv_bfloat16* __restrict__ out, int M) {
    int idx = blockIdx.x * blockDim.x + threadIdx.x;
    int total = M * (INC / 4);
    if (idx >= total) return;
    int n = idx / (INC / 4);
    int c4 = (idx % (INC / 4)) * 4;
    float4 v = *(const float4*)(in + (size_t)n * INC + c4);
    float vv[4] = {v.x, v.y, v.z, v.w};
    unsigned short hs[4], ls[4];
#pragma unroll
    for (int i = 0; i < 4; i++) {
        __nv_bfloat16 h = __float2bfloat16(vv[i]);
        __nv_bfloat16 l = __float2bfloat16(vv[i] - __bfloat162float(h));
        hs[i] = *(unsigned short*)&h;
        ls[i] = *(unsigned short*)&l;
    }
    __nv_bfloat16* row = out + (size_t)n * KSPLIT;
    ushort4 hv = make_ushort4(hs[0], hs[1], hs[2], hs[3]);
    ushort4 lv = make_ushort4(ls[0], ls[1], ls[2], ls[3]);
    *(ushort4*)(row + c4)            = hv;
    *(ushort4*)(row + INC + c4)      = lv;
    *(ushort4*)(row + 2 * INC + c4)  = hv;
}
__global__ void split_w_kernel(const float* __restrict__ in, __nv_bfloat16* __restrict__ out, int Nw) {
    int idx = blockIdx.x * blockDim.x + threadIdx.x;
    if (idx >= INC * Nw) return;
    int k = idx / Nw, n = idx % Nw;
    float v = in[(size_t)k * Nw + n];
    __nv_bfloat16 h = __float2bfloat16(v);
    __nv_bfloat16 l = __float2bfloat16(v - __bfloat162float(h));
    __nv_bfloat16* row = out + (size_t)n * KSPLIT;
    row[k] = h;
    row[INC + k] = h;
    row[2 * INC + k] = l;
}

// ---------------- bf16 tensor-core GEMM (NT): C[M][Nc] = A[M][K] * Bt[Nc][K]^T ----------------
#define BM 128
#define BN 128
#define BK 32
#define APAD 40   // smem row stride in bf16 (80B): conflict-free, 16B aligned

__global__ __launch_bounds__(256, 2) void mma_gemm_kernel(
    const __nv_bfloat16* __restrict__ A, const __nv_bfloat16* __restrict__ Bt,
    float* __restrict__ C, int M, int Nc, int K)
{
    __shared__ __nv_bfloat16 As[2][BM][APAD];
    __shared__ __nv_bfloat16 Bs[2][BN][APAD];

    int tid = threadIdx.x;
    int warp = tid >> 5, lane = tid & 31;
    int wm = (warp & 3) * 32;
    int wn = (warp >> 2) * 64;
    int m0 = blockIdx.y * BM, n0 = blockIdx.x * BN;
    int g = lane >> 2, t4 = lane & 3;

    // ldmatrix lane addressing
    int a_row = (lane & 7) + ((lane >> 3) & 1) * 8;   // row within 16-row fragment
    int a_half = (lane >> 4) * 8;                     // k half (0/8)
    int b_row = (lane & 7) + ((lane >> 4) << 3);      // row within 16-n pair
    int b_half = ((lane >> 3) & 1) * 8;               // k half

    float acc[2][8][4];
#pragma unroll
    for (int mi = 0; mi < 2; mi++)
#pragma unroll
        for (int ni = 0; ni < 8; ni++)
#pragma unroll
            for (int j = 0; j < 4; j++) acc[mi][ni][j] = 0.f;

    uint4 ra[2], rb[2];
    int nk = K / BK;

#define LOADG(KT) {                                                              \
        int k0 = (KT) * BK;                                                      \
        _Pragma("unroll")                                                        \
        for (int i = 0; i < 2; i++) {                                            \
            int uu = tid + i * 256; int r = uu >> 2; int cq = (uu & 3) * 8;      \
            int gr = m0 + r;                                                     \
            ra[i] = (gr < M) ? *(const uint4*)(A + (size_t)gr * K + k0 + cq)     \
                             : make_uint4(0u, 0u, 0u, 0u);                       \
            rb[i] = *(const uint4*)(Bt + (size_t)(n0 + r) * K + k0 + cq);        \
        } }
#define STORES(BUF) {                                                            \
        _Pragma("unroll")                                                        \
        for (int i = 0; i < 2; i++) {                                            \
            int uu = tid + i * 256; int r = uu >> 2; int cq = (uu & 3) * 8;      \
            *(uint4*)&As[BUF][r][cq] = ra[i];                                    \
            *(uint4*)&Bs[BUF][r][cq] = rb[i];                                    \
        } }

    LOADG(0); STORES(0); __syncthreads();

    for (int kt = 0; kt < nk; kt++) {
        int buf = kt & 1;
        if (kt + 1 < nk) LOADG(kt + 1);
#pragma unroll
        for (int kk = 0; kk < 2; kk++) {
            int kb = kk * 16;
            uint32_t af[2][4];
            uint32_t bfrag[8][2];
#pragma unroll
            for (int mi = 0; mi < 2; mi++) {
                uint32_t ad = smem_u32(&As[buf][wm + mi * 16 + a_row][kb + a_half]);
                ldsm_x4(af[mi][0], af[mi][1], af[mi][2], af[mi][3], ad);
            }
#pragma unroll
            for (int p = 0; p < 4; p++) {
                uint32_t bd = smem_u32(&Bs[buf][wn + p * 16 + b_row][kb + b_half]);
                ldsm_x4(bfrag[2 * p][0], bfrag[2 * p][1], bfrag[2 * p + 1][0], bfrag[2 * p + 1][1], bd);
            }
#pragma unroll
            for (int mi = 0; mi < 2; mi++)
#pragma unroll
                for (int ni = 0; ni < 8; ni++) {
                    asm volatile(
                        "mma.sync.aligned.m16n8k16.row.col.f32.bf16.bf16.f32 "
                        "{%0,%1,%2,%3}, {%4,%5,%6,%7}, {%8,%9}, {%0,%1,%2,%3};\n"
                        : "+f"(acc[mi][ni][0]), "+f"(acc[mi][ni][1]),
                          "+f"(acc[mi][ni][2]), "+f"(acc[mi][ni][3])
                        : "r"(af[mi][0]), "r"(af[mi][1]), "r"(af[mi][2]), "r"(af[mi][3]),
                          "r"(bfrag[ni][0]), "r"(bfrag[ni][1]));
                }
        }
        if (kt + 1 < nk) STORES((kt + 1) & 1);
        __syncthreads();
    }

#pragma unroll
    for (int mi = 0; mi < 2; mi++) {
        int r = m0 + wm + mi * 16;
#pragma unroll
        for (int ni = 0; ni < 8; ni++) {
            int c = n0 + wn + ni * 8 + 2 * t4;
            if (r + g < M) {
                float2 v0 = make_float2(acc[mi][ni][0], acc[mi][ni][1]);
                *(float2*)(C + (size_t)(r + g) * Nc + c) = v0;
            }
            if (r + g + 8 < M) {
                float2 v1 = make_float2(acc[mi][ni][2], acc[mi][ni][3]);
                *(float2*)(C + (size_t)(r + g + 8) * Nc + c) = v1;
            }
        }
    }
#undef LOADG
#undef STORES
}

// ---------------- per-node attention logits ----------------
__global__ void alpha1_kernel(const float* __restrict__ asrc, const float* __restrict__ adst) {
    int gw = (blockIdx.x * blockDim.x + threadIdx.x) >> 5;
    int lane = threadIdx.x & 31;
    if (gw >= NN) return;
    const float* hr = g_h1 + (size_t)gw * HID1;
#pragma unroll
    for (int hd = 0; hd < 8; hd++) {
        int c0 = hd * 64 + lane, c1 = c0 + 32;
        float h0 = hr[c0], h1v = hr[c1];
        float vs = h0 * asrc[c0] + h1v * asrc[c1];
        float vd = h0 * adst[c0] + h1v * adst[c1];
        vs = warp_sum(vs);
        vd = warp_sum(vd);
        if (lane == 0) { g_as1[gw * 8 + hd] = vs; g_ad1[gw * 8 + hd] = vd; }
    }
}
__global__ void alpha2_kernel(const float* __restrict__ asrc, const float* __restrict__ adst) {
    int gw = (blockIdx.x * blockDim.x + threadIdx.x) >> 5;
    int lane = threadIdx.x & 31;
    if (gw >= NN) return;
    const float* hr = g_h2 + (size_t)gw * OUTC;
    float vs = 0.f, vd = 0.f;
#pragma unroll
    for (int c = 0; c < OUTC; c += 32) {
        float hv = hr[c + lane];
        vs += hv * asrc[c + lane];
        vd += hv * adst[c + lane];
    }
    vs = warp_sum(vs);
    vd = warp_sum(vd);
    if (lane == 0) { g_as2[gw] = vs; g_ad2[gw] = vd; }
}

// ---------------- layer1 aggregation: softmax + gather + bias + elu + bf16 split ----------------
__global__ void agg1_kernel(const float* __restrict__ bias) {
    int n = blockIdx.x;
    int tid = threadIdx.x;
    int beg = g_offs[n], end = g_offs[n + 1];

    __shared__ float s_ad[8];
    __shared__ unsigned s_maxi[8];
    __shared__ float s_max[8];
    __shared__ float s_sum[8];
    __shared__ int   s_src[32];
    __shared__ float s_coef[32][8];

    if (tid < 8) {
        s_ad[tid] = g_ad1[n * 8 + tid];
        s_maxi[tid] = 0x007FFFFFu;
        s_sum[tid] = 0.f;
    }
    __syncthreads();

    const float4* as4 = (const float4*)g_as1;

    // pass 1: per-head max
    float lmax[8];
#pragma unroll
    for (int h = 0; h < 8; h++) lmax[h] = -INFINITY;
    for (int e = beg + tid; e < end; e += 256) {
        int s = g_csr[e];
        float4 lo = as4[s * 2], hi = as4[s * 2 + 1];
        float av[8] = {lo.x, lo.y, lo.z, lo.w, hi.x, hi.y, hi.z, hi.w};
#pragma unroll
        for (int h = 0; h < 8; h++) lmax[h] = fmaxf(lmax[h], lrelu(av[h] + s_ad[h]));
    }
#pragma unroll
    for (int h = 0; h < 8; h++) atomicMax(&s_maxi[h], fenc(lmax[h]));
    __syncthreads();
    if (tid < 8) s_max[tid] = fdec(s_maxi[tid]);
    __syncthreads();

    // pass 2: per-head exp-sum
    float lsum[8];
#pragma unroll
    for (int h = 0; h < 8; h++) lsum[h] = 0.f;
    for (int e = beg + tid; e < end; e += 256) {
        int s = g_csr[e];
        float4 lo = as4[s * 2], hi = as4[s * 2 + 1];
        float av[8] = {lo.x, lo.y, lo.z, lo.w, hi.x, hi.y, hi.z, hi.w};
#pragma unroll
        for (int h = 0; h < 8; h++) lsum[h] += expf(lrelu(av[h] + s_ad[h]) - s_max[h]);
    }
#pragma unroll
    for (int h = 0; h < 8; h++) atomicAdd(&s_sum[h], lsum[h]);
    __syncthreads();
    if (tid < 8) s_sum[tid] = 1.f / (s_sum[tid] + 1e-16f);
    __syncthreads();

    // pass 3: weighted gather (float2 per thread: channels c, c+1)
    int c = 2 * tid;           // 0..510, both channels in head h
    int h = c >> 6;
    float accx = 0.f, accy = 0.f;
    for (int cb = beg; cb < end; cb += 32) {
        int cn = end - cb; if (cn > 32) cn = 32;
        int el = tid >> 3, hh = tid & 7;
        if (el < cn) {
            int s = g_csr[cb + el];
            float a = lrelu(g_as1[s * 8 + hh] + s_ad[hh]);
            s_coef[el][hh] = expf(a - s_max[hh]) * s_sum[hh];
            if (hh == 0) s_src[el] = s;
        }
        __syncthreads();
        int e = 0;
        for (; e + 4 <= cn; e += 4) {
            const float2* r0 = (const float2*)(g_h1 + (size_t)s_src[e + 0] * HID1 + c);
            const float2* r1 = (const float2*)(g_h1 + (size_t)s_src[e + 1] * HID1 + c);
            const float2* r2 = (const float2*)(g_h1 + (size_t)s_src[e + 2] * HID1 + c);
            const float2* r3 = (const float2*)(g_h1 + (size_t)s_src[e + 3] * HID1 + c);
            float2 v0 = *r0, v1 = *r1, v2 = *r2, v3 = *r3;
            float k0 = s_coef[e + 0][h], k1 = s_coef[e + 1][h];
            float k2 = s_coef[e + 2][h], k3 = s_coef[e + 3][h];
            accx += v0.x * k0 + v1.x * k1 + v2.x * k2 + v3.x * k3;
            accy += v0.y * k0 + v1.y * k1 + v2.y * k2 + v3.y * k3;
        }
        for (; e < cn; e++) {
            float2 v = *(const float2*)(g_h1 + (size_t)s_src[e] * HID1 + c);
            float kc = s_coef[e][h];
            accx += v.x * kc;
            accy += v.y * kc;
        }
        __syncthreads();
    }
    float2 bv = *(const float2*)(bias + c);
    float ox = accx + bv.x, oy = accy + bv.y;
    ox = ox > 0.f ? ox : expm1f(ox);
    oy = oy > 0.f ? oy : expm1f(oy);
    // bf16 split write: [hi | lo | hi]
    __nv_bfloat16 hx = __float2bfloat16(ox), hy = __float2bfloat16(oy);
    __nv_bfloat16 lx = __float2bfloat16(ox - __bfloat162float(hx));
    __nv_bfloat16 ly = __float2bfloat16(oy - __bfloat162float(hy));
    __nv_bfloat16* row = g_o1s + (size_t)n * KSPLIT;
    ushort2 hv = make_ushort2(*(unsigned short*)&hx, *(unsigned short*)&hy);
    ushort2 lv = make_ushort2(*(unsigned short*)&lx, *(unsigned short*)&ly);
    *(ushort2*)(row + c)           = hv;
    *(ushort2*)(row + INC + c)     = lv;
    *(ushort2*)(row + 2 * INC + c) = hv;
}

// ---------------- layer2 aggregation + bias + log-softmax ----------------
__global__ void agg2_kernel(const float* __restrict__ bias, float* __restrict__ out) {
    int n = blockIdx.x;
    int tid = threadIdx.x;
    int beg = g_offs[n], end = g_offs[n + 1];

    __shared__ float s_ad;
    __shared__ unsigned s_maxi;
    __shared__ float s_max;
    __shared__ float s_sum;
    __shared__ int   s_src[64];
    __shared__ float s_coef[64];
    __shared__ float shm[8];
    __shared__ float shs[8];

    if (tid == 0) {
        s_ad = g_ad2[n];
        s_maxi = 0x007FFFFFu;
        s_sum = 0.f;
    }
    __syncthreads();

    float lmax = -INFINITY;
    for (int e = beg + tid; e < end; e += 256) {
        float a = lrelu(g_as2[g_csr[e]] + s_ad);
        lmax = fmaxf(lmax, a);
    }
    atomicMax(&s_maxi, fenc(lmax));
    __syncthreads();
    if (tid == 0) s_max = fdec(s_maxi);
    __syncthreads();

    float lsum = 0.f;
    for (int e = beg + tid; e < end; e += 256) {
        float a = lrelu(g_as2[g_csr[e]] + s_ad);
        lsum += expf(a - s_max);
    }
    atomicAdd(&s_sum, lsum);
    __syncthreads();
    if (tid == 0) s_sum = 1.f / (s_sum + 1e-16f);
    __syncthreads();

    float acc = 0.f;
    for (int cb = beg; cb < end; cb += 64) {
        int cn = end - cb; if (cn > 64) cn = 64;
        if (tid < cn) {
            int s = g_csr[cb + tid];
            float a = lrelu(g_as2[s] + s_ad);
            s_coef[tid] = expf(a - s_max) * s_sum;
            s_src[tid] = s;
        }
        __syncthreads();
        int e = 0;
        for (; e + 4 <= cn; e += 4) {
            float v0 = g_h2[(size_t)s_src[e + 0] * OUTC + tid];
            float v1 = g_h2[(size_t)s_src[e + 1] * OUTC + tid];
            float v2 = g_h2[(size_t)s_src[e + 2] * OUTC + tid];
            float v3 = g_h2[(size_t)s_src[e + 3] * OUTC + tid];
            acc += v0 * s_coef[e + 0] + v1 * s_coef[e + 1] + v2 * s_coef[e + 2] + v3 * s_coef[e + 3];
        }
        for (; e < cn; e++) {
            acc += g_h2[(size_t)s_src[e] * OUTC + tid] * s_coef[e];
        }
        __syncthreads();
    }
    float v = acc + bias[tid];

    // fused log-softmax over the 256 channels of this node
    float wm = warp_max(v);
    if ((tid & 31) == 0) shm[tid >> 5] = wm;
    __syncthreads();
    float m = shm[0];
#pragma unroll
    for (int i = 1; i < 8; i++) m = fmaxf(m, shm[i]);
    float ex = expf(v - m);
    float ws = warp_sum(ex);
    if ((tid & 31) == 0) shs[tid >> 5] = ws;
    __syncthreads();
    float s = 0.f;
#pragma unroll
    for (int i = 0; i < 8; i++) s += shs[i];
    out[(size_t)n * OUTC + tid] = v - m - logf(s);
}

// ---------------- launch ----------------
extern "C" void kernel_launch(void* const* d_in, const int* in_sizes, int n_in,
                              void* d_out, int out_size) {
    const float* x    = (const float*)d_in[0];
    const int*   ei   = (const int*)d_in[1];
    const float* W1   = (const float*)d_in[2];
    const float* as1  = (const float*)d_in[3];
    const float* ad1  = (const float*)d_in[4];
    const float* b1   = (const float*)d_in[5];
    const float* W2   = (const float*)d_in[6];
    const float* as2  = (const float*)d_in[7];
    const float* ad2  = (const float*)d_in[8];
    const float* b2   = (const float*)d_in[9];
    float* out = (float*)d_out;

    float *p_h1, *p_h2;
    __nv_bfloat16 *p_xs, *p_o1s, *p_w1t, *p_w2t;
    cudaGetSymbolAddress((void**)&p_h1, g_h1);
    cudaGetSymbolAddress((void**)&p_h2, g_h2);
    cudaGetSymbolAddress((void**)&p_xs, g_xs);
    cudaGetSymbolAddress((void**)&p_o1s, g_o1s);
    cudaGetSymbolAddress((void**)&p_w1t, g_w1t);
    cudaGetSymbolAddress((void**)&p_w2t, g_w2t);

    // (1-3) splits first so launch #4 is the big GEMM (ncu capture lands on #4)
    split_act_kernel<<<(NN * (INC / 4) + 255) / 256, 256>>>(x, p_xs, NN);
    split_w_kernel<<<(INC * HID1 + 255) / 256, 256>>>(W1, p_w1t, HID1);
    split_w_kernel<<<(INC * OUTC + 255) / 256, 256>>>(W2, p_w2t, OUTC);
    // (4) layer1 GEMM
    mma_gemm_kernel<<<dim3(HID1 / BN, (NN + BM - 1) / BM), 256>>>(p_xs, p_w1t, p_h1, NN, HID1, KSPLIT);

    // (5-8) CSR build
    zero_deg_kernel<<<(NN + 255) / 256, 256>>>();
    deg_kernel<<<(NTOT + 255) / 256, 256>>>(ei);
    scan_kernel<<<1, 1024>>>();
    scatter_kernel<<<(NTOT + 255) / 256, 256>>>(ei);

    // (9-10) layer1 attention + aggregation (writes bf16 split directly)
    alpha1_kernel<<<(NN + 7) / 8, 256>>>(as1, ad1);
    agg1_kernel<<<NN, 256>>>(b1);

    // (11-13) layer2
    mma_gemm_kernel<<<dim3(OUTC / BN, (NN + BM - 1) / BM), 256>>>(p_o1s, p_w2t, p_h2, NN, OUTC, KSPLIT);
    alpha2_kernel<<<(NN + 7) / 8, 256>>>(as2, ad2);
    agg2_kernel<<<NN, 256>>>(b2, out);
}

// round 4
// speedup vs baseline: 1.9314x; 1.6483x over previous
#include <cuda_runtime.h>
#include <cuda_bf16.h>
#include <math.h>
#include <stdint.h>

#define NN     20000
#define INC    512
#define HID1   512      // H1*HID = 8*64
#define OUTC   256
#define NE     320000
#define NTOT   (NE + NN)   // edges + self loops = 340000
#define NEGS   0.2f
#define KSPLIT 1536        // 3 * 512 (hi | lo | hi blocks along K)
#define CAP1   96
#define CAP2   128

// ---------------- scratch (device globals: no allocation allowed) ----------------
__device__ float g_h1[(size_t)NN * HID1];
__device__ float g_h2[(size_t)NN * OUTC];
__device__ __nv_bfloat16 g_xs[(size_t)NN * KSPLIT];
__device__ __nv_bfloat16 g_o1s[(size_t)NN * KSPLIT];
__device__ __nv_bfloat16 g_w1t[(size_t)HID1 * KSPLIT];
__device__ __nv_bfloat16 g_w2t[(size_t)OUTC * KSPLIT];
__device__ float g_as1[NN * 8];
__device__ float g_ad1[NN * 8];
__device__ float g_as2[NN];
__device__ float g_ad2[NN];
__device__ int   g_deg[NN];
__device__ int   g_offs[NN + 1];
__device__ int   g_cursor[NN];
__device__ int   g_csr[NTOT];

// ---------------- helpers ----------------
__device__ __forceinline__ float warp_sum(float v) {
#pragma unroll
    for (int o = 16; o; o >>= 1) v += __shfl_xor_sync(0xffffffffu, v, o);
    return v;
}
__device__ __forceinline__ float warp_max(float v) {
#pragma unroll
    for (int o = 16; o; o >>= 1) v = fmaxf(v, __shfl_xor_sync(0xffffffffu, v, o));
    return v;
}
__device__ __forceinline__ unsigned fenc(float f) {
    unsigned u = __float_as_uint(f);
    return (u >> 31) ? ~u : (u | 0x80000000u);
}
__device__ __forceinline__ float fdec(unsigned u) {
    return __uint_as_float((u >> 31) ? (u & 0x7fffffffu) : ~u);
}
__device__ __forceinline__ float lrelu(float a) { return a > 0.f ? a : NEGS * a; }

__device__ __forceinline__ uint32_t smem_u32(const void* p) {
    return (uint32_t)__cvta_generic_to_shared(p);
}
__device__ __forceinline__ void ldsm_x4(uint32_t& r0, uint32_t& r1, uint32_t& r2, uint32_t& r3, uint32_t addr) {
    asm volatile("ldmatrix.sync.aligned.m8n8.x4.shared.b16 {%0,%1,%2,%3}, [%4];\n"
                 : "=r"(r0), "=r"(r1), "=r"(r2), "=r"(r3) : "r"(addr));
}

// ---------------- CSR build ----------------
__global__ void zero_deg_kernel() {
    int i = blockIdx.x * blockDim.x + threadIdx.x;
    if (i < NN) g_deg[i] = 0;
}
__global__ void deg_kernel(const int* __restrict__ ei) {
    int i = blockIdx.x * blockDim.x + threadIdx.x;
    if (i < NTOT) {
        int d = (i < NE) ? ei[NE + i] : (i - NE);
        atomicAdd(&g_deg[d], 1);
    }
}
__global__ void scan_kernel() {
    __shared__ int s[1024];
    __shared__ int carry;
    if (threadIdx.x == 0) { carry = 0; g_offs[0] = 0; }
    __syncthreads();
    for (int base = 0; base < NN; base += 1024) {
        int i = base + threadIdx.x;
        int v = (i < NN) ? g_deg[i] : 0;
        s[threadIdx.x] = v;
        __syncthreads();
#pragma unroll
        for (int off = 1; off < 1024; off <<= 1) {
            int t = 0;
            if (threadIdx.x >= off) t = s[threadIdx.x - off];
            __syncthreads();
            if (threadIdx.x >= off) s[threadIdx.x] += t;
            __syncthreads();
        }
        int cur = carry;
        if (i < NN) {
            int incl = cur + s[threadIdx.x];
            g_offs[i + 1] = incl;
            g_cursor[i] = incl - v;
        }
        __syncthreads();
        if (threadIdx.x == 0) carry = cur + s[1023];
        __syncthreads();
    }
}
__global__ void scatter_kernel(const int* __restrict__ ei) {
    int i = blockIdx.x * blockDim.x + threadIdx.x;
    if (i < NTOT) {
        int s, d;
        if (i < NE) { s = ei[i]; d = ei[NE + i]; }
        else        { s = d = i - NE; }
        int p = atomicAdd(&g_cursor[d], 1);
        g_csr[p] = s;
    }
}

// ---------------- bf16 split conversions ----------------
__global__ void split_act_kernel(const float* __restrict__ in, __nv_bfloat16* __restrict__ out, int M) {
    int idx = blockIdx.x * blockDim.x + threadIdx.x;
    int total = M * (INC / 4);
    if (idx >= total) return;
    int n = idx / (INC / 4);
    int c4 = (idx % (INC / 4)) * 4;
    float4 v = *(const float4*)(in + (size_t)n * INC + c4);
    float vv[4] = {v.x, v.y, v.z, v.w};
    unsigned short hs[4], ls[4];
#pragma unroll
    for (int i = 0; i < 4; i++) {
        __nv_bfloat16 h = __float2bfloat16(vv[i]);
        __nv_bfloat16 l = __float2bfloat16(vv[i] - __bfloat162float(h));
        hs[i] = *(unsigned short*)&h;
        ls[i] = *(unsigned short*)&l;
    }
    __nv_bfloat16* row = out + (size_t)n * KSPLIT;
    ushort4 hv = make_ushort4(hs[0], hs[1], hs[2], hs[3]);
    ushort4 lv = make_ushort4(ls[0], ls[1], ls[2], ls[3]);
    *(ushort4*)(row + c4)            = hv;
    *(ushort4*)(row + INC + c4)      = lv;
    *(ushort4*)(row + 2 * INC + c4)  = hv;
}
// coalesced-write mapping: thread idx -> (n = idx/INC, k = idx%INC)
__global__ void split_w_kernel(const float* __restrict__ in, __nv_bfloat16* __restrict__ out, int Nw) {
    int idx = blockIdx.x * blockDim.x + threadIdx.x;
    if (idx >= INC * Nw) return;
    int n = idx / INC, k = idx % INC;
    float v = in[(size_t)k * Nw + n];
    __nv_bfloat16 h = __float2bfloat16(v);
    __nv_bfloat16 l = __float2bfloat16(v - __bfloat162float(h));
    __nv_bfloat16* row = out + (size_t)n * KSPLIT;
    row[k] = h;
    row[INC + k] = h;
    row[2 * INC + k] = l;
}

// ---------------- bf16 tensor-core GEMM (NT) ----------------
#define BM 128
#define BN 128
#define BK 32
#define APAD 40

__global__ __launch_bounds__(256, 2) void mma_gemm_kernel(
    const __nv_bfloat16* __restrict__ A, const __nv_bfloat16* __restrict__ Bt,
    float* __restrict__ C, int M, int Nc, int K)
{
    __shared__ __nv_bfloat16 As[2][BM][APAD];
    __shared__ __nv_bfloat16 Bs[2][BN][APAD];

    int tid = threadIdx.x;
    int warp = tid >> 5, lane = tid & 31;
    int wm = (warp & 3) * 32;
    int wn = (warp >> 2) * 64;
    int m0 = blockIdx.y * BM, n0 = blockIdx.x * BN;
    int g = lane >> 2, t4 = lane & 3;

    int a_row = (lane & 7) + ((lane >> 3) & 1) * 8;
    int a_half = (lane >> 4) * 8;
    int b_row = (lane & 7) + ((lane >> 4) << 3);
    int b_half = ((lane >> 3) & 1) * 8;

    float acc[2][8][4];
#pragma unroll
    for (int mi = 0; mi < 2; mi++)
#pragma unroll
        for (int ni = 0; ni < 8; ni++)
#pragma unroll
            for (int j = 0; j < 4; j++) acc[mi][ni][j] = 0.f;

    uint4 ra[2], rb[2];
    int nk = K / BK;

#define LOADG(KT) {                                                              \
        int k0 = (KT) * BK;                                                      \
        _Pragma("unroll")                                                        \
        for (int i = 0; i < 2; i++) {                                            \
            int uu = tid + i * 256; int r = uu >> 2; int cq = (uu & 3) * 8;      \
            int gr = m0 + r;                                                     \
            ra[i] = (gr < M) ? *(const uint4*)(A + (size_t)gr * K + k0 + cq)     \
                             : make_uint4(0u, 0u, 0u, 0u);                       \
            rb[i] = *(const uint4*)(Bt + (size_t)(n0 + r) * K + k0 + cq);        \
        } }
#define STORES(BUF) {                                                            \
        _Pragma("unroll")                                                        \
        for (int i = 0; i < 2; i++) {                                            \
            int uu = tid + i * 256; int r = uu >> 2; int cq = (uu & 3) * 8;      \
            *(uint4*)&As[BUF][r][cq] = ra[i];                                    \
            *(uint4*)&Bs[BUF][r][cq] = rb[i];                                    \
        } }

    LOADG(0); STORES(0); __syncthreads();

    for (int kt = 0; kt < nk; kt++) {
        int buf = kt & 1;
        if (kt + 1 < nk) LOADG(kt + 1);
#pragma unroll
        for (int kk = 0; kk < 2; kk++) {
            int kb = kk * 16;
            uint32_t af[2][4];
            uint32_t bfrag[8][2];
#pragma unroll
            for (int mi = 0; mi < 2; mi++) {
                uint32_t ad = smem_u32(&As[buf][wm + mi * 16 + a_row][kb + a_half]);
                ldsm_x4(af[mi][0], af[mi][1], af[mi][2], af[mi][3], ad);
            }
#pragma unroll
            for (int p = 0; p < 4; p++) {
                uint32_t bd = smem_u32(&Bs[buf][wn + p * 16 + b_row][kb + b_half]);
                ldsm_x4(bfrag[2 * p][0], bfrag[2 * p][1], bfrag[2 * p + 1][0], bfrag[2 * p + 1][1], bd);
            }
#pragma unroll
            for (int mi = 0; mi < 2; mi++)
#pragma unroll
                for (int ni = 0; ni < 8; ni++) {
                    asm volatile(
                        "mma.sync.aligned.m16n8k16.row.col.f32.bf16.bf16.f32 "
                        "{%0,%1,%2,%3}, {%4,%5,%6,%7}, {%8,%9}, {%0,%1,%2,%3};\n"
                        : "+f"(acc[mi][ni][0]), "+f"(acc[mi][ni][1]),
                          "+f"(acc[mi][ni][2]), "+f"(acc[mi][ni][3])
                        : "r"(af[mi][0]), "r"(af[mi][1]), "r"(af[mi][2]), "r"(af[mi][3]),
                          "r"(bfrag[ni][0]), "r"(bfrag[ni][1]));
                }
        }
        if (kt + 1 < nk) STORES((kt + 1) & 1);
        __syncthreads();
    }

#pragma unroll
    for (int mi = 0; mi < 2; mi++) {
        int r = m0 + wm + mi * 16;
#pragma unroll
        for (int ni = 0; ni < 8; ni++) {
            int c = n0 + wn + ni * 8 + 2 * t4;
            if (r + g < M) {
                float2 v0 = make_float2(acc[mi][ni][0], acc[mi][ni][1]);
                *(float2*)(C + (size_t)(r + g) * Nc + c) = v0;
            }
            if (r + g + 8 < M) {
                float2 v1 = make_float2(acc[mi][ni][2], acc[mi][ni][3]);
                *(float2*)(C + (size_t)(r + g + 8) * Nc + c) = v1;
            }
        }
    }
#undef LOADG
#undef STORES
}

// ---------------- per-node attention logits ----------------
__global__ void alpha1_kernel(const float* __restrict__ asrc, const float* __restrict__ adst) {
    int gw = (blockIdx.x * blockDim.x + threadIdx.x) >> 5;
    int lane = threadIdx.x & 31;
    if (gw >= NN) return;
    const float* hr = g_h1 + (size_t)gw * HID1;
#pragma unroll
    for (int hd = 0; hd < 8; hd++) {
        int c0 = hd * 64 + lane, c1 = c0 + 32;
        float h0 = hr[c0], h1v = hr[c1];
        float vs = h0 * asrc[c0] + h1v * asrc[c1];
        float vd = h0 * adst[c0] + h1v * adst[c1];
        vs = warp_sum(vs);
        vd = warp_sum(vd);
        if (lane == 0) { g_as1[gw * 8 + hd] = vs; g_ad1[gw * 8 + hd] = vd; }
    }
}
__global__ void alpha2_kernel(const float* __restrict__ asrc, const float* __restrict__ adst) {
    int gw = (blockIdx.x * blockDim.x + threadIdx.x) >> 5;
    int lane = threadIdx.x & 31;
    if (gw >= NN) return;
    const float* hr = g_h2 + (size_t)gw * OUTC;
    float vs = 0.f, vd = 0.f;
#pragma unroll
    for (int c = 0; c < OUTC; c += 32) {
        float hv = hr[c + lane];
        vs += hv * asrc[c + lane];
        vd += hv * adst[c + lane];
    }
    vs = warp_sum(vs);
    vd = warp_sum(vd);
    if (lane == 0) { g_as2[gw] = vs; g_ad2[gw] = vd; }
}

// ---------------- layer1 aggregation: single-pass softmax + gather + bias + elu + bf16 split ----------------
__global__ void agg1_kernel(const float* __restrict__ bias) {
    int n = blockIdx.x;
    int tid = threadIdx.x;
    int beg = g_offs[n], end = g_offs[n + 1];
    int deg = end - beg;

    __shared__ float s_ad[8];
    __shared__ float s_max[8];
    __shared__ float s_inv[8];
    __shared__ int   s_src[CAP1];
    __shared__ float s_alpha[CAP1][9];   // pad 9: conflict-free column reads
    __shared__ unsigned s_maxi[8];
    __shared__ float s_sum8[8];

    if (tid < 8) {
        s_ad[tid] = g_ad1[n * 8 + tid];
        s_maxi[tid] = 0x007FFFFFu;
        s_sum8[tid] = 0.f;
    }
    __syncthreads();

    int c = 2 * tid;
    int hch = c >> 6;
    float accx = 0.f, accy = 0.f;

    if (deg <= CAP1) {
        // stage logits + src once
        for (int base = 0; base < deg; base += 32) {
            int el = base + (tid >> 3), hh = tid & 7;
            if (el < deg) {
                int s = g_csr[beg + el];
                if (hh == 0) s_src[el] = s;
                s_alpha[el][hh] = lrelu(g_as1[s * 8 + hh] + s_ad[hh]);
            }
        }
        __syncthreads();
        // per-head stats: warp h handles head h
        {
            int h = tid >> 5, l = tid & 31;
            float m = -INFINITY;
            for (int e = l; e < deg; e += 32) m = fmaxf(m, s_alpha[e][h]);
            m = warp_max(m);
            float ssum = 0.f;
            for (int e = l; e < deg; e += 32) ssum += __expf(s_alpha[e][h] - m);
            ssum = warp_sum(ssum);
            if (l == 0) { s_max[h] = m; s_inv[h] = 1.f / (ssum + 1e-16f); }
        }
        __syncthreads();
        // coef in place
        for (int base = 0; base < deg; base += 32) {
            int el = base + (tid >> 3), hh = tid & 7;
            if (el < deg) s_alpha[el][hh] = __expf(s_alpha[el][hh] - s_max[hh]) * s_inv[hh];
        }
        __syncthreads();
        // gather
        int e = 0;
        for (; e + 4 <= deg; e += 4) {
            float2 v0 = *(const float2*)(g_h1 + (size_t)s_src[e + 0] * HID1 + c);
            float2 v1 = *(const float2*)(g_h1 + (size_t)s_src[e + 1] * HID1 + c);
            float2 v2 = *(const float2*)(g_h1 + (size_t)s_src[e + 2] * HID1 + c);
            float2 v3 = *(const float2*)(g_h1 + (size_t)s_src[e + 3] * HID1 + c);
            float k0 = s_alpha[e + 0][hch], k1 = s_alpha[e + 1][hch];
            float k2 = s_alpha[e + 2][hch], k3 = s_alpha[e + 3][hch];
            accx += v0.x * k0 + v1.x * k1 + v2.x * k2 + v3.x * k3;
            accy += v0.y * k0 + v1.y * k1 + v2.y * k2 + v3.y * k3;
        }
        for (; e < deg; e++) {
            float2 v = *(const float2*)(g_h1 + (size_t)s_src[e] * HID1 + c);
            float kc = s_alpha[e][hch];
            accx += v.x * kc;
            accy += v.y * kc;
        }
    } else {
        // generic fallback (3-pass, chunked)
        const float4* as4 = (const float4*)g_as1;
        float lmax[8];
#pragma unroll
        for (int h = 0; h < 8; h++) lmax[h] = -INFINITY;
        for (int e = beg + tid; e < end; e += 256) {
            int s = g_csr[e];
            float4 lo = as4[s * 2], hi = as4[s * 2 + 1];
            float av[8] = {lo.x, lo.y, lo.z, lo.w, hi.x, hi.y, hi.z, hi.w};
#pragma unroll
            for (int h = 0; h < 8; h++) lmax[h] = fmaxf(lmax[h], lrelu(av[h] + s_ad[h]));
        }
#pragma unroll
        for (int h = 0; h < 8; h++) atomicMax(&s_maxi[h], fenc(lmax[h]));
        __syncthreads();
        if (tid < 8) s_max[tid] = fdec(s_maxi[tid]);
        __syncthreads();
        float lsum[8];
#pragma unroll
        for (int h = 0; h < 8; h++) lsum[h] = 0.f;
        for (int e = beg + tid; e < end; e += 256) {
            int s = g_csr[e];
            float4 lo = as4[s * 2], hi = as4[s * 2 + 1];
            float av[8] = {lo.x, lo.y, lo.z, lo.w, hi.x, hi.y, hi.z, hi.w};
#pragma unroll
            for (int h = 0; h < 8; h++) lsum[h] += __expf(lrelu(av[h] + s_ad[h]) - s_max[h]);
        }
#pragma unroll
        for (int h = 0; h < 8; h++) atomicAdd(&s_sum8[h], lsum[h]);
        __syncthreads();
        if (tid < 8) s_inv[tid] = 1.f / (s_sum8[tid] + 1e-16f);
        __syncthreads();
        for (int cb = beg; cb < end; cb += 32) {
            int cn = end - cb; if (cn > 32) cn = 32;
            int el = tid >> 3, hh = tid & 7;
            if (el < cn) {
                int s = g_csr[cb + el];
                float a = lrelu(g_as1[s * 8 + hh] + s_ad[hh]);
                s_alpha[el][hh] = __expf(a - s_max[hh]) * s_inv[hh];
                if (hh == 0) s_src[el] = s;
            }
            __syncthreads();
            for (int e = 0; e < cn; e++) {
                float2 v = *(const float2*)(g_h1 + (size_t)s_src[e] * HID1 + c);
                float kc = s_alpha[e][hch];
                accx += v.x * kc;
                accy += v.y * kc;
            }
            __syncthreads();
        }
    }

    float2 bv = *(const float2*)(bias + c);
    float ox = accx + bv.x, oy = accy + bv.y;
    ox = ox > 0.f ? ox : expm1f(ox);
    oy = oy > 0.f ? oy : expm1f(oy);
    __nv_bfloat16 hx = __float2bfloat16(ox), hy = __float2bfloat16(oy);
    __nv_bfloat16 lx = __float2bfloat16(ox - __bfloat162float(hx));
    __nv_bfloat16 ly = __float2bfloat16(oy - __bfloat162float(hy));
    __nv_bfloat16* row = g_o1s + (size_t)n * KSPLIT;
    ushort2 hv = make_ushort2(*(unsigned short*)&hx, *(unsigned short*)&hy);
    ushort2 lv = make_ushort2(*(unsigned short*)&lx, *(unsigned short*)&ly);
    *(ushort2*)(row + c)           = hv;
    *(ushort2*)(row + INC + c)     = lv;
    *(ushort2*)(row + 2 * INC + c) = hv;
}

// ---------------- layer2 aggregation + bias + log-softmax ----------------
__global__ void agg2_kernel(const float* __restrict__ bias, float* __restrict__ out) {
    int n = blockIdx.x;
    int tid = threadIdx.x;
    int beg = g_offs[n], end = g_offs[n + 1];
    int deg = end - beg;

    __shared__ float s_ad;
    __shared__ float s_max;
    __shared__ float s_inv;
    __shared__ unsigned s_maxi;
    __shared__ float s_sum1;
    __shared__ int   s_src[CAP2];
    __shared__ float s_alpha[CAP2];
    __shared__ float shm[8];
    __shared__ float shs[8];

    if (tid == 0) {
        s_ad = g_ad2[n];
        s_maxi = 0x007FFFFFu;
        s_sum1 = 0.f;
    }
    __syncthreads();

    float acc = 0.f;

    if (deg <= CAP2) {
        if (tid < deg) {
            int s = g_csr[beg + tid];
            s_src[tid] = s;
            s_alpha[tid] = lrelu(g_as2[s] + s_ad);
        }
        __syncthreads();
        if (tid < 32) {
            float m = -INFINITY;
            for (int e = tid; e < deg; e += 32) m = fmaxf(m, s_alpha[e]);
            m = warp_max(m);
            float ssum = 0.f;
            for (int e = tid; e < deg; e += 32) ssum += __expf(s_alpha[e] - m);
            ssum = warp_sum(ssum);
            if (tid == 0) { s_max = m; s_inv = 1.f / (ssum + 1e-16f); }
        }
        __syncthreads();
        if (tid < deg) s_alpha[tid] = __expf(s_alpha[tid] - s_max) * s_inv;
        __syncthreads();
        int e = 0;
        for (; e + 4 <= deg; e += 4) {
            float v0 = g_h2[(size_t)s_src[e + 0] * OUTC + tid];
            float v1 = g_h2[(size_t)s_src[e + 1] * OUTC + tid];
            float v2 = g_h2[(size_t)s_src[e + 2] * OUTC + tid];
            float v3 = g_h2[(size_t)s_src[e + 3] * OUTC + tid];
            acc += v0 * s_alpha[e + 0] + v1 * s_alpha[e + 1] + v2 * s_alpha[e + 2] + v3 * s_alpha[e + 3];
        }
        for (; e < deg; e++) acc += g_h2[(size_t)s_src[e] * OUTC + tid] * s_alpha[e];
    } else {
        float lmax = -INFINITY;
        for (int e = beg + tid; e < end; e += 256) {
            float a = lrelu(g_as2[g_csr[e]] + s_ad);
            lmax = fmaxf(lmax, a);
        }
        atomicMax(&s_maxi, fenc(lmax));
        __syncthreads();
        if (tid == 0) s_max = fdec(s_maxi);
        __syncthreads();
        float lsum = 0.f;
        for (int e = beg + tid; e < end; e += 256) {
            float a = lrelu(g_as2[g_csr[e]] + s_ad);
            lsum += __expf(a - s_max);
        }
        atomicAdd(&s_sum1, lsum);
        __syncthreads();
        if (tid == 0) s_inv = 1.f / (s_sum1 + 1e-16f);
        __syncthreads();
        for (int cb = beg; cb < end; cb += CAP2) {
            int cn = end - cb; if (cn > CAP2) cn = CAP2;
            if (tid < cn) {
                int s = g_csr[cb + tid];
                float a = lrelu(g_as2[s] + s_ad);
                s_alpha[tid] = __expf(a - s_max) * s_inv;
                s_src[tid] = s;
            }
            __syncthreads();
            for (int e = 0; e < cn; e++) acc += g_h2[(size_t)s_src[e] * OUTC + tid] * s_alpha[e];
            __syncthreads();
        }
    }

    float v = acc + bias[tid];
    // fused log-softmax
    float wm = warp_max(v);
    if ((tid & 31) == 0) shm[tid >> 5] = wm;
    __syncthreads();
    float m = shm[0];
#pragma unroll
    for (int i = 1; i < 8; i++) m = fmaxf(m, shm[i]);
    float ex = __expf(v - m);
    float ws = warp_sum(ex);
    if ((tid & 31) == 0) shs[tid >> 5] = ws;
    __syncthreads();
    float s = 0.f;
#pragma unroll
    for (int i = 0; i < 8; i++) s += shs[i];
    out[(size_t)n * OUTC + tid] = v - m - __logf(s);
}

// ---------------- launch ----------------
extern "C" void kernel_launch(void* const* d_in, const int* in_sizes, int n_in,
                              void* d_out, int out_size) {
    const float* x    = (const float*)d_in[0];
    const int*   ei   = (const int*)d_in[1];
    const float* W1   = (const float*)d_in[2];
    const float* as1  = (const float*)d_in[3];
    const float* ad1  = (const float*)d_in[4];
    const float* b1   = (const float*)d_in[5];
    const float* W2   = (const float*)d_in[6];
    const float* as2  = (const float*)d_in[7];
    const float* ad2  = (const float*)d_in[8];
    const float* b2   = (const float*)d_in[9];
    float* out = (float*)d_out;

    float *p_h1, *p_h2;
    __nv_bfloat16 *p_xs, *p_o1s, *p_w1t, *p_w2t;
    cudaGetSymbolAddress((void**)&p_h1, g_h1);
    cudaGetSymbolAddress((void**)&p_h2, g_h2);
    cudaGetSymbolAddress((void**)&p_xs, g_xs);
    cudaGetSymbolAddress((void**)&p_o1s, g_o1s);
    cudaGetSymbolAddress((void**)&p_w1t, g_w1t);
    cudaGetSymbolAddress((void**)&p_w2t, g_w2t);

    // (1-3)
    split_act_kernel<<<(NN * (INC / 4) + 255) / 256, 256>>>(x, p_xs, NN);
    split_w_kernel<<<(INC * HID1 + 255) / 256, 256>>>(W1, p_w1t, HID1);
    split_w_kernel<<<(INC * OUTC + 255) / 256, 256>>>(W2, p_w2t, OUTC);

    // (4) PROBE: duplicate agg1 so the ncu capture (4th launch) profiles it.
    // Reads steady-state scratch from the previous replay (identical every
    // replay); its g_o1s output is rewritten by the real agg1 below.
    // First-ever call: g_offs is zero-initialized -> deg=0 -> no OOB.
    agg1_kernel<<<NN, 256>>>(b1);

    // (5) layer1 GEMM
    mma_gemm_kernel<<<dim3(HID1 / BN, (NN + BM - 1) / BM), 256>>>(p_xs, p_w1t, p_h1, NN, HID1, KSPLIT);

    // (6-9) CSR build
    zero_deg_kernel<<<(NN + 255) / 256, 256>>>();
    deg_kernel<<<(NTOT + 255) / 256, 256>>>(ei);
    scan_kernel<<<1, 1024>>>();
    scatter_kernel<<<(NTOT + 255) / 256, 256>>>(ei);

    // (10-11) layer1 attention + aggregation
    alpha1_kernel<<<(NN + 7) / 8, 256>>>(as1, ad1);
    agg1_kernel<<<NN, 256>>>(b1);

    // (12-14) layer2
    mma_gemm_kernel<<<dim3(OUTC / BN, (NN + BM - 1) / BM), 256>>>(p_o1s, p_w2t, p_h2, NN, OUTC, KSPLIT);
    alpha2_kernel<<<(NN + 7) / 8, 256>>>(as2, ad2);
    agg2_kernel<<<NN, 256>>>(b2, out);
}

// round 5
// speedup vs baseline: 2.5823x; 1.3370x over previous
#include <cuda_runtime.h>
#include <cuda_bf16.h>
#include <math.h>
#include <stdint.h>

#define NN     20000
#define INC    512
#define HID1   512      // H1*HID = 8*64
#define OUTC   256
#define NE     320000
#define NTOT   (NE + NN)   // edges + self loops = 340000
#define NEGS   0.2f
#define KSPLIT 1536        // 3 * 512 (hi | lo | hi blocks along K)
#define CAP1   96
#define CAP2   128

// ---------------- scratch (device globals: no allocation allowed) ----------------
__device__ float g_h1[(size_t)NN * HID1];
__device__ float g_h2[(size_t)NN * OUTC];
__device__ __nv_bfloat16 g_xs[(size_t)NN * KSPLIT];
__device__ __nv_bfloat16 g_o1s[(size_t)NN * KSPLIT];
__device__ __nv_bfloat16 g_w1t[(size_t)HID1 * KSPLIT];
__device__ __nv_bfloat16 g_w2t[(size_t)OUTC * KSPLIT];
__device__ float g_as1[NN * 8];
__device__ float g_ad1[NN * 8];
__device__ float g_as2[NN];
__device__ float g_ad2[NN];
__device__ int   g_deg[NN];
__device__ int   g_offs[NN + 1];
__device__ int   g_cursor[NN];
__device__ int   g_csr[NTOT];

// ---------------- helpers ----------------
__device__ __forceinline__ float warp_sum(float v) {
#pragma unroll
    for (int o = 16; o; o >>= 1) v += __shfl_xor_sync(0xffffffffu, v, o);
    return v;
}
__device__ __forceinline__ float warp_max(float v) {
#pragma unroll
    for (int o = 16; o; o >>= 1) v = fmaxf(v, __shfl_xor_sync(0xffffffffu, v, o));
    return v;
}
__device__ __forceinline__ unsigned fenc(float f) {
    unsigned u = __float_as_uint(f);
    return (u >> 31) ? ~u : (u | 0x80000000u);
}
__device__ __forceinline__ float fdec(unsigned u) {
    return __uint_as_float((u >> 31) ? (u & 0x7fffffffu) : ~u);
}
__device__ __forceinline__ float lrelu(float a) { return a > 0.f ? a : NEGS * a; }

__device__ __forceinline__ uint32_t smem_u32(const void* p) {
    return (uint32_t)__cvta_generic_to_shared(p);
}
__device__ __forceinline__ void ldsm_x4(uint32_t& r0, uint32_t& r1, uint32_t& r2, uint32_t& r3, uint32_t addr) {
    asm volatile("ldmatrix.sync.aligned.m8n8.x4.shared.b16 {%0,%1,%2,%3}, [%4];\n"
                 : "=r"(r0), "=r"(r1), "=r"(r2), "=r"(r3) : "r"(addr));
}
__device__ __forceinline__ void cp_async16(uint32_t dst, const void* src, bool pred) {
    int sz = pred ? 16 : 0;
    asm volatile("cp.async.cg.shared.global [%0], [%1], 16, %2;\n"
                 :: "r"(dst), "l"(src), "r"(sz));
}
__device__ __forceinline__ void cp_commit() {
    asm volatile("cp.async.commit_group;\n" ::: "memory");
}

// ---------------- CSR build ----------------
__global__ void zero_deg_kernel() {
    int i = blockIdx.x * blockDim.x + threadIdx.x;
    if (i < NN) g_deg[i] = 0;
}
__global__ void deg_kernel(const int* __restrict__ ei) {
    int i = blockIdx.x * blockDim.x + threadIdx.x;
    if (i < NTOT) {
        int d = (i < NE) ? ei[NE + i] : (i - NE);
        atomicAdd(&g_deg[d], 1);
    }
}
// warp-shuffle inclusive scan; writes g_offs[1..NN] and g_cursor[i] = g_offs[i]
__global__ void scan_kernel() {
    __shared__ int warpsum[32];
    __shared__ int carry;
    int tid = threadIdx.x, lane = tid & 31, w = tid >> 5;
    if (tid == 0) { carry = 0; g_offs[0] = 0; }
    __syncthreads();
    for (int base = 0; base < NN; base += 1024) {
        int i = base + tid;
        int v = (i < NN) ? g_deg[i] : 0;
        int x = v;
#pragma unroll
        for (int o = 1; o < 32; o <<= 1) {
            int t = __shfl_up_sync(0xffffffffu, x, o);
            if (lane >= o) x += t;
        }
        if (lane == 31) warpsum[w] = x;
        __syncthreads();
        if (w == 0) {
            int s = warpsum[lane];
#pragma unroll
            for (int o = 1; o < 32; o <<= 1) {
                int t = __shfl_up_sync(0xffffffffu, s, o);
                if (lane >= o) s += t;
            }
            warpsum[lane] = s;
        }
        __syncthreads();
        int incl = carry + (w ? warpsum[w - 1] : 0) + x;
        if (i < NN) {
            g_offs[i + 1] = incl;
            g_cursor[i] = incl - v;
        }
        __syncthreads();
        if (tid == 1023) carry = incl;
        __syncthreads();
    }
}
__global__ void scatter_kernel(const int* __restrict__ ei) {
    int i = blockIdx.x * blockDim.x + threadIdx.x;
    if (i < NTOT) {
        int s, d;
        if (i < NE) { s = ei[i]; d = ei[NE + i]; }
        else        { s = d = i - NE; }
        int p = atomicAdd(&g_cursor[d], 1);
        g_csr[p] = s;
    }
}

// ---------------- bf16 split conversions ----------------
__global__ void split_act_kernel(const float* __restrict__ in, __nv_bfloat16* __restrict__ out, int M) {
    int idx = blockIdx.x * blockDim.x + threadIdx.x;
    int total = M * (INC / 4);
    if (idx >= total) return;
    int n = idx / (INC / 4);
    int c4 = (idx % (INC / 4)) * 4;
    float4 v = *(const float4*)(in + (size_t)n * INC + c4);
    float vv[4] = {v.x, v.y, v.z, v.w};
    unsigned short hs[4], ls[4];
#pragma unroll
    for (int i = 0; i < 4; i++) {
        __nv_bfloat16 h = __float2bfloat16(vv[i]);
        __nv_bfloat16 l = __float2bfloat16(vv[i] - __bfloat162float(h));
        hs[i] = *(unsigned short*)&h;
        ls[i] = *(unsigned short*)&l;
    }
    __nv_bfloat16* row = out + (size_t)n * KSPLIT;
    ushort4 hv = make_ushort4(hs[0], hs[1], hs[2], hs[3]);
    ushort4 lv = make_ushort4(ls[0], ls[1], ls[2], ls[3]);
    *(ushort4*)(row + c4)            = hv;
    *(ushort4*)(row + INC + c4)      = lv;
    *(ushort4*)(row + 2 * INC + c4)  = hv;
}
__global__ void split_w_kernel(const float* __restrict__ in, __nv_bfloat16* __restrict__ out, int Nw) {
    int idx = blockIdx.x * blockDim.x + threadIdx.x;
    if (idx >= INC * Nw) return;
    int n = idx / INC, k = idx % INC;
    float v = in[(size_t)k * Nw + n];
    __nv_bfloat16 h = __float2bfloat16(v);
    __nv_bfloat16 l = __float2bfloat16(v - __bfloat162float(h));
    __nv_bfloat16* row = out + (size_t)n * KSPLIT;
    row[k] = h;
    row[INC + k] = h;
    row[2 * INC + k] = l;
}

// ---------------- bf16 tensor-core GEMM (NT), cp.async 3-stage pipeline ----------------
#define BM 128
#define BN 128
#define BK 32
#define APAD 40
#define NSTAGE 3
#define GEMM_SMEM (NSTAGE * (BM + BN) * APAD * 2)   // 61440 bytes

__global__ __launch_bounds__(256, 2) void mma_gemm_kernel(
    const __nv_bfloat16* __restrict__ A, const __nv_bfloat16* __restrict__ Bt,
    float* __restrict__ C, int M, int Nc, int K)
{
    extern __shared__ __nv_bfloat16 sm[];
    const int STG = (BM + BN) * APAD;

    int tid = threadIdx.x;
    int warp = tid >> 5, lane = tid & 31;
    int wm = (warp & 3) * 32;
    int wn = (warp >> 2) * 64;
    int m0 = blockIdx.y * BM, n0 = blockIdx.x * BN;
    int g = lane >> 2, t4 = lane & 3;

    int a_row = (lane & 7) + ((lane >> 3) & 1) * 8;
    int a_half = (lane >> 4) * 8;
    int b_row = (lane & 7) + ((lane >> 4) << 3);
    int b_half = ((lane >> 3) & 1) * 8;

    // load mapping: rows r0 (0..63) and r0+64, 16B chunk cq
    int lr0 = tid >> 2;
    int lcq = (tid & 3) * 8;
    bool am0 = (m0 + lr0) < M;
    bool am1 = (m0 + lr0 + 64) < M;
    const __nv_bfloat16* gA0 = A + (size_t)(m0 + lr0) * K + lcq;
    const __nv_bfloat16* gA1 = A + (size_t)(m0 + lr0 + 64) * K + lcq;
    const __nv_bfloat16* gB0 = Bt + (size_t)(n0 + lr0) * K + lcq;
    const __nv_bfloat16* gB1 = Bt + (size_t)(n0 + lr0 + 64) * K + lcq;

    float acc[2][8][4];
#pragma unroll
    for (int mi = 0; mi < 2; mi++)
#pragma unroll
        for (int ni = 0; ni < 8; ni++)
#pragma unroll
            for (int j = 0; j < 4; j++) acc[mi][ni][j] = 0.f;

    int nk = K / BK;

#define ISSUE(KT) {                                                            \
        int _buf = (KT) % NSTAGE;                                              \
        int _k0 = (KT) * BK;                                                   \
        __nv_bfloat16* sA = sm + _buf * STG;                                   \
        __nv_bfloat16* sB = sA + BM * APAD;                                    \
        cp_async16(smem_u32(sA + lr0 * APAD + lcq),        gA0 + _k0, am0);    \
        cp_async16(smem_u32(sA + (lr0 + 64) * APAD + lcq), gA1 + _k0, am1);    \
        cp_async16(smem_u32(sB + lr0 * APAD + lcq),        gB0 + _k0, true);   \
        cp_async16(smem_u32(sB + (lr0 + 64) * APAD + lcq), gB1 + _k0, true);   \
        cp_commit();                                                           \
    }

    ISSUE(0);
    ISSUE(1);

    for (int kt = 0; kt < nk; kt++) {
        asm volatile("cp.async.wait_group 1;\n" ::: "memory");
        __syncthreads();
        if (kt + 2 < nk) { ISSUE(kt + 2); }
        else             { cp_commit(); }

        __nv_bfloat16* sA = sm + (kt % NSTAGE) * STG;
        __nv_bfloat16* sB = sA + BM * APAD;
#pragma unroll
        for (int kk = 0; kk < 2; kk++) {
            int kb = kk * 16;
            uint32_t af[2][4];
            uint32_t bfrag[8][2];
#pragma unroll
            for (int mi = 0; mi < 2; mi++) {
                uint32_t ad = smem_u32(sA + (wm + mi * 16 + a_row) * APAD + kb + a_half);
                ldsm_x4(af[mi][0], af[mi][1], af[mi][2], af[mi][3], ad);
            }
#pragma unroll
            for (int p = 0; p < 4; p++) {
                uint32_t bd = smem_u32(sB + (wn + p * 16 + b_row) * APAD + kb + b_half);
                ldsm_x4(bfrag[2 * p][0], bfrag[2 * p][1], bfrag[2 * p + 1][0], bfrag[2 * p + 1][1], bd);
            }
#pragma unroll
            for (int mi = 0; mi < 2; mi++)
#pragma unroll
                for (int ni = 0; ni < 8; ni++) {
                    asm volatile(
                        "mma.sync.aligned.m16n8k16.row.col.f32.bf16.bf16.f32 "
                        "{%0,%1,%2,%3}, {%4,%5,%6,%7}, {%8,%9}, {%0,%1,%2,%3};\n"
                        : "+f"(acc[mi][ni][0]), "+f"(acc[mi][ni][1]),
                          "+f"(acc[mi][ni][2]), "+f"(acc[mi][ni][3])
                        : "r"(af[mi][0]), "r"(af[mi][1]), "r"(af[mi][2]), "r"(af[mi][3]),
                          "r"(bfrag[ni][0]), "r"(bfrag[ni][1]));
                }
        }
    }
#undef ISSUE

#pragma unroll
    for (int mi = 0; mi < 2; mi++) {
        int r = m0 + wm + mi * 16;
#pragma unroll
        for (int ni = 0; ni < 8; ni++) {
            int c = n0 + wn + ni * 8 + 2 * t4;
            if (r + g < M) {
                float2 v0 = make_float2(acc[mi][ni][0], acc[mi][ni][1]);
                *(float2*)(C + (size_t)(r + g) * Nc + c) = v0;
            }
            if (r + g + 8 < M) {
                float2 v1 = make_float2(acc[mi][ni][2], acc[mi][ni][3]);
                *(float2*)(C + (size_t)(r + g + 8) * Nc + c) = v1;
            }
        }
    }
}

// ---------------- per-node attention logits ----------------
__global__ void alpha1_kernel(const float* __restrict__ asrc, const float* __restrict__ adst) {
    int gw = (blockIdx.x * blockDim.x + threadIdx.x) >> 5;
    int lane = threadIdx.x & 31;
    if (gw >= NN) return;
    const float* hr = g_h1 + (size_t)gw * HID1;
#pragma unroll
    for (int hd = 0; hd < 8; hd++) {
        int c0 = hd * 64 + lane, c1 = c0 + 32;
        float h0 = hr[c0], h1v = hr[c1];
        float vs = h0 * asrc[c0] + h1v * asrc[c1];
        float vd = h0 * adst[c0] + h1v * adst[c1];
        vs = warp_sum(vs);
        vd = warp_sum(vd);
        if (lane == 0) { g_as1[gw * 8 + hd] = vs; g_ad1[gw * 8 + hd] = vd; }
    }
}
__global__ void alpha2_kernel(const float* __restrict__ asrc, const float* __restrict__ adst) {
    int gw = (blockIdx.x * blockDim.x + threadIdx.x) >> 5;
    int lane = threadIdx.x & 31;
    if (gw >= NN) return;
    const float* hr = g_h2 + (size_t)gw * OUTC;
    float vs = 0.f, vd = 0.f;
#pragma unroll
    for (int c = 0; c < OUTC; c += 32) {
        float hv = hr[c + lane];
        vs += hv * asrc[c + lane];
        vd += hv * adst[c + lane];
    }
    vs = warp_sum(vs);
    vd = warp_sum(vd);
    if (lane == 0) { g_as2[gw] = vs; g_ad2[gw] = vd; }
}

// ---------------- layer1 aggregation ----------------
__global__ void agg1_kernel(const float* __restrict__ bias) {
    int n = blockIdx.x;
    int tid = threadIdx.x;
    int beg = g_offs[n], end = g_offs[n + 1];
    int deg = end - beg;

    __shared__ float s_ad[8];
    __shared__ float s_max[8];
    __shared__ float s_inv[8];
    __shared__ int   s_src[CAP1];
    __shared__ float s_alpha[CAP1][9];
    __shared__ unsigned s_maxi[8];
    __shared__ float s_sum8[8];

    if (tid < 8) {
        s_ad[tid] = g_ad1[n * 8 + tid];
        s_maxi[tid] = 0x007FFFFFu;
        s_sum8[tid] = 0.f;
    }
    __syncthreads();

    int c = 2 * tid;
    int hch = c >> 6;
    float accx = 0.f, accy = 0.f;

    if (deg <= CAP1) {
        for (int base = 0; base < deg; base += 32) {
            int el = base + (tid >> 3), hh = tid & 7;
            if (el < deg) {
                int s = g_csr[beg + el];
                if (hh == 0) s_src[el] = s;
                s_alpha[el][hh] = lrelu(g_as1[s * 8 + hh] + s_ad[hh]);
            }
        }
        __syncthreads();
        {
            int h = tid >> 5, l = tid & 31;
            float m = -INFINITY;
            for (int e = l; e < deg; e += 32) m = fmaxf(m, s_alpha[e][h]);
            m = warp_max(m);
            float ssum = 0.f;
            for (int e = l; e < deg; e += 32) ssum += __expf(s_alpha[e][h] - m);
            ssum = warp_sum(ssum);
            if (l == 0) { s_max[h] = m; s_inv[h] = 1.f / (ssum + 1e-16f); }
        }
        __syncthreads();
        for (int base = 0; base < deg; base += 32) {
            int el = base + (tid >> 3), hh = tid & 7;
            if (el < deg) s_alpha[el][hh] = __expf(s_alpha[el][hh] - s_max[hh]) * s_inv[hh];
        }
        __syncthreads();
        int e = 0;
        for (; e + 4 <= deg; e += 4) {
            float2 v0 = *(const float2*)(g_h1 + (size_t)s_src[e + 0] * HID1 + c);
            float2 v1 = *(const float2*)(g_h1 + (size_t)s_src[e + 1] * HID1 + c);
            float2 v2 = *(const float2*)(g_h1 + (size_t)s_src[e + 2] * HID1 + c);
            float2 v3 = *(const float2*)(g_h1 + (size_t)s_src[e + 3] * HID1 + c);
            float k0 = s_alpha[e + 0][hch], k1 = s_alpha[e + 1][hch];
            float k2 = s_alpha[e + 2][hch], k3 = s_alpha[e + 3][hch];
            accx += v0.x * k0 + v1.x * k1 + v2.x * k2 + v3.x * k3;
            accy += v0.y * k0 + v1.y * k1 + v2.y * k2 + v3.y * k3;
        }
        for (; e < deg; e++) {
            float2 v = *(const float2*)(g_h1 + (size_t)s_src[e] * HID1 + c);
            float kc = s_alpha[e][hch];
            accx += v.x * kc;
            accy += v.y * kc;
        }
    } else {
        const float4* as4 = (const float4*)g_as1;
        float lmax[8];
#pragma unroll
        for (int h = 0; h < 8; h++) lmax[h] = -INFINITY;
        for (int e = beg + tid; e < end; e += 256) {
            int s = g_csr[e];
            float4 lo = as4[s * 2], hi = as4[s * 2 + 1];
            float av[8] = {lo.x, lo.y, lo.z, lo.w, hi.x, hi.y, hi.z, hi.w};
#pragma unroll
            for (int h = 0; h < 8; h++) lmax[h] = fmaxf(lmax[h], lrelu(av[h] + s_ad[h]));
        }
#pragma unroll
        for (int h = 0; h < 8; h++) atomicMax(&s_maxi[h], fenc(lmax[h]));
        __syncthreads();
        if (tid < 8) s_max[tid] = fdec(s_maxi[tid]);
        __syncthreads();
        float lsum[8];
#pragma unroll
        for (int h = 0; h < 8; h++) lsum[h] = 0.f;
        for (int e = beg + tid; e < end; e += 256) {
            int s = g_csr[e];
            float4 lo = as4[s * 2], hi = as4[s * 2 + 1];
            float av[8] = {lo.x, lo.y, lo.z, lo.w, hi.x, hi.y, hi.z, hi.w};
#pragma unroll
            for (int h = 0; h < 8; h++) lsum[h] += __expf(lrelu(av[h] + s_ad[h]) - s_max[h]);
        }
#pragma unroll
        for (int h = 0; h < 8; h++) atomicAdd(&s_sum8[h], lsum[h]);
        __syncthreads();
        if (tid < 8) s_inv[tid] = 1.f / (s_sum8[tid] + 1e-16f);
        __syncthreads();
        for (int cb = beg; cb < end; cb += 32) {
            int cn = end - cb; if (cn > 32) cn = 32;
            int el = tid >> 3, hh = tid & 7;
            if (el < cn) {
                int s = g_csr[cb + el];
                float a = lrelu(g_as1[s * 8 + hh] + s_ad[hh]);
                s_alpha[el][hh] = __expf(a - s_max[hh]) * s_inv[hh];
                if (hh == 0) s_src[el] = s;
            }
            __syncthreads();
            for (int e = 0; e < cn; e++) {
                float2 v = *(const float2*)(g_h1 + (size_t)s_src[e] * HID1 + c);
                float kc = s_alpha[e][hch];
                accx += v.x * kc;
                accy += v.y * kc;
            }
            __syncthreads();
        }
    }

    float2 bv = *(const float2*)(bias + c);
    float ox = accx + bv.x, oy = accy + bv.y;
    ox = ox > 0.f ? ox : expm1f(ox);
    oy = oy > 0.f ? oy : expm1f(oy);
    __nv_bfloat16 hx = __float2bfloat16(ox), hy = __float2bfloat16(oy);
    __nv_bfloat16 lx = __float2bfloat16(ox - __bfloat162float(hx));
    __nv_bfloat16 ly = __float2bfloat16(oy - __bfloat162float(hy));
    __nv_bfloat16* row = g_o1s + (size_t)n * KSPLIT;
    ushort2 hv = make_ushort2(*(unsigned short*)&hx, *(unsigned short*)&hy);
    ushort2 lv = make_ushort2(*(unsigned short*)&lx, *(unsigned short*)&ly);
    *(ushort2*)(row + c)           = hv;
    *(ushort2*)(row + INC + c)     = lv;
    *(ushort2*)(row + 2 * INC + c) = hv;
}

// ---------------- layer2 aggregation + bias + log-softmax ----------------
__global__ void agg2_kernel(const float* __restrict__ bias, float* __restrict__ out) {
    int n = blockIdx.x;
    int tid = threadIdx.x;
    int beg = g_offs[n], end = g_offs[n + 1];
    int deg = end - beg;

    __shared__ float s_ad;
    __shared__ float s_max;
    __shared__ float s_inv;
    __shared__ unsigned s_maxi;
    __shared__ float s_sum1;
    __shared__ int   s_src[CAP2];
    __shared__ float s_alpha[CAP2];
    __shared__ float shm[8];
    __shared__ float shs[8];

    if (tid == 0) {
        s_ad = g_ad2[n];
        s_maxi = 0x007FFFFFu;
        s_sum1 = 0.f;
    }
    __syncthreads();

    float acc = 0.f;

    if (deg <= CAP2) {
        if (tid < deg) {
            int s = g_csr[beg + tid];
            s_src[tid] = s;
            s_alpha[tid] = lrelu(g_as2[s] + s_ad);
        }
        __syncthreads();
        if (tid < 32) {
            float m = -INFINITY;
            for (int e = tid; e < deg; e += 32) m = fmaxf(m, s_alpha[e]);
            m = warp_max(m);
            float ssum = 0.f;
            for (int e = tid; e < deg; e += 32) ssum += __expf(s_alpha[e] - m);
            ssum = warp_sum(ssum);
            if (tid == 0) { s_max = m; s_inv = 1.f / (ssum + 1e-16f); }
        }
        __syncthreads();
        if (tid < deg) s_alpha[tid] = __expf(s_alpha[tid] - s_max) * s_inv;
        __syncthreads();
        int e = 0;
        for (; e + 4 <= deg; e += 4) {
            float v0 = g_h2[(size_t)s_src[e + 0] * OUTC + tid];
            float v1 = g_h2[(size_t)s_src[e + 1] * OUTC + tid];
            float v2 = g_h2[(size_t)s_src[e + 2] * OUTC + tid];
            float v3 = g_h2[(size_t)s_src[e + 3] * OUTC + tid];
            acc += v0 * s_alpha[e + 0] + v1 * s_alpha[e + 1] + v2 * s_alpha[e + 2] + v3 * s_alpha[e + 3];
        }
        for (; e < deg; e++) acc += g_h2[(size_t)s_src[e] * OUTC + tid] * s_alpha[e];
    } else {
        float lmax = -INFINITY;
        for (int e = beg + tid; e < end; e += 256) {
            float a = lrelu(g_as2[g_csr[e]] + s_ad);
            lmax = fmaxf(lmax, a);
        }
        atomicMax(&s_maxi, fenc(lmax));
        __syncthreads();
        if (tid == 0) s_max = fdec(s_maxi);
        __syncthreads();
        float lsum = 0.f;
        for (int e = beg + tid; e < end; e += 256) {
            float a = lrelu(g_as2[g_csr[e]] + s_ad);
            lsum += __expf(a - s_max);
        }
        atomicAdd(&s_sum1, lsum);
        __syncthreads();
        if (tid == 0) s_inv = 1.f / (s_sum1 + 1e-16f);
        __syncthreads();
        for (int cb = beg; cb < end; cb += CAP2) {
            int cn = end - cb; if (cn > CAP2) cn = CAP2;
            if (tid < cn) {
                int s = g_csr[cb + tid];
                float a = lrelu(g_as2[s] + s_ad);
                s_alpha[tid] = __expf(a - s_max) * s_inv;
                s_src[tid] = s;
            }
            __syncthreads();
            for (int e = 0; e < cn; e++) acc += g_h2[(size_t)s_src[e] * OUTC + tid] * s_alpha[e];
            __syncthreads();
        }
    }

    float v = acc + bias[tid];
    float wm = warp_max(v);
    if ((tid & 31) == 0) shm[tid >> 5] = wm;
    __syncthreads();
    float m = shm[0];
#pragma unroll
    for (int i = 1; i < 8; i++) m = fmaxf(m, shm[i]);
    float ex = __expf(v - m);
    float ws = warp_sum(ex);
    if ((tid & 31) == 0) shs[tid >> 5] = ws;
    __syncthreads();
    float s = 0.f;
#pragma unroll
    for (int i = 0; i < 8; i++) s += shs[i];
    out[(size_t)n * OUTC + tid] = v - m - __logf(s);
}

// ---------------- launch ----------------
extern "C" void kernel_launch(void* const* d_in, const int* in_sizes, int n_in,
                              void* d_out, int out_size) {
    const float* x    = (const float*)d_in[0];
    const int*   ei   = (const int*)d_in[1];
    const float* W1   = (const float*)d_in[2];
    const float* as1  = (const float*)d_in[3];
    const float* ad1  = (const float*)d_in[4];
    const float* b1   = (const float*)d_in[5];
    const float* W2   = (const float*)d_in[6];
    const float* as2  = (const float*)d_in[7];
    const float* ad2  = (const float*)d_in[8];
    const float* b2   = (const float*)d_in[9];
    float* out = (float*)d_out;

    float *p_h1, *p_h2;
    __nv_bfloat16 *p_xs, *p_o1s, *p_w1t, *p_w2t;
    cudaGetSymbolAddress((void**)&p_h1, g_h1);
    cudaGetSymbolAddress((void**)&p_h2, g_h2);
    cudaGetSymbolAddress((void**)&p_xs, g_xs);
    cudaGetSymbolAddress((void**)&p_o1s, g_o1s);
    cudaGetSymbolAddress((void**)&p_w1t, g_w1t);
    cudaGetSymbolAddress((void**)&p_w2t, g_w2t);

    cudaFuncSetAttribute(mma_gemm_kernel,
                         cudaFuncAttributeMaxDynamicSharedMemorySize, GEMM_SMEM);

    // (1-3) splits; launch #4 = layer1 GEMM (profiled by ncu)
    split_act_kernel<<<(NN * (INC / 4) + 255) / 256, 256>>>(x, p_xs, NN);
    split_w_kernel<<<(INC * HID1 + 255) / 256, 256>>>(W1, p_w1t, HID1);
    split_w_kernel<<<(INC * OUTC + 255) / 256, 256>>>(W2, p_w2t, OUTC);

    // (4) layer1 GEMM
    mma_gemm_kernel<<<dim3(HID1 / BN, (NN + BM - 1) / BM), 256, GEMM_SMEM>>>(
        p_xs, p_w1t, p_h1, NN, HID1, KSPLIT);

    // (5-8) CSR build
    zero_deg_kernel<<<(NN + 255) / 256, 256>>>();
    deg_kernel<<<(NTOT + 255) / 256, 256>>>(ei);
    scan_kernel<<<1, 1024>>>();
    scatter_kernel<<<(NTOT + 255) / 256, 256>>>(ei);

    // (9-10) layer1 attention + aggregation
    alpha1_kernel<<<(NN + 7) / 8, 256>>>(as1, ad1);
    agg1_kernel<<<NN, 256>>>(b1);

    // (11-13) layer2
    mma_gemm_kernel<<<dim3(OUTC / BN, (NN + BM - 1) / BM), 256, GEMM_SMEM>>>(
        p_o1s, p_w2t, p_h2, NN, OUTC, KSPLIT);
    alpha2_kernel<<<(NN + 7) / 8, 256>>>(as2, ad2);
    agg2_kernel<<<NN, 256>>>(b2, out);
}

// round 6
// speedup vs baseline: 3.1979x; 1.2384x over previous
#include <cuda_runtime.h>
#include <cuda_fp16.h>
#include <math.h>
#include <stdint.h>

#define NN     20000
#define INC    512
#define HID1   512      // H1*HID = 8*64
#define OUTC   256
#define NE     320000
#define NTOT   (NE + NN)   // edges + self loops = 340000
#define NEGS   0.2f
#define KSPLIT 1024        // 2 * 512 : [A_hi | A_lo] x [W_h | W_h]
#define CAP1   96
#define CAP2   128

// ---------------- scratch ----------------
__device__ float g_h1[(size_t)NN * HID1];
__device__ float g_h2[(size_t)NN * OUTC];
__device__ __half g_xs[(size_t)NN * KSPLIT];
__device__ __half g_o1s[(size_t)NN * KSPLIT];
__device__ __half g_w1t[(size_t)HID1 * KSPLIT];
__device__ __half g_w2t[(size_t)OUTC * KSPLIT];
__device__ float g_as1[NN * 8];
__device__ float g_ad1[NN * 8];
__device__ float g_as2[NN];
__device__ float g_ad2[NN];
__device__ int   g_deg[NN];
__device__ int   g_offs[NN + 1];
__device__ int   g_cursor[NN];
__device__ int   g_csr[NTOT];

// ---------------- helpers ----------------
__device__ __forceinline__ float warp_sum(float v) {
#pragma unroll
    for (int o = 16; o; o >>= 1) v += __shfl_xor_sync(0xffffffffu, v, o);
    return v;
}
__device__ __forceinline__ float warp_max(float v) {
#pragma unroll
    for (int o = 16; o; o >>= 1) v = fmaxf(v, __shfl_xor_sync(0xffffffffu, v, o));
    return v;
}
__device__ __forceinline__ unsigned fenc(float f) {
    unsigned u = __float_as_uint(f);
    return (u >> 31) ? ~u : (u | 0x80000000u);
}
__device__ __forceinline__ float fdec(unsigned u) {
    return __uint_as_float((u >> 31) ? (u & 0x7fffffffu) : ~u);
}
__device__ __forceinline__ float lrelu(float a) { return a > 0.f ? a : NEGS * a; }

__device__ __forceinline__ uint32_t smem_u32(const void* p) {
    return (uint32_t)__cvta_generic_to_shared(p);
}
__device__ __forceinline__ void ldsm_x4(uint32_t& r0, uint32_t& r1, uint32_t& r2, uint32_t& r3, uint32_t addr) {
    asm volatile("ldmatrix.sync.aligned.m8n8.x4.shared.b16 {%0,%1,%2,%3}, [%4];\n"
                 : "=r"(r0), "=r"(r1), "=r"(r2), "=r"(r3) : "r"(addr));
}
__device__ __forceinline__ void cp_async16(uint32_t dst, const void* src, bool pred) {
    int sz = pred ? 16 : 0;
    asm volatile("cp.async.cg.shared.global [%0], [%1], 16, %2;\n"
                 :: "r"(dst), "l"(src), "r"(sz));
}
__device__ __forceinline__ void cp_commit() {
    asm volatile("cp.async.commit_group;\n" ::: "memory");
}

// ---------------- CSR build ----------------
__global__ void deg_kernel(const int* __restrict__ ei) {
    int i = blockIdx.x * blockDim.x + threadIdx.x;
    if (i < NTOT) {
        int d = (i < NE) ? ei[NE + i] : (i - NE);
        atomicAdd(&g_deg[d], 1);
    }
}
__global__ void scan_kernel() {
    __shared__ int warpsum[32];
    __shared__ int carry;
    int tid = threadIdx.x, lane = tid & 31, w = tid >> 5;
    if (tid == 0) { carry = 0; g_offs[0] = 0; }
    __syncthreads();
    for (int base = 0; base < NN; base += 1024) {
        int i = base + tid;
        int v = (i < NN) ? g_deg[i] : 0;
        int x = v;
#pragma unroll
        for (int o = 1; o < 32; o <<= 1) {
            int t = __shfl_up_sync(0xffffffffu, x, o);
            if (lane >= o) x += t;
        }
        if (lane == 31) warpsum[w] = x;
        __syncthreads();
        if (w == 0) {
            int s = warpsum[lane];
#pragma unroll
            for (int o = 1; o < 32; o <<= 1) {
                int t = __shfl_up_sync(0xffffffffu, s, o);
                if (lane >= o) s += t;
            }
            warpsum[lane] = s;
        }
        __syncthreads();
        int incl = carry + (w ? warpsum[w - 1] : 0) + x;
        if (i < NN) {
            g_offs[i + 1] = incl;
            g_cursor[i] = incl - v;
        }
        __syncthreads();
        if (tid == 1023) carry = incl;
        __syncthreads();
    }
}
__global__ void scatter_kernel(const int* __restrict__ ei) {
    int i = blockIdx.x * blockDim.x + threadIdx.x;
    if (i < NTOT) {
        int s, d;
        if (i < NE) { s = ei[i]; d = ei[NE + i]; }
        else        { s = d = i - NE; }
        int p = atomicAdd(&g_cursor[d], 1);
        g_csr[p] = s;
    }
}

// ---------------- fp16 split conversions ----------------
// activations: fp32 [M][512] -> fp16 [M][1024] blocks [hi | lo]; also zeroes g_deg
__global__ void split_act_kernel(const float* __restrict__ in, __half* __restrict__ out, int M) {
    int idx = blockIdx.x * blockDim.x + threadIdx.x;
    if (idx < NN) g_deg[idx] = 0;
    int total = M * (INC / 4);
    if (idx >= total) return;
    int n = idx / (INC / 4);
    int c4 = (idx % (INC / 4)) * 4;
    float4 v = *(const float4*)(in + (size_t)n * INC + c4);
    float vv[4] = {v.x, v.y, v.z, v.w};
    unsigned short hs[4], ls[4];
#pragma unroll
    for (int i = 0; i < 4; i++) {
        __half h = __float2half(vv[i]);
        __half l = __float2half(vv[i] - __half2float(h));
        hs[i] = *(unsigned short*)&h;
        ls[i] = *(unsigned short*)&l;
    }
    __half* row = out + (size_t)n * KSPLIT;
    *(ushort4*)(row + c4)       = make_ushort4(hs[0], hs[1], hs[2], hs[3]);
    *(ushort4*)(row + INC + c4) = make_ushort4(ls[0], ls[1], ls[2], ls[3]);
}
// weights: fp32 [512][Nw] -> fp16 [Nw][1024] blocks [Wh | Wh] (transposed)
__global__ void split_w_kernel(const float* __restrict__ in, __half* __restrict__ out, int Nw) {
    int idx = blockIdx.x * blockDim.x + threadIdx.x;
    if (idx >= INC * Nw) return;
    int n = idx / INC, k = idx % INC;
    float v = in[(size_t)k * Nw + n];
    __half h = __float2half(v);
    __half* row = out + (size_t)n * KSPLIT;
    row[k] = h;
    row[INC + k] = h;
}

// ---------------- fp16 tensor-core GEMM (NT), cp.async 3-stage pipeline ----------------
// optional fused attention-logit epilogue (layer1): asrc/adst != nullptr
#define BM 128
#define BN 128
#define BK 32
#define APAD 40
#define NSTAGE 3
#define GEMM_SMEM (NSTAGE * (BM + BN) * APAD * 2)   // 61440 bytes

__global__ __launch_bounds__(256, 2) void mma_gemm_kernel(
    const __half* __restrict__ A, const __half* __restrict__ Bt,
    float* __restrict__ C, int M, int Nc, int K,
    const float* __restrict__ asrc, const float* __restrict__ adst,
    float* __restrict__ oas, float* __restrict__ oad)
{
    extern __shared__ __half sm[];
    const int STG = (BM + BN) * APAD;

    int tid = threadIdx.x;
    int warp = tid >> 5, lane = tid & 31;
    int wm = (warp & 3) * 32;
    int wn = (warp >> 2) * 64;
    int m0 = blockIdx.y * BM, n0 = blockIdx.x * BN;
    int g = lane >> 2, t4 = lane & 3;

    int a_row = (lane & 7) + ((lane >> 3) & 1) * 8;
    int a_half = (lane >> 4) * 8;
    int b_row = (lane & 7) + ((lane >> 4) << 3);
    int b_half = ((lane >> 3) & 1) * 8;

    int lr0 = tid >> 2;
    int lcq = (tid & 3) * 8;
    bool am0 = (m0 + lr0) < M;
    bool am1 = (m0 + lr0 + 64) < M;
    const __half* gA0 = A + (size_t)(m0 + lr0) * K + lcq;
    const __half* gA1 = A + (size_t)(m0 + lr0 + 64) * K + lcq;
    const __half* gB0 = Bt + (size_t)(n0 + lr0) * K + lcq;
    const __half* gB1 = Bt + (size_t)(n0 + lr0 + 64) * K + lcq;

    float acc[2][8][4];
#pragma unroll
    for (int mi = 0; mi < 2; mi++)
#pragma unroll
        for (int ni = 0; ni < 8; ni++)
#pragma unroll
            for (int j = 0; j < 4; j++) acc[mi][ni][j] = 0.f;

    int nk = K / BK;

#define ISSUE(KT) {                                                            \
        int _buf = (KT) % NSTAGE;                                              \
        int _k0 = (KT) * BK;                                                   \
        __half* sA = sm + _buf * STG;                                          \
        __half* sB = sA + BM * APAD;                                           \
        cp_async16(smem_u32(sA + lr0 * APAD + lcq),        gA0 + _k0, am0);    \
        cp_async16(smem_u32(sA + (lr0 + 64) * APAD + lcq), gA1 + _k0, am1);    \
        cp_async16(smem_u32(sB + lr0 * APAD + lcq),        gB0 + _k0, true);   \
        cp_async16(smem_u32(sB + (lr0 + 64) * APAD + lcq), gB1 + _k0, true);   \
        cp_commit();                                                           \
    }

    ISSUE(0);
    ISSUE(1);

    for (int kt = 0; kt < nk; kt++) {
        asm volatile("cp.async.wait_group 1;\n" ::: "memory");
        __syncthreads();
        if (kt + 2 < nk) { ISSUE(kt + 2); }
        else             { cp_commit(); }

        __half* sA = sm + (kt % NSTAGE) * STG;
        __half* sB = sA + BM * APAD;
#pragma unroll
        for (int kk = 0; kk < 2; kk++) {
            int kb = kk * 16;
            uint32_t af[2][4];
            uint32_t bfrag[8][2];
#pragma unroll
            for (int mi = 0; mi < 2; mi++) {
                uint32_t ad = smem_u32(sA + (wm + mi * 16 + a_row) * APAD + kb + a_half);
                ldsm_x4(af[mi][0], af[mi][1], af[mi][2], af[mi][3], ad);
            }
#pragma unroll
            for (int p = 0; p < 4; p++) {
                uint32_t bd = smem_u32(sB + (wn + p * 16 + b_row) * APAD + kb + b_half);
                ldsm_x4(bfrag[2 * p][0], bfrag[2 * p][1], bfrag[2 * p + 1][0], bfrag[2 * p + 1][1], bd);
            }
#pragma unroll
            for (int mi = 0; mi < 2; mi++)
#pragma unroll
                for (int ni = 0; ni < 8; ni++) {
                    asm volatile(
                        "mma.sync.aligned.m16n8k16.row.col.f32.f16.f16.f32 "
                        "{%0,%1,%2,%3}, {%4,%5,%6,%7}, {%8,%9}, {%0,%1,%2,%3};\n"
                        : "+f"(acc[mi][ni][0]), "+f"(acc[mi][ni][1]),
                          "+f"(acc[mi][ni][2]), "+f"(acc[mi][ni][3])
                        : "r"(af[mi][0]), "r"(af[mi][1]), "r"(af[mi][2]), "r"(af[mi][3]),
                          "r"(bfrag[ni][0]), "r"(bfrag[ni][1]));
                }
        }
    }
#undef ISSUE

    // store C tile
#pragma unroll
    for (int mi = 0; mi < 2; mi++) {
        int r = m0 + wm + mi * 16;
#pragma unroll
        for (int ni = 0; ni < 8; ni++) {
            int c = n0 + wn + ni * 8 + 2 * t4;
            if (r + g < M) {
                float2 v0 = make_float2(acc[mi][ni][0], acc[mi][ni][1]);
                *(float2*)(C + (size_t)(r + g) * Nc + c) = v0;
            }
            if (r + g + 8 < M) {
                float2 v1 = make_float2(acc[mi][ni][2], acc[mi][ni][3]);
                *(float2*)(C + (size_t)(r + g + 8) * Nc + c) = v1;
            }
        }
    }

    // fused attention logits (layer1): this warp's 64 cols = one full head
    if (asrc) {
        int head = (n0 + wn) >> 6;   // 64-channel heads
#pragma unroll
        for (int mi = 0; mi < 2; mi++) {
            float s0 = 0.f, s1 = 0.f, d0 = 0.f, d1 = 0.f;
#pragma unroll
            for (int ni = 0; ni < 8; ni++) {
#pragma unroll
                for (int j = 0; j < 2; j++) {
                    int c = n0 + wn + ni * 8 + 2 * t4 + j;
                    float a_s = asrc[c], a_d = adst[c];
                    s0 += acc[mi][ni][j] * a_s;
                    d0 += acc[mi][ni][j] * a_d;
                    s1 += acc[mi][ni][j + 2] * a_s;
                    d1 += acc[mi][ni][j + 2] * a_d;
                }
            }
            // reduce over the 4 t4-lanes (consecutive lanes)
#pragma unroll
            for (int o = 1; o < 4; o <<= 1) {
                s0 += __shfl_xor_sync(0xffffffffu, s0, o);
                s1 += __shfl_xor_sync(0xffffffffu, s1, o);
                d0 += __shfl_xor_sync(0xffffffffu, d0, o);
                d1 += __shfl_xor_sync(0xffffffffu, d1, o);
            }
            if (t4 == 0) {
                int r0 = m0 + wm + mi * 16 + g;
                int r1 = r0 + 8;
                if (r0 < M) { oas[r0 * 8 + head] = s0; oad[r0 * 8 + head] = d0; }
                if (r1 < M) { oas[r1 * 8 + head] = s1; oad[r1 * 8 + head] = d1; }
            }
        }
    }
}

// ---------------- layer2 attention logits ----------------
__global__ void alpha2_kernel(const float* __restrict__ asrc, const float* __restrict__ adst) {
    int gw = (blockIdx.x * blockDim.x + threadIdx.x) >> 5;
    int lane = threadIdx.x & 31;
    if (gw >= NN) return;
    const float* hr = g_h2 + (size_t)gw * OUTC;
    float vs = 0.f, vd = 0.f;
#pragma unroll
    for (int c = 0; c < OUTC; c += 32) {
        float hv = hr[c + lane];
        vs += hv * asrc[c + lane];
        vd += hv * adst[c + lane];
    }
    vs = warp_sum(vs);
    vd = warp_sum(vd);
    if (lane == 0) { g_as2[gw] = vs; g_ad2[gw] = vd; }
}

// ---------------- layer1 aggregation: softmax + gather + bias + elu + fp16 split ----------------
__global__ void agg1_kernel(const float* __restrict__ bias) {
    int n = blockIdx.x;
    int tid = threadIdx.x;
    int beg = g_offs[n], end = g_offs[n + 1];
    int deg = end - beg;

    __shared__ float s_ad[8];
    __shared__ float s_max[8];
    __shared__ float s_inv[8];
    __shared__ int   s_src[CAP1];
    __shared__ float s_alpha[CAP1][9];
    __shared__ unsigned s_maxi[8];
    __shared__ float s_sum8[8];

    if (tid < 8) {
        s_ad[tid] = g_ad1[n * 8 + tid];
        s_maxi[tid] = 0x007FFFFFu;
        s_sum8[tid] = 0.f;
    }
    __syncthreads();

    int c = 2 * tid;
    int hch = c >> 6;
    float accx = 0.f, accy = 0.f;

    if (deg <= CAP1) {
        for (int base = 0; base < deg; base += 32) {
            int el = base + (tid >> 3), hh = tid & 7;
            if (el < deg) {
                int s = g_csr[beg + el];
                if (hh == 0) s_src[el] = s;
                s_alpha[el][hh] = lrelu(g_as1[s * 8 + hh] + s_ad[hh]);
            }
        }
        __syncthreads();
        {
            int h = tid >> 5, l = tid & 31;
            float m = -INFINITY;
            for (int e = l; e < deg; e += 32) m = fmaxf(m, s_alpha[e][h]);
            m = warp_max(m);
            float ssum = 0.f;
            for (int e = l; e < deg; e += 32) ssum += __expf(s_alpha[e][h] - m);
            ssum = warp_sum(ssum);
            if (l == 0) { s_max[h] = m; s_inv[h] = 1.f / (ssum + 1e-16f); }
        }
        __syncthreads();
        for (int base = 0; base < deg; base += 32) {
            int el = base + (tid >> 3), hh = tid & 7;
            if (el < deg) s_alpha[el][hh] = __expf(s_alpha[el][hh] - s_max[hh]) * s_inv[hh];
        }
        __syncthreads();
        int e = 0;
        for (; e + 4 <= deg; e += 4) {
            float2 v0 = *(const float2*)(g_h1 + (size_t)s_src[e + 0] * HID1 + c);
            float2 v1 = *(const float2*)(g_h1 + (size_t)s_src[e + 1] * HID1 + c);
            float2 v2 = *(const float2*)(g_h1 + (size_t)s_src[e + 2] * HID1 + c);
            float2 v3 = *(const float2*)(g_h1 + (size_t)s_src[e + 3] * HID1 + c);
            float k0 = s_alpha[e + 0][hch], k1 = s_alpha[e + 1][hch];
            float k2 = s_alpha[e + 2][hch], k3 = s_alpha[e + 3][hch];
            accx += v0.x * k0 + v1.x * k1 + v2.x * k2 + v3.x * k3;
            accy += v0.y * k0 + v1.y * k1 + v2.y * k2 + v3.y * k3;
        }
        for (; e < deg; e++) {
            float2 v = *(const float2*)(g_h1 + (size_t)s_src[e] * HID1 + c);
            float kc = s_alpha[e][hch];
            accx += v.x * kc;
            accy += v.y * kc;
        }
    } else {
        const float4* as4 = (const float4*)g_as1;
        float lmax[8];
#pragma unroll
        for (int h = 0; h < 8; h++) lmax[h] = -INFINITY;
        for (int e = beg + tid; e < end; e += 256) {
            int s = g_csr[e];
            float4 lo = as4[s * 2], hi = as4[s * 2 + 1];
            float av[8] = {lo.x, lo.y, lo.z, lo.w, hi.x, hi.y, hi.z, hi.w};
#pragma unroll
            for (int h = 0; h < 8; h++) lmax[h] = fmaxf(lmax[h], lrelu(av[h] + s_ad[h]));
        }
#pragma unroll
        for (int h = 0; h < 8; h++) atomicMax(&s_maxi[h], fenc(lmax[h]));
        __syncthreads();
        if (tid < 8) s_max[tid] = fdec(s_maxi[tid]);
        __syncthreads();
        float lsum[8];
#pragma unroll
        for (int h = 0; h < 8; h++) lsum[h] = 0.f;
        for (int e = beg + tid; e < end; e += 256) {
            int s = g_csr[e];
            float4 lo = as4[s * 2], hi = as4[s * 2 + 1];
            float av[8] = {lo.x, lo.y, lo.z, lo.w, hi.x, hi.y, hi.z, hi.w};
#pragma unroll
            for (int h = 0; h < 8; h++) lsum[h] += __expf(lrelu(av[h] + s_ad[h]) - s_max[h]);
        }
#pragma unroll
        for (int h = 0; h < 8; h++) atomicAdd(&s_sum8[h], lsum[h]);
        __syncthreads();
        if (tid < 8) s_inv[tid] = 1.f / (s_sum8[tid] + 1e-16f);
        __syncthreads();
        for (int cb = beg; cb < end; cb += 32) {
            int cn = end - cb; if (cn > 32) cn = 32;
            int el = tid >> 3, hh = tid & 7;
            if (el < cn) {
                int s = g_csr[cb + el];
                float a = lrelu(g_as1[s * 8 + hh] + s_ad[hh]);
                s_alpha[el][hh] = __expf(a - s_max[hh]) * s_inv[hh];
                if (hh == 0) s_src[el] = s;
            }
            __syncthreads();
            for (int e = 0; e < cn; e++) {
                float2 v = *(const float2*)(g_h1 + (size_t)s_src[e] * HID1 + c);
                float kc = s_alpha[e][hch];
                accx += v.x * kc;
                accy += v.y * kc;
            }
            __syncthreads();
        }
    }

    float2 bv = *(const float2*)(bias + c);
    float ox = accx + bv.x, oy = accy + bv.y;
    ox = ox > 0.f ? ox : expm1f(ox);
    oy = oy > 0.f ? oy : expm1f(oy);
    __half hx = __float2half(ox), hy = __float2half(oy);
    __half lx = __float2half(ox - __half2float(hx));
    __half ly = __float2half(oy - __half2float(hy));
    __half* row = g_o1s + (size_t)n * KSPLIT;
    ushort2 hv = make_ushort2(*(unsigned short*)&hx, *(unsigned short*)&hy);
    ushort2 lv = make_ushort2(*(unsigned short*)&lx, *(unsigned short*)&ly);
    *(ushort2*)(row + c)       = hv;
    *(ushort2*)(row + INC + c) = lv;
}

// ---------------- layer2 aggregation + bias + log-softmax ----------------
__global__ void agg2_kernel(const float* __restrict__ bias, float* __restrict__ out) {
    int n = blockIdx.x;
    int tid = threadIdx.x;
    int beg = g_offs[n], end = g_offs[n + 1];
    int deg = end - beg;

    __shared__ float s_ad;
    __shared__ float s_max;
    __shared__ float s_inv;
    __shared__ unsigned s_maxi;
    __shared__ float s_sum1;
    __shared__ int   s_src[CAP2];
    __shared__ float s_alpha[CAP2];
    __shared__ float shm[8];
    __shared__ float shs[8];

    if (tid == 0) {
        s_ad = g_ad2[n];
        s_maxi = 0x007FFFFFu;
        s_sum1 = 0.f;
    }
    __syncthreads();

    float acc = 0.f;

    if (deg <= CAP2) {
        if (tid < deg) {
            int s = g_csr[beg + tid];
            s_src[tid] = s;
            s_alpha[tid] = lrelu(g_as2[s] + s_ad);
        }
        __syncthreads();
        if (tid < 32) {
            float m = -INFINITY;
            for (int e = tid; e < deg; e += 32) m = fmaxf(m, s_alpha[e]);
            m = warp_max(m);
            float ssum = 0.f;
            for (int e = tid; e < deg; e += 32) ssum += __expf(s_alpha[e] - m);
            ssum = warp_sum(ssum);
            if (tid == 0) { s_max = m; s_inv = 1.f / (ssum + 1e-16f); }
        }
        __syncthreads();
        if (tid < deg) s_alpha[tid] = __expf(s_alpha[tid] - s_max) * s_inv;
        __syncthreads();
        int e = 0;
        for (; e + 4 <= deg; e += 4) {
            float v0 = g_h2[(size_t)s_src[e + 0] * OUTC + tid];
            float v1 = g_h2[(size_t)s_src[e + 1] * OUTC + tid];
            float v2 = g_h2[(size_t)s_src[e + 2] * OUTC + tid];
            float v3 = g_h2[(size_t)s_src[e + 3] * OUTC + tid];
            acc += v0 * s_alpha[e + 0] + v1 * s_alpha[e + 1] + v2 * s_alpha[e + 2] + v3 * s_alpha[e + 3];
        }
        for (; e < deg; e++) acc += g_h2[(size_t)s_src[e] * OUTC + tid] * s_alpha[e];
    } else {
        float lmax = -INFINITY;
        for (int e = beg + tid; e < end; e += 256) {
            float a = lrelu(g_as2[g_csr[e]] + s_ad);
            lmax = fmaxf(lmax, a);
        }
        atomicMax(&s_maxi, fenc(lmax));
        __syncthreads();
        if (tid == 0) s_max = fdec(s_maxi);
        __syncthreads();
        float lsum = 0.f;
        for (int e = beg + tid; e < end; e += 256) {
            float a = lrelu(g_as2[g_csr[e]] + s_ad);
            lsum += __expf(a - s_max);
        }
        atomicAdd(&s_sum1, lsum);
        __syncthreads();
        if (tid == 0) s_inv = 1.f / (s_sum1 + 1e-16f);
        __syncthreads();
        for (int cb = beg; cb < end; cb += CAP2) {
            int cn = end - cb; if (cn > CAP2) cn = CAP2;
            if (tid < cn) {
                int s = g_csr[cb + tid];
                float a = lrelu(g_as2[s] + s_ad);
                s_alpha[tid] = __expf(a - s_max) * s_inv;
                s_src[tid] = s;
            }
            __syncthreads();
            for (int e = 0; e < cn; e++) acc += g_h2[(size_t)s_src[e] * OUTC + tid] * s_alpha[e];
            __syncthreads();
        }
    }

    float v = acc + bias[tid];
    float wm = warp_max(v);
    if ((tid & 31) == 0) shm[tid >> 5] = wm;
    __syncthreads();
    float m = shm[0];
#pragma unroll
    for (int i = 1; i < 8; i++) m = fmaxf(m, shm[i]);
    float ex = __expf(v - m);
    float ws = warp_sum(ex);
    if ((tid & 31) == 0) shs[tid >> 5] = ws;
    __syncthreads();
    float s = 0.f;
#pragma unroll
    for (int i = 0; i < 8; i++) s += shs[i];
    out[(size_t)n * OUTC + tid] = v - m - __logf(s);
}

// ---------------- launch ----------------
extern "C" void kernel_launch(void* const* d_in, const int* in_sizes, int n_in,
                              void* d_out, int out_size) {
    const float* x    = (const float*)d_in[0];
    const int*   ei   = (const int*)d_in[1];
    const float* W1   = (const float*)d_in[2];
    const float* as1  = (const float*)d_in[3];
    const float* ad1  = (const float*)d_in[4];
    const float* b1   = (const float*)d_in[5];
    const float* W2   = (const float*)d_in[6];
    const float* as2  = (const float*)d_in[7];
    const float* ad2  = (const float*)d_in[8];
    const float* b2   = (const float*)d_in[9];
    float* out = (float*)d_out;

    float *p_h1, *p_h2, *p_as1, *p_ad1;
    __half *p_xs, *p_o1s, *p_w1t, *p_w2t;
    cudaGetSymbolAddress((void**)&p_h1, g_h1);
    cudaGetSymbolAddress((void**)&p_h2, g_h2);
    cudaGetSymbolAddress((void**)&p_as1, g_as1);
    cudaGetSymbolAddress((void**)&p_ad1, g_ad1);
    cudaGetSymbolAddress((void**)&p_xs, g_xs);
    cudaGetSymbolAddress((void**)&p_o1s, g_o1s);
    cudaGetSymbolAddress((void**)&p_w1t, g_w1t);
    cudaGetSymbolAddress((void**)&p_w2t, g_w2t);

    cudaFuncSetAttribute(mma_gemm_kernel,
                         cudaFuncAttributeMaxDynamicSharedMemorySize, GEMM_SMEM);

    // (1-3) splits (+ g_deg zeroing piggybacked); launch #4 = layer1 GEMM (profiled)
    split_act_kernel<<<(NN * (INC / 4) + 255) / 256, 256>>>(x, p_xs, NN);
    split_w_kernel<<<(INC * HID1 + 255) / 256, 256>>>(W1, p_w1t, HID1);
    split_w_kernel<<<(INC * OUTC + 255) / 256, 256>>>(W2, p_w2t, OUTC);

    // (4) layer1 GEMM with fused attention-logit epilogue
    mma_gemm_kernel<<<dim3(HID1 / BN, (NN + BM - 1) / BM), 256, GEMM_SMEM>>>(
        p_xs, p_w1t, p_h1, NN, HID1, KSPLIT, as1, ad1, p_as1, p_ad1);

    // (5-7) CSR build
    deg_kernel<<<(NTOT + 255) / 256, 256>>>(ei);
    scan_kernel<<<1, 1024>>>();
    scatter_kernel<<<(NTOT + 255) / 256, 256>>>(ei);

    // (8) layer1 aggregation (writes fp16 split directly)
    agg1_kernel<<<NN, 256>>>(b1);

    // (9-11) layer2
    mma_gemm_kernel<<<dim3(OUTC / BN, (NN + BM - 1) / BM), 256, GEMM_SMEM>>>(
        p_o1s, p_w2t, p_h2, NN, OUTC, KSPLIT, nullptr, nullptr, nullptr, nullptr);
    alpha2_kernel<<<(NN + 7) / 8, 256>>>(as2, ad2);
    agg2_kernel<<<NN, 256>>>(b2, out);
}

// round 7
// speedup vs baseline: 3.8844x; 1.2147x over previous
#include <cuda_runtime.h>
#include <cuda_fp16.h>
#include <math.h>
#include <stdint.h>

#define NN     20000
#define INC    512
#define HID1   512      // H1*HID = 8*64
#define OUTC   256
#define NE     320000
#define NTOT   (NE + NN)   // edges + self loops = 340000
#define NEGS   0.2f
#define KDIM   512
#define CAP1   96
#define CAP2   128

// ---------------- scratch ----------------
__device__ float g_h1[(size_t)NN * HID1];
__device__ float g_h2[(size_t)NN * OUTC];
__device__ __half g_xs[(size_t)NN * KDIM];
__device__ __half g_o1s[(size_t)NN * KDIM];
__device__ __half g_w1t[(size_t)HID1 * KDIM];
__device__ __half g_w2t[(size_t)OUTC * KDIM];
__device__ float g_as1[NN * 8];
__device__ float g_ad1[NN * 8];
__device__ float g_as2[NN];
__device__ float g_ad2[NN];
__device__ int   g_deg[NN];
__device__ int   g_offs[NN + 1];
__device__ int   g_cursor[NN];
__device__ int   g_csr[NTOT];

// ---------------- helpers ----------------
__device__ __forceinline__ float warp_sum(float v) {
#pragma unroll
    for (int o = 16; o; o >>= 1) v += __shfl_xor_sync(0xffffffffu, v, o);
    return v;
}
__device__ __forceinline__ float warp_max(float v) {
#pragma unroll
    for (int o = 16; o; o >>= 1) v = fmaxf(v, __shfl_xor_sync(0xffffffffu, v, o));
    return v;
}
__device__ __forceinline__ unsigned fenc(float f) {
    unsigned u = __float_as_uint(f);
    return (u >> 31) ? ~u : (u | 0x80000000u);
}
__device__ __forceinline__ float fdec(unsigned u) {
    return __uint_as_float((u >> 31) ? (u & 0x7fffffffu) : ~u);
}
__device__ __forceinline__ float lrelu(float a) { return a > 0.f ? a : NEGS * a; }

__device__ __forceinline__ uint32_t smem_u32(const void* p) {
    return (uint32_t)__cvta_generic_to_shared(p);
}
__device__ __forceinline__ void ldsm_x4(uint32_t& r0, uint32_t& r1, uint32_t& r2, uint32_t& r3, uint32_t addr) {
    asm volatile("ldmatrix.sync.aligned.m8n8.x4.shared.b16 {%0,%1,%2,%3}, [%4];\n"
                 : "=r"(r0), "=r"(r1), "=r"(r2), "=r"(r3) : "r"(addr));
}
__device__ __forceinline__ void cp_async16(uint32_t dst, const void* src, bool pred) {
    int sz = pred ? 16 : 0;
    asm volatile("cp.async.cg.shared.global [%0], [%1], 16, %2;\n"
                 :: "r"(dst), "l"(src), "r"(sz));
}
__device__ __forceinline__ void cp_commit() {
    asm volatile("cp.async.commit_group;\n" ::: "memory");
}

// ---------------- CSR build ----------------
// also zeroes the alpha2 accumulators for the fused GEMM2 epilogue
__global__ void deg_kernel(const int* __restrict__ ei) {
    int i = blockIdx.x * blockDim.x + threadIdx.x;
    if (i < NN) { g_as2[i] = 0.f; g_ad2[i] = 0.f; }
    if (i < NTOT) {
        int d = (i < NE) ? ei[NE + i] : (i - NE);
        atomicAdd(&g_deg[d], 1);
    }
}
__global__ void scan_kernel() {
    __shared__ int warpsum[32];
    __shared__ int carry;
    int tid = threadIdx.x, lane = tid & 31, w = tid >> 5;
    if (tid == 0) { carry = 0; g_offs[0] = 0; }
    __syncthreads();
    for (int base = 0; base < NN; base += 1024) {
        int i = base + tid;
        int v = (i < NN) ? g_deg[i] : 0;
        int x = v;
#pragma unroll
        for (int o = 1; o < 32; o <<= 1) {
            int t = __shfl_up_sync(0xffffffffu, x, o);
            if (lane >= o) x += t;
        }
        if (lane == 31) warpsum[w] = x;
        __syncthreads();
        if (w == 0) {
            int s = warpsum[lane];
#pragma unroll
            for (int o = 1; o < 32; o <<= 1) {
                int t = __shfl_up_sync(0xffffffffu, s, o);
                if (lane >= o) s += t;
            }
            warpsum[lane] = s;
        }
        __syncthreads();
        int incl = carry + (w ? warpsum[w - 1] : 0) + x;
        if (i < NN) {
            g_offs[i + 1] = incl;
            g_cursor[i] = incl - v;
        }
        __syncthreads();
        if (tid == 1023) carry = incl;
        __syncthreads();
    }
}
__global__ void scatter_kernel(const int* __restrict__ ei) {
    int i = blockIdx.x * blockDim.x + threadIdx.x;
    if (i < NTOT) {
        int s, d;
        if (i < NE) { s = ei[i]; d = ei[NE + i]; }
        else        { s = d = i - NE; }
        int p = atomicAdd(&g_cursor[d], 1);
        g_csr[p] = s;
    }
}

// ---------------- fp16 conversions ----------------
// activations: fp32 [M][512] -> fp16 [M][512]; also zeroes g_deg
__global__ void conv_act_kernel(const float* __restrict__ in, __half* __restrict__ out, int M) {
    int idx = blockIdx.x * blockDim.x + threadIdx.x;
    if (idx < NN) g_deg[idx] = 0;
    int total = M * (KDIM / 4);
    if (idx >= total) return;
    int c4 = idx * 4;
    float4 v = *(const float4*)(in + c4);
    __half h0 = __float2half(v.x), h1 = __float2half(v.y);
    __half h2 = __float2half(v.z), h3 = __float2half(v.w);
    *(ushort4*)(out + c4) = make_ushort4(
        *(unsigned short*)&h0, *(unsigned short*)&h1,
        *(unsigned short*)&h2, *(unsigned short*)&h3);
}
// weights: fp32 [512][Nw] -> fp16 [Nw][512] (transposed)
__global__ void conv_w_kernel(const float* __restrict__ in, __half* __restrict__ out, int Nw) {
    int idx = blockIdx.x * blockDim.x + threadIdx.x;
    if (idx >= KDIM * Nw) return;
    int n = idx / KDIM, k = idx % KDIM;
    out[(size_t)n * KDIM + k] = __float2half(in[(size_t)k * Nw + n]);
}

// ---------------- fp16 tensor-core GEMM (NT), cp.async 3-stage ----------------
// fused attention-logit epilogue:
//  heads==8 (layer1): warp tile = one head, direct write to oas/oad [M][8]
//  heads==1 (layer2): 128-ch partial per CTA, atomicAdd into oas/oad [M]
#define BM 128
#define BN 128
#define BK 32
#define APAD 40
#define NSTAGE 3
#define GEMM_SMEM (NSTAGE * (BM + BN) * APAD * 2)   // 61440 bytes

__global__ __launch_bounds__(256, 2) void mma_gemm_kernel(
    const __half* __restrict__ A, const __half* __restrict__ Bt,
    float* __restrict__ C, int M, int Nc, int K,
    const float* __restrict__ asrc, const float* __restrict__ adst,
    float* __restrict__ oas, float* __restrict__ oad, int heads)
{
    extern __shared__ __half sm[];
    const int STG = (BM + BN) * APAD;

    int tid = threadIdx.x;
    int warp = tid >> 5, lane = tid & 31;
    int wm = (warp & 3) * 32;
    int wn = (warp >> 2) * 64;
    int m0 = blockIdx.y * BM, n0 = blockIdx.x * BN;
    int g = lane >> 2, t4 = lane & 3;

    int a_row = (lane & 7) + ((lane >> 3) & 1) * 8;
    int a_half = (lane >> 4) * 8;
    int b_row = (lane & 7) + ((lane >> 4) << 3);
    int b_half = ((lane >> 3) & 1) * 8;

    int lr0 = tid >> 2;
    int lcq = (tid & 3) * 8;
    bool am0 = (m0 + lr0) < M;
    bool am1 = (m0 + lr0 + 64) < M;
    const __half* gA0 = A + (size_t)(m0 + lr0) * K + lcq;
    const __half* gA1 = A + (size_t)(m0 + lr0 + 64) * K + lcq;
    const __half* gB0 = Bt + (size_t)(n0 + lr0) * K + lcq;
    const __half* gB1 = Bt + (size_t)(n0 + lr0 + 64) * K + lcq;

    float acc[2][8][4];
#pragma unroll
    for (int mi = 0; mi < 2; mi++)
#pragma unroll
        for (int ni = 0; ni < 8; ni++)
#pragma unroll
            for (int j = 0; j < 4; j++) acc[mi][ni][j] = 0.f;

    int nk = K / BK;

#define ISSUE(KT) {                                                            \
        int _buf = (KT) % NSTAGE;                                              \
        int _k0 = (KT) * BK;                                                   \
        __half* sA = sm + _buf * STG;                                          \
        __half* sB = sA + BM * APAD;                                           \
        cp_async16(smem_u32(sA + lr0 * APAD + lcq),        gA0 + _k0, am0);    \
        cp_async16(smem_u32(sA + (lr0 + 64) * APAD + lcq), gA1 + _k0, am1);    \
        cp_async16(smem_u32(sB + lr0 * APAD + lcq),        gB0 + _k0, true);   \
        cp_async16(smem_u32(sB + (lr0 + 64) * APAD + lcq), gB1 + _k0, true);   \
        cp_commit();                                                           \
    }

    ISSUE(0);
    ISSUE(1);

    for (int kt = 0; kt < nk; kt++) {
        asm volatile("cp.async.wait_group 1;\n" ::: "memory");
        __syncthreads();
        if (kt + 2 < nk) { ISSUE(kt + 2); }
        else             { cp_commit(); }

        __half* sA = sm + (kt % NSTAGE) * STG;
        __half* sB = sA + BM * APAD;
#pragma unroll
        for (int kk = 0; kk < 2; kk++) {
            int kb = kk * 16;
            uint32_t af[2][4];
            uint32_t bfrag[8][2];
#pragma unroll
            for (int mi = 0; mi < 2; mi++) {
                uint32_t ad = smem_u32(sA + (wm + mi * 16 + a_row) * APAD + kb + a_half);
                ldsm_x4(af[mi][0], af[mi][1], af[mi][2], af[mi][3], ad);
            }
#pragma unroll
            for (int p = 0; p < 4; p++) {
                uint32_t bd = smem_u32(sB + (wn + p * 16 + b_row) * APAD + kb + b_half);
                ldsm_x4(bfrag[2 * p][0], bfrag[2 * p][1], bfrag[2 * p + 1][0], bfrag[2 * p + 1][1], bd);
            }
#pragma unroll
            for (int mi = 0; mi < 2; mi++)
#pragma unroll
                for (int ni = 0; ni < 8; ni++) {
                    asm volatile(
                        "mma.sync.aligned.m16n8k16.row.col.f32.f16.f16.f32 "
                        "{%0,%1,%2,%3}, {%4,%5,%6,%7}, {%8,%9}, {%0,%1,%2,%3};\n"
                        : "+f"(acc[mi][ni][0]), "+f"(acc[mi][ni][1]),
                          "+f"(acc[mi][ni][2]), "+f"(acc[mi][ni][3])
                        : "r"(af[mi][0]), "r"(af[mi][1]), "r"(af[mi][2]), "r"(af[mi][3]),
                          "r"(bfrag[ni][0]), "r"(bfrag[ni][1]));
                }
        }
    }
#undef ISSUE

    // store C tile
#pragma unroll
    for (int mi = 0; mi < 2; mi++) {
        int r = m0 + wm + mi * 16;
#pragma unroll
        for (int ni = 0; ni < 8; ni++) {
            int c = n0 + wn + ni * 8 + 2 * t4;
            if (r + g < M) {
                float2 v0 = make_float2(acc[mi][ni][0], acc[mi][ni][1]);
                *(float2*)(C + (size_t)(r + g) * Nc + c) = v0;
            }
            if (r + g + 8 < M) {
                float2 v1 = make_float2(acc[mi][ni][2], acc[mi][ni][3]);
                *(float2*)(C + (size_t)(r + g + 8) * Nc + c) = v1;
            }
        }
    }

    // fused attention logits
    if (asrc) {
#pragma unroll
        for (int mi = 0; mi < 2; mi++) {
            float s0 = 0.f, s1 = 0.f, d0 = 0.f, d1 = 0.f;
#pragma unroll
            for (int ni = 0; ni < 8; ni++) {
#pragma unroll
                for (int j = 0; j < 2; j++) {
                    int c = n0 + wn + ni * 8 + 2 * t4 + j;
                    float a_s = asrc[c], a_d = adst[c];
                    s0 += acc[mi][ni][j] * a_s;
                    d0 += acc[mi][ni][j] * a_d;
                    s1 += acc[mi][ni][j + 2] * a_s;
                    d1 += acc[mi][ni][j + 2] * a_d;
                }
            }
#pragma unroll
            for (int o = 1; o < 4; o <<= 1) {
                s0 += __shfl_xor_sync(0xffffffffu, s0, o);
                s1 += __shfl_xor_sync(0xffffffffu, s1, o);
                d0 += __shfl_xor_sync(0xffffffffu, d0, o);
                d1 += __shfl_xor_sync(0xffffffffu, d1, o);
            }
            if (t4 == 0) {
                int r0 = m0 + wm + mi * 16 + g;
                int r1 = r0 + 8;
                if (heads == 8) {
                    int head = (n0 + wn) >> 6;
                    if (r0 < M) { oas[r0 * 8 + head] = s0; oad[r0 * 8 + head] = d0; }
                    if (r1 < M) { oas[r1 * 8 + head] = s1; oad[r1 * 8 + head] = d1; }
                } else {
                    // single head spanning column-CTAs: 2 deterministic contributions
                    // per row per array (warp pairs within a CTA handled below)
                    if (r0 < M) { atomicAdd(&oas[r0], s0); atomicAdd(&oad[r0], d0); }
                    if (r1 < M) { atomicAdd(&oas[r1], s1); atomicAdd(&oad[r1], d1); }
                }
            }
        }
    }
}

// ---------------- layer1 aggregation: softmax + gather + bias + elu + fp16 ----------------
__global__ void agg1_kernel(const float* __restrict__ bias) {
    int n = blockIdx.x;
    int tid = threadIdx.x;
    int beg = g_offs[n], end = g_offs[n + 1];
    int deg = end - beg;

    __shared__ float s_ad[8];
    __shared__ float s_max[8];
    __shared__ float s_inv[8];
    __shared__ int   s_src[CAP1];
    __shared__ float s_alpha[CAP1][9];
    __shared__ unsigned s_maxi[8];
    __shared__ float s_sum8[8];

    if (tid < 8) {
        s_ad[tid] = g_ad1[n * 8 + tid];
        s_maxi[tid] = 0x007FFFFFu;
        s_sum8[tid] = 0.f;
    }
    __syncthreads();

    int c = 2 * tid;
    int hch = c >> 6;
    float accx = 0.f, accy = 0.f;

    if (deg <= CAP1) {
        for (int base = 0; base < deg; base += 32) {
            int el = base + (tid >> 3), hh = tid & 7;
            if (el < deg) {
                int s = g_csr[beg + el];
                if (hh == 0) s_src[el] = s;
                s_alpha[el][hh] = lrelu(g_as1[s * 8 + hh] + s_ad[hh]);
            }
        }
        __syncthreads();
        {
            int h = tid >> 5, l = tid & 31;
            float m = -INFINITY;
            for (int e = l; e < deg; e += 32) m = fmaxf(m, s_alpha[e][h]);
            m = warp_max(m);
            float ssum = 0.f;
            for (int e = l; e < deg; e += 32) ssum += __expf(s_alpha[e][h] - m);
            ssum = warp_sum(ssum);
            if (l == 0) { s_max[h] = m; s_inv[h] = 1.f / (ssum + 1e-16f); }
        }
        __syncthreads();
        for (int base = 0; base < deg; base += 32) {
            int el = base + (tid >> 3), hh = tid & 7;
            if (el < deg) s_alpha[el][hh] = __expf(s_alpha[el][hh] - s_max[hh]) * s_inv[hh];
        }
        __syncthreads();
        int e = 0;
        for (; e + 4 <= deg; e += 4) {
            float2 v0 = *(const float2*)(g_h1 + (size_t)s_src[e + 0] * HID1 + c);
            float2 v1 = *(const float2*)(g_h1 + (size_t)s_src[e + 1] * HID1 + c);
            float2 v2 = *(const float2*)(g_h1 + (size_t)s_src[e + 2] * HID1 + c);
            float2 v3 = *(const float2*)(g_h1 + (size_t)s_src[e + 3] * HID1 + c);
            float k0 = s_alpha[e + 0][hch], k1 = s_alpha[e + 1][hch];
            float k2 = s_alpha[e + 2][hch], k3 = s_alpha[e + 3][hch];
            accx += v0.x * k0 + v1.x * k1 + v2.x * k2 + v3.x * k3;
            accy += v0.y * k0 + v1.y * k1 + v2.y * k2 + v3.y * k3;
        }
        for (; e < deg; e++) {
            float2 v = *(const float2*)(g_h1 + (size_t)s_src[e] * HID1 + c);
            float kc = s_alpha[e][hch];
            accx += v.x * kc;
            accy += v.y * kc;
        }
    } else {
        const float4* as4 = (const float4*)g_as1;
        float lmax[8];
#pragma unroll
        for (int h = 0; h < 8; h++) lmax[h] = -INFINITY;
        for (int e = beg + tid; e < end; e += 256) {
            int s = g_csr[e];
            float4 lo = as4[s * 2], hi = as4[s * 2 + 1];
            float av[8] = {lo.x, lo.y, lo.z, lo.w, hi.x, hi.y, hi.z, hi.w};
#pragma unroll
            for (int h = 0; h < 8; h++) lmax[h] = fmaxf(lmax[h], lrelu(av[h] + s_ad[h]));
        }
#pragma unroll
        for (int h = 0; h < 8; h++) atomicMax(&s_maxi[h], fenc(lmax[h]));
        __syncthreads();
        if (tid < 8) s_max[tid] = fdec(s_maxi[tid]);
        __syncthreads();
        float lsum[8];
#pragma unroll
        for (int h = 0; h < 8; h++) lsum[h] = 0.f;
        for (int e = beg + tid; e < end; e += 256) {
            int s = g_csr[e];
            float4 lo = as4[s * 2], hi = as4[s * 2 + 1];
            float av[8] = {lo.x, lo.y, lo.z, lo.w, hi.x, hi.y, hi.z, hi.w};
#pragma unroll
            for (int h = 0; h < 8; h++) lsum[h] += __expf(lrelu(av[h] + s_ad[h]) - s_max[h]);
        }
#pragma unroll
        for (int h = 0; h < 8; h++) atomicAdd(&s_sum8[h], lsum[h]);
        __syncthreads();
        if (tid < 8) s_inv[tid] = 1.f / (s_sum8[tid] + 1e-16f);
        __syncthreads();
        for (int cb = beg; cb < end; cb += 32) {
            int cn = end - cb; if (cn > 32) cn = 32;
            int el = tid >> 3, hh = tid & 7;
            if (el < cn) {
                int s = g_csr[cb + el];
                float a = lrelu(g_as1[s * 8 + hh] + s_ad[hh]);
                s_alpha[el][hh] = __expf(a - s_max[hh]) * s_inv[hh];
                if (hh == 0) s_src[el] = s;
            }
            __syncthreads();
            for (int e = 0; e < cn; e++) {
                float2 v = *(const float2*)(g_h1 + (size_t)s_src[e] * HID1 + c);
                float kc = s_alpha[e][hch];
                accx += v.x * kc;
                accy += v.y * kc;
            }
            __syncthreads();
        }
    }

    float2 bv = *(const float2*)(bias + c);
    float ox = accx + bv.x, oy = accy + bv.y;
    ox = ox > 0.f ? ox : expm1f(ox);
    oy = oy > 0.f ? oy : expm1f(oy);
    __half hx = __float2half(ox), hy = __float2half(oy);
    *(ushort2*)(g_o1s + (size_t)n * KDIM + c) =
        make_ushort2(*(unsigned short*)&hx, *(unsigned short*)&hy);
}

// ---------------- layer2 aggregation + bias + log-softmax ----------------
__global__ void agg2_kernel(const float* __restrict__ bias, float* __restrict__ out) {
    int n = blockIdx.x;
    int tid = threadIdx.x;
    int beg = g_offs[n], end = g_offs[n + 1];
    int deg = end - beg;

    __shared__ float s_ad;
    __shared__ float s_max;
    __shared__ float s_inv;
    __shared__ unsigned s_maxi;
    __shared__ float s_sum1;
    __shared__ int   s_src[CAP2];
    __shared__ float s_alpha[CAP2];
    __shared__ float shm[8];
    __shared__ float shs[8];

    if (tid == 0) {
        s_ad = g_ad2[n];
        s_maxi = 0x007FFFFFu;
        s_sum1 = 0.f;
    }
    __syncthreads();

    float acc = 0.f;

    if (deg <= CAP2) {
        if (tid < deg) {
            int s = g_csr[beg + tid];
            s_src[tid] = s;
            s_alpha[tid] = lrelu(g_as2[s] + s_ad);
        }
        __syncthreads();
        if (tid < 32) {
            float m = -INFINITY;
            for (int e = tid; e < deg; e += 32) m = fmaxf(m, s_alpha[e]);
            m = warp_max(m);
            float ssum = 0.f;
            for (int e = tid; e < deg; e += 32) ssum += __expf(s_alpha[e] - m);
            ssum = warp_sum(ssum);
            if (tid == 0) { s_max = m; s_inv = 1.f / (ssum + 1e-16f); }
        }
        __syncthreads();
        if (tid < deg) s_alpha[tid] = __expf(s_alpha[tid] - s_max) * s_inv;
        __syncthreads();
        int e = 0;
        for (; e + 4 <= deg; e += 4) {
            float v0 = g_h2[(size_t)s_src[e + 0] * OUTC + tid];
            float v1 = g_h2[(size_t)s_src[e + 1] * OUTC + tid];
            float v2 = g_h2[(size_t)s_src[e + 2] * OUTC + tid];
            float v3 = g_h2[(size_t)s_src[e + 3] * OUTC + tid];
            acc += v0 * s_alpha[e + 0] + v1 * s_alpha[e + 1] + v2 * s_alpha[e + 2] + v3 * s_alpha[e + 3];
        }
        for (; e < deg; e++) acc += g_h2[(size_t)s_src[e] * OUTC + tid] * s_alpha[e];
    } else {
        float lmax = -INFINITY;
        for (int e = beg + tid; e < end; e += 256) {
            float a = lrelu(g_as2[g_csr[e]] + s_ad);
            lmax = fmaxf(lmax, a);
        }
        atomicMax(&s_maxi, fenc(lmax));
        __syncthreads();
        if (tid == 0) s_max = fdec(s_maxi);
        __syncthreads();
        float lsum = 0.f;
        for (int e = beg + tid; e < end; e += 256) {
            float a = lrelu(g_as2[g_csr[e]] + s_ad);
            lsum += __expf(a - s_max);
        }
        atomicAdd(&s_sum1, lsum);
        __syncthreads();
        if (tid == 0) s_inv = 1.f / (s_sum1 + 1e-16f);
        __syncthreads();
        for (int cb = beg; cb < end; cb += CAP2) {
            int cn = end - cb; if (cn > CAP2) cn = CAP2;
            if (tid < cn) {
                int s = g_csr[cb + tid];
                float a = lrelu(g_as2[s] + s_ad);
                s_alpha[tid] = __expf(a - s_max) * s_inv;
                s_src[tid] = s;
            }
            __syncthreads();
            for (int e = 0; e < cn; e++) acc += g_h2[(size_t)s_src[e] * OUTC + tid] * s_alpha[e];
            __syncthreads();
        }
    }

    float v = acc + bias[tid];
    float wm = warp_max(v);
    if ((tid & 31) == 0) shm[tid >> 5] = wm;
    __syncthreads();
    float m = shm[0];
#pragma unroll
    for (int i = 1; i < 8; i++) m = fmaxf(m, shm[i]);
    float ex = __expf(v - m);
    float ws = warp_sum(ex);
    if ((tid & 31) == 0) shs[tid >> 5] = ws;
    __syncthreads();
    float s = 0.f;
#pragma unroll
    for (int i = 0; i < 8; i++) s += shs[i];
    out[(size_t)n * OUTC + tid] = v - m - __logf(s);
}

// ---------------- launch ----------------
extern "C" void kernel_launch(void* const* d_in, const int* in_sizes, int n_in,
                              void* d_out, int out_size) {
    const float* x    = (const float*)d_in[0];
    const int*   ei   = (const int*)d_in[1];
    const float* W1   = (const float*)d_in[2];
    const float* as1  = (const float*)d_in[3];
    const float* ad1  = (const float*)d_in[4];
    const float* b1   = (const float*)d_in[5];
    const float* W2   = (const float*)d_in[6];
    const float* as2  = (const float*)d_in[7];
    const float* ad2  = (const float*)d_in[8];
    const float* b2   = (const float*)d_in[9];
    float* out = (float*)d_out;

    float *p_h1, *p_h2, *p_as1, *p_ad1, *p_as2, *p_ad2;
    __half *p_xs, *p_o1s, *p_w1t, *p_w2t;
    cudaGetSymbolAddress((void**)&p_h1, g_h1);
    cudaGetSymbolAddress((void**)&p_h2, g_h2);
    cudaGetSymbolAddress((void**)&p_as1, g_as1);
    cudaGetSymbolAddress((void**)&p_ad1, g_ad1);
    cudaGetSymbolAddress((void**)&p_as2, g_as2);
    cudaGetSymbolAddress((void**)&p_ad2, g_ad2);
    cudaGetSymbolAddress((void**)&p_xs, g_xs);
    cudaGetSymbolAddress((void**)&p_o1s, g_o1s);
    cudaGetSymbolAddress((void**)&p_w1t, g_w1t);
    cudaGetSymbolAddress((void**)&p_w2t, g_w2t);

    cudaFuncSetAttribute(mma_gemm_kernel,
                         cudaFuncAttributeMaxDynamicSharedMemorySize, GEMM_SMEM);

    // (1-3) converts (+ g_deg zero); launch #4 = layer1 GEMM (profiled)
    conv_act_kernel<<<(NN * (KDIM / 4) + 255) / 256, 256>>>(x, p_xs, NN);
    conv_w_kernel<<<(KDIM * HID1 + 255) / 256, 256>>>(W1, p_w1t, HID1);
    conv_w_kernel<<<(KDIM * OUTC + 255) / 256, 256>>>(W2, p_w2t, OUTC);

    // (4) layer1 GEMM + fused alpha1
    mma_gemm_kernel<<<dim3(HID1 / BN, (NN + BM - 1) / BM), 256, GEMM_SMEM>>>(
        p_xs, p_w1t, p_h1, NN, HID1, KDIM, as1, ad1, p_as1, p_ad1, 8);

    // (5-7) CSR build (+ alpha2 accumulator zero)
    deg_kernel<<<(NTOT + 255) / 256, 256>>>(ei);
    scan_kernel<<<1, 1024>>>();
    scatter_kernel<<<(NTOT + 255) / 256, 256>>>(ei);

    // (8) layer1 aggregation (writes fp16 directly)
    agg1_kernel<<<NN, 256>>>(b1);

    // (9) layer2 GEMM + fused alpha2 (atomic partials)
    mma_gemm_kernel<<<dim3(OUTC / BN, (NN + BM - 1) / BM), 256, GEMM_SMEM>>>(
        p_o1s, p_w2t, p_h2, NN, OUTC, KDIM, as2, ad2, p_as2, p_ad2, 1);

    // (10) layer2 aggregation + log-softmax
    agg2_kernel<<<NN, 256>>>(b2, out);
}

// round 8
// speedup vs baseline: 4.0389x; 1.0398x over previous
#include <cuda_runtime.h>
#include <cuda_fp16.h>
#include <math.h>
#include <stdint.h>

#define NN     20000
#define INC    512
#define HID1   512      // H1*HID = 8*64
#define OUTC   256
#define NE     320000
#define NTOT   (NE + NN)   // edges + self loops = 340000
#define NEGS   0.2f
#define KDIM   512
#define CAP1   96
#define CAP2   128

// ---------------- scratch ----------------
__device__ __half g_h1[(size_t)NN * HID1];   // layer1 GEMM out (fp16)
__device__ __half g_h2[(size_t)NN * OUTC];   // layer2 GEMM out (fp16)
__device__ __half g_xs[(size_t)NN * KDIM];
__device__ __half g_o1s[(size_t)NN * KDIM];
__device__ __half g_w1t[(size_t)HID1 * KDIM];
__device__ __half g_w2t[(size_t)OUTC * KDIM];
__device__ float g_as1[NN * 8];
__device__ float g_ad1[NN * 8];
__device__ float g_as2[NN];
__device__ float g_ad2[NN];
__device__ int   g_deg[NN];
__device__ int   g_offs[NN + 1];
__device__ int   g_cursor[NN];
__device__ int   g_csr[NTOT];

// ---------------- helpers ----------------
__device__ __forceinline__ float warp_sum(float v) {
#pragma unroll
    for (int o = 16; o; o >>= 1) v += __shfl_xor_sync(0xffffffffu, v, o);
    return v;
}
__device__ __forceinline__ float warp_max(float v) {
#pragma unroll
    for (int o = 16; o; o >>= 1) v = fmaxf(v, __shfl_xor_sync(0xffffffffu, v, o));
    return v;
}
__device__ __forceinline__ unsigned fenc(float f) {
    unsigned u = __float_as_uint(f);
    return (u >> 31) ? ~u : (u | 0x80000000u);
}
__device__ __forceinline__ float fdec(unsigned u) {
    return __uint_as_float((u >> 31) ? (u & 0x7fffffffu) : ~u);
}
__device__ __forceinline__ float lrelu(float a) { return a > 0.f ? a : NEGS * a; }

__device__ __forceinline__ uint32_t smem_u32(const void* p) {
    return (uint32_t)__cvta_generic_to_shared(p);
}
__device__ __forceinline__ void ldsm_x4(uint32_t& r0, uint32_t& r1, uint32_t& r2, uint32_t& r3, uint32_t addr) {
    asm volatile("ldmatrix.sync.aligned.m8n8.x4.shared.b16 {%0,%1,%2,%3}, [%4];\n"
                 : "=r"(r0), "=r"(r1), "=r"(r2), "=r"(r3) : "r"(addr));
}
__device__ __forceinline__ void cp_async16(uint32_t dst, const void* src, bool pred) {
    int sz = pred ? 16 : 0;
    asm volatile("cp.async.cg.shared.global [%0], [%1], 16, %2;\n"
                 :: "r"(dst), "l"(src), "r"(sz));
}
__device__ __forceinline__ void cp_commit() {
    asm volatile("cp.async.commit_group;\n" ::: "memory");
}

// ---------------- CSR build ----------------
__global__ void deg_kernel(const int* __restrict__ ei) {
    int i = blockIdx.x * blockDim.x + threadIdx.x;
    if (i < NN) { g_as2[i] = 0.f; g_ad2[i] = 0.f; }
    if (i < NTOT) {
        int d = (i < NE) ? ei[NE + i] : (i - NE);
        atomicAdd(&g_deg[d], 1);
    }
}
__global__ void scan_kernel() {
    __shared__ int warpsum[32];
    __shared__ int carry;
    int tid = threadIdx.x, lane = tid & 31, w = tid >> 5;
    if (tid == 0) { carry = 0; g_offs[0] = 0; }
    __syncthreads();
    for (int base = 0; base < NN; base += 1024) {
        int i = base + tid;
        int v = (i < NN) ? g_deg[i] : 0;
        int x = v;
#pragma unroll
        for (int o = 1; o < 32; o <<= 1) {
            int t = __shfl_up_sync(0xffffffffu, x, o);
            if (lane >= o) x += t;
        }
        if (lane == 31) warpsum[w] = x;
        __syncthreads();
        if (w == 0) {
            int s = warpsum[lane];
#pragma unroll
            for (int o = 1; o < 32; o <<= 1) {
                int t = __shfl_up_sync(0xffffffffu, s, o);
                if (lane >= o) s += t;
            }
            warpsum[lane] = s;
        }
        __syncthreads();
        int incl = carry + (w ? warpsum[w - 1] : 0) + x;
        if (i < NN) {
            g_offs[i + 1] = incl;
            g_cursor[i] = incl - v;
        }
        __syncthreads();
        if (tid == 1023) carry = incl;
        __syncthreads();
    }
}
__global__ void scatter_kernel(const int* __restrict__ ei) {
    int i = blockIdx.x * blockDim.x + threadIdx.x;
    if (i < NTOT) {
        int s, d;
        if (i < NE) { s = ei[i]; d = ei[NE + i]; }
        else        { s = d = i - NE; }
        int p = atomicAdd(&g_cursor[d], 1);
        g_csr[p] = s;
    }
}

// ---------------- fp16 conversions ----------------
__global__ void conv_act_kernel(const float* __restrict__ in, __half* __restrict__ out, int M) {
    int idx = blockIdx.x * blockDim.x + threadIdx.x;
    if (idx < NN) g_deg[idx] = 0;
    int total = M * (KDIM / 4);
    if (idx >= total) return;
    int c4 = idx * 4;
    float4 v = *(const float4*)(in + c4);
    __half h0 = __float2half(v.x), h1 = __float2half(v.y);
    __half h2 = __float2half(v.z), h3 = __float2half(v.w);
    *(ushort4*)(out + c4) = make_ushort4(
        *(unsigned short*)&h0, *(unsigned short*)&h1,
        *(unsigned short*)&h2, *(unsigned short*)&h3);
}
__global__ void conv_w_kernel(const float* __restrict__ in, __half* __restrict__ out, int Nw) {
    int idx = blockIdx.x * blockDim.x + threadIdx.x;
    if (idx >= KDIM * Nw) return;
    int n = idx / KDIM, k = idx % KDIM;
    out[(size_t)n * KDIM + k] = __float2half(in[(size_t)k * Nw + n]);
}

// ---------------- fp16 tensor-core GEMM (NT), BK=64, 3-stage cp.async ----------------
// C written in fp16. Fused attention-logit epilogue (fp32 accumulators).
#define BM 128
#define BN 128
#define BK 64
#define APAD 72     // halves per row (144B): ldmatrix conflict-free
#define NSTAGE 3
#define GEMM_SMEM (NSTAGE * (BM + BN) * APAD * 2)   // 110592 bytes

__global__ __launch_bounds__(256, 2) void mma_gemm_kernel(
    const __half* __restrict__ A, const __half* __restrict__ Bt,
    __half* __restrict__ C, int M, int Nc, int K,
    const float* __restrict__ asrc, const float* __restrict__ adst,
    float* __restrict__ oas, float* __restrict__ oad, int heads)
{
    extern __shared__ __half sm[];
    const int STG = (BM + BN) * APAD;

    int tid = threadIdx.x;
    int warp = tid >> 5, lane = tid & 31;
    int wm = (warp & 3) * 32;
    int wn = (warp >> 2) * 64;
    int m0 = blockIdx.y * BM, n0 = blockIdx.x * BN;
    int g = lane >> 2, t4 = lane & 3;

    int a_row = (lane & 7) + ((lane >> 3) & 1) * 8;
    int a_half = (lane >> 4) * 8;
    int b_row = (lane & 7) + ((lane >> 4) << 3);
    int b_half = ((lane >> 3) & 1) * 8;

    // load mapping: r = r0 + 32*i (i=0..3), 16B chunk cq (in halves)
    int r0 = tid >> 3;
    int cq = (tid & 7) * 8;
    bool am[4];
#pragma unroll
    for (int i = 0; i < 4; i++) am[i] = (m0 + r0 + 32 * i) < M;
    const __half* gA = A + (size_t)(m0 + r0) * K + cq;
    const __half* gB = Bt + (size_t)(n0 + r0) * K + cq;

    float acc[2][8][4];
#pragma unroll
    for (int mi = 0; mi < 2; mi++)
#pragma unroll
        for (int ni = 0; ni < 8; ni++)
#pragma unroll
            for (int j = 0; j < 4; j++) acc[mi][ni][j] = 0.f;

    int nk = K / BK;   // 8

#define ISSUE(KT) {                                                               \
        int _buf = (KT) % NSTAGE;                                                 \
        int _k0 = (KT) * BK;                                                      \
        __half* sA = sm + _buf * STG;                                             \
        __half* sB = sA + BM * APAD;                                              \
        _Pragma("unroll")                                                         \
        for (int i = 0; i < 4; i++) {                                             \
            int rr = r0 + 32 * i;                                                 \
            cp_async16(smem_u32(sA + rr * APAD + cq), gA + (size_t)32 * i * K + _k0, am[i]); \
            cp_async16(smem_u32(sB + rr * APAD + cq), gB + (size_t)32 * i * K + _k0, true);  \
        }                                                                         \
        cp_commit();                                                              \
    }

    ISSUE(0);
    ISSUE(1);

    for (int kt = 0; kt < nk; kt++) {
        asm volatile("cp.async.wait_group 1;\n" ::: "memory");
        __syncthreads();
        if (kt + 2 < nk) { ISSUE(kt + 2); }
        else             { cp_commit(); }

        __half* sA = sm + (kt % NSTAGE) * STG;
        __half* sB = sA + BM * APAD;
#pragma unroll
        for (int kk = 0; kk < 4; kk++) {
            int kb = kk * 16;
            uint32_t af[2][4];
            uint32_t bfrag[8][2];
#pragma unroll
            for (int mi = 0; mi < 2; mi++) {
                uint32_t ad = smem_u32(sA + (wm + mi * 16 + a_row) * APAD + kb + a_half);
                ldsm_x4(af[mi][0], af[mi][1], af[mi][2], af[mi][3], ad);
            }
#pragma unroll
            for (int p = 0; p < 4; p++) {
                uint32_t bd = smem_u32(sB + (wn + p * 16 + b_row) * APAD + kb + b_half);
                ldsm_x4(bfrag[2 * p][0], bfrag[2 * p][1], bfrag[2 * p + 1][0], bfrag[2 * p + 1][1], bd);
            }
#pragma unroll
            for (int mi = 0; mi < 2; mi++)
#pragma unroll
                for (int ni = 0; ni < 8; ni++) {
                    asm volatile(
                        "mma.sync.aligned.m16n8k16.row.col.f32.f16.f16.f32 "
                        "{%0,%1,%2,%3}, {%4,%5,%6,%7}, {%8,%9}, {%0,%1,%2,%3};\n"
                        : "+f"(acc[mi][ni][0]), "+f"(acc[mi][ni][1]),
                          "+f"(acc[mi][ni][2]), "+f"(acc[mi][ni][3])
                        : "r"(af[mi][0]), "r"(af[mi][1]), "r"(af[mi][2]), "r"(af[mi][3]),
                          "r"(bfrag[ni][0]), "r"(bfrag[ni][1]));
                }
        }
    }
#undef ISSUE

    // store C tile (fp16)
#pragma unroll
    for (int mi = 0; mi < 2; mi++) {
        int r = m0 + wm + mi * 16;
#pragma unroll
        for (int ni = 0; ni < 8; ni++) {
            int c = n0 + wn + ni * 8 + 2 * t4;
            if (r + g < M) {
                __half2 v0 = __floats2half2_rn(acc[mi][ni][0], acc[mi][ni][1]);
                *(__half2*)(C + (size_t)(r + g) * Nc + c) = v0;
            }
            if (r + g + 8 < M) {
                __half2 v1 = __floats2half2_rn(acc[mi][ni][2], acc[mi][ni][3]);
                *(__half2*)(C + (size_t)(r + g + 8) * Nc + c) = v1;
            }
        }
    }

    // fused attention logits (fp32 accumulators)
    if (asrc) {
#pragma unroll
        for (int mi = 0; mi < 2; mi++) {
            float s0 = 0.f, s1 = 0.f, d0 = 0.f, d1 = 0.f;
#pragma unroll
            for (int ni = 0; ni < 8; ni++) {
#pragma unroll
                for (int j = 0; j < 2; j++) {
                    int c = n0 + wn + ni * 8 + 2 * t4 + j;
                    float a_s = asrc[c], a_d = adst[c];
                    s0 += acc[mi][ni][j] * a_s;
                    d0 += acc[mi][ni][j] * a_d;
                    s1 += acc[mi][ni][j + 2] * a_s;
                    d1 += acc[mi][ni][j + 2] * a_d;
                }
            }
#pragma unroll
            for (int o = 1; o < 4; o <<= 1) {
                s0 += __shfl_xor_sync(0xffffffffu, s0, o);
                s1 += __shfl_xor_sync(0xffffffffu, s1, o);
                d0 += __shfl_xor_sync(0xffffffffu, d0, o);
                d1 += __shfl_xor_sync(0xffffffffu, d1, o);
            }
            if (t4 == 0) {
                int r0w = m0 + wm + mi * 16 + g;
                int r1w = r0w + 8;
                if (heads == 8) {
                    int head = (n0 + wn) >> 6;
                    if (r0w < M) { oas[r0w * 8 + head] = s0; oad[r0w * 8 + head] = d0; }
                    if (r1w < M) { oas[r1w * 8 + head] = s1; oad[r1w * 8 + head] = d1; }
                } else {
                    if (r0w < M) { atomicAdd(&oas[r0w], s0); atomicAdd(&oad[r0w], d0); }
                    if (r1w < M) { atomicAdd(&oas[r1w], s1); atomicAdd(&oad[r1w], d1); }
                }
            }
        }
    }
}

// ---------------- layer1 aggregation: softmax + gather(fp16) + bias + elu + fp16 ----------------
__global__ void agg1_kernel(const float* __restrict__ bias) {
    int n = blockIdx.x;
    int tid = threadIdx.x;
    int beg = g_offs[n], end = g_offs[n + 1];
    int deg = end - beg;

    __shared__ float s_ad[8];
    __shared__ float s_max[8];
    __shared__ float s_inv[8];
    __shared__ int   s_src[CAP1];
    __shared__ float s_alpha[CAP1][9];
    __shared__ unsigned s_maxi[8];
    __shared__ float s_sum8[8];

    if (tid < 8) {
        s_ad[tid] = g_ad1[n * 8 + tid];
        s_maxi[tid] = 0x007FFFFFu;
        s_sum8[tid] = 0.f;
    }
    __syncthreads();

    int c = 2 * tid;
    int hch = c >> 6;
    float accx = 0.f, accy = 0.f;

    if (deg <= CAP1) {
        for (int base = 0; base < deg; base += 32) {
            int el = base + (tid >> 3), hh = tid & 7;
            if (el < deg) {
                int s = g_csr[beg + el];
                if (hh == 0) s_src[el] = s;
                s_alpha[el][hh] = lrelu(g_as1[s * 8 + hh] + s_ad[hh]);
            }
        }
        __syncthreads();
        {
            int h = tid >> 5, l = tid & 31;
            float m = -INFINITY;
            for (int e = l; e < deg; e += 32) m = fmaxf(m, s_alpha[e][h]);
            m = warp_max(m);
            float ssum = 0.f;
            for (int e = l; e < deg; e += 32) ssum += __expf(s_alpha[e][h] - m);
            ssum = warp_sum(ssum);
            if (l == 0) { s_max[h] = m; s_inv[h] = 1.f / (ssum + 1e-16f); }
        }
        __syncthreads();
        for (int base = 0; base < deg; base += 32) {
            int el = base + (tid >> 3), hh = tid & 7;
            if (el < deg) s_alpha[el][hh] = __expf(s_alpha[el][hh] - s_max[hh]) * s_inv[hh];
        }
        __syncthreads();
        int e = 0;
        for (; e + 4 <= deg; e += 4) {
            float2 v0 = __half22float2(*(const __half2*)(g_h1 + (size_t)s_src[e + 0] * HID1 + c));
            float2 v1 = __half22float2(*(const __half2*)(g_h1 + (size_t)s_src[e + 1] * HID1 + c));
            float2 v2 = __half22float2(*(const __half2*)(g_h1 + (size_t)s_src[e + 2] * HID1 + c));
            float2 v3 = __half22float2(*(const __half2*)(g_h1 + (size_t)s_src[e + 3] * HID1 + c));
            float k0 = s_alpha[e + 0][hch], k1 = s_alpha[e + 1][hch];
            float k2 = s_alpha[e + 2][hch], k3 = s_alpha[e + 3][hch];
            accx += v0.x * k0 + v1.x * k1 + v2.x * k2 + v3.x * k3;
            accy += v0.y * k0 + v1.y * k1 + v2.y * k2 + v3.y * k3;
        }
        for (; e < deg; e++) {
            float2 v = __half22float2(*(const __half2*)(g_h1 + (size_t)s_src[e] * HID1 + c));
            float kc = s_alpha[e][hch];
            accx += v.x * kc;
            accy += v.y * kc;
        }
    } else {
        const float4* as4 = (const float4*)g_as1;
        float lmax[8];
#pragma unroll
        for (int h = 0; h < 8; h++) lmax[h] = -INFINITY;
        for (int e = beg + tid; e < end; e += 256) {
            int s = g_csr[e];
            float4 lo = as4[s * 2], hi = as4[s * 2 + 1];
            float av[8] = {lo.x, lo.y, lo.z, lo.w, hi.x, hi.y, hi.z, hi.w};
#pragma unroll
            for (int h = 0; h < 8; h++) lmax[h] = fmaxf(lmax[h], lrelu(av[h] + s_ad[h]));
        }
#pragma unroll
        for (int h = 0; h < 8; h++) atomicMax(&s_maxi[h], fenc(lmax[h]));
        __syncthreads();
        if (tid < 8) s_max[tid] = fdec(s_maxi[tid]);
        __syncthreads();
        float lsum[8];
#pragma unroll
        for (int h = 0; h < 8; h++) lsum[h] = 0.f;
        for (int e = beg + tid; e < end; e += 256) {
            int s = g_csr[e];
            float4 lo = as4[s * 2], hi = as4[s * 2 + 1];
            float av[8] = {lo.x, lo.y, lo.z, lo.w, hi.x, hi.y, hi.z, hi.w};
#pragma unroll
            for (int h = 0; h < 8; h++) lsum[h] += __expf(lrelu(av[h] + s_ad[h]) - s_max[h]);
        }
#pragma unroll
        for (int h = 0; h < 8; h++) atomicAdd(&s_sum8[h], lsum[h]);
        __syncthreads();
        if (tid < 8) s_inv[tid] = 1.f / (s_sum8[tid] + 1e-16f);
        __syncthreads();
        for (int cb = beg; cb < end; cb += 32) {
            int cn = end - cb; if (cn > 32) cn = 32;
            int el = tid >> 3, hh = tid & 7;
            if (el < cn) {
                int s = g_csr[cb + el];
                float a = lrelu(g_as1[s * 8 + hh] + s_ad[hh]);
                s_alpha[el][hh] = __expf(a - s_max[hh]) * s_inv[hh];
                if (hh == 0) s_src[el] = s;
            }
            __syncthreads();
            for (int e = 0; e < cn; e++) {
                float2 v = __half22float2(*(const __half2*)(g_h1 + (size_t)s_src[e] * HID1 + c));
                float kc = s_alpha[e][hch];
                accx += v.x * kc;
                accy += v.y * kc;
            }
            __syncthreads();
        }
    }

    float2 bv = *(const float2*)(bias + c);
    float ox = accx + bv.x, oy = accy + bv.y;
    ox = ox > 0.f ? ox : expm1f(ox);
    oy = oy > 0.f ? oy : expm1f(oy);
    __half hx = __float2half(ox), hy = __float2half(oy);
    *(ushort2*)(g_o1s + (size_t)n * KDIM + c) =
        make_ushort2(*(unsigned short*)&hx, *(unsigned short*)&hy);
}

// ---------------- layer2 aggregation (fp16 gather) + bias + log-softmax ----------------
__global__ void agg2_kernel(const float* __restrict__ bias, float* __restrict__ out) {
    int n = blockIdx.x;
    int tid = threadIdx.x;
    int beg = g_offs[n], end = g_offs[n + 1];
    int deg = end - beg;

    __shared__ float s_ad;
    __shared__ float s_max;
    __shared__ float s_inv;
    __shared__ unsigned s_maxi;
    __shared__ float s_sum1;
    __shared__ int   s_src[CAP2];
    __shared__ float s_alpha[CAP2];
    __shared__ float shm[8];
    __shared__ float shs[8];

    if (tid == 0) {
        s_ad = g_ad2[n];
        s_maxi = 0x007FFFFFu;
        s_sum1 = 0.f;
    }
    __syncthreads();

    float acc = 0.f;

    if (deg <= CAP2) {
        if (tid < deg) {
            int s = g_csr[beg + tid];
            s_src[tid] = s;
            s_alpha[tid] = lrelu(g_as2[s] + s_ad);
        }
        __syncthreads();
        if (tid < 32) {
            float m = -INFINITY;
            for (int e = tid; e < deg; e += 32) m = fmaxf(m, s_alpha[e]);
            m = warp_max(m);
            float ssum = 0.f;
            for (int e = tid; e < deg; e += 32) ssum += __expf(s_alpha[e] - m);
            ssum = warp_sum(ssum);
            if (tid == 0) { s_max = m; s_inv = 1.f / (ssum + 1e-16f); }
        }
        __syncthreads();
        if (tid < deg) s_alpha[tid] = __expf(s_alpha[tid] - s_max) * s_inv;
        __syncthreads();
        int e = 0;
        for (; e + 4 <= deg; e += 4) {
            float v0 = __half2float(g_h2[(size_t)s_src[e + 0] * OUTC + tid]);
            float v1 = __half2float(g_h2[(size_t)s_src[e + 1] * OUTC + tid]);
            float v2 = __half2float(g_h2[(size_t)s_src[e + 2] * OUTC + tid]);
            float v3 = __half2float(g_h2[(size_t)s_src[e + 3] * OUTC + tid]);
            acc += v0 * s_alpha[e + 0] + v1 * s_alpha[e + 1] + v2 * s_alpha[e + 2] + v3 * s_alpha[e + 3];
        }
        for (; e < deg; e++) acc += __half2float(g_h2[(size_t)s_src[e] * OUTC + tid]) * s_alpha[e];
    } else {
        float lmax = -INFINITY;
        for (int e = beg + tid; e < end; e += 256) {
            float a = lrelu(g_as2[g_csr[e]] + s_ad);
            lmax = fmaxf(lmax, a);
        }
        atomicMax(&s_maxi, fenc(lmax));
        __syncthreads();
        if (tid == 0) s_max = fdec(s_maxi);
        __syncthreads();
        float lsum = 0.f;
        for (int e = beg + tid; e < end; e += 256) {
            float a = lrelu(g_as2[g_csr[e]] + s_ad);
            lsum += __expf(a - s_max);
        }
        atomicAdd(&s_sum1, lsum);
        __syncthreads();
        if (tid == 0) s_inv = 1.f / (s_sum1 + 1e-16f);
        __syncthreads();
        for (int cb = beg; cb < end; cb += CAP2) {
            int cn = end - cb; if (cn > CAP2) cn = CAP2;
            if (tid < cn) {
                int s = g_csr[cb + tid];
                float a = lrelu(g_as2[s] + s_ad);
                s_alpha[tid] = __expf(a - s_max) * s_inv;
                s_src[tid] = s;
            }
            __syncthreads();
            for (int e = 0; e < cn; e++)
                acc += __half2float(g_h2[(size_t)s_src[e] * OUTC + tid]) * s_alpha[e];
            __syncthreads();
        }
    }

    float v = acc + bias[tid];
    float wm = warp_max(v);
    if ((tid & 31) == 0) shm[tid >> 5] = wm;
    __syncthreads();
    float m = shm[0];
#pragma unroll
    for (int i = 1; i < 8; i++) m = fmaxf(m, shm[i]);
    float ex = __expf(v - m);
    float ws = warp_sum(ex);
    if ((tid & 31) == 0) shs[tid >> 5] = ws;
    __syncthreads();
    float s = 0.f;
#pragma unroll
    for (int i = 0; i < 8; i++) s += shs[i];
    out[(size_t)n * OUTC + tid] = v - m - __logf(s);
}

// ---------------- launch ----------------
extern "C" void kernel_launch(void* const* d_in, const int* in_sizes, int n_in,
                              void* d_out, int out_size) {
    const float* x    = (const float*)d_in[0];
    const int*   ei   = (const int*)d_in[1];
    const float* W1   = (const float*)d_in[2];
    const float* as1  = (const float*)d_in[3];
    const float* ad1  = (const float*)d_in[4];
    const float* b1   = (const float*)d_in[5];
    const float* W2   = (const float*)d_in[6];
    const float* as2  = (const float*)d_in[7];
    const float* ad2  = (const float*)d_in[8];
    const float* b2   = (const float*)d_in[9];
    float* out = (float*)d_out;

    float *p_as1, *p_ad1, *p_as2, *p_ad2;
    __half *p_h1, *p_h2, *p_xs, *p_o1s, *p_w1t, *p_w2t;
    cudaGetSymbolAddress((void**)&p_h1, g_h1);
    cudaGetSymbolAddress((void**)&p_h2, g_h2);
    cudaGetSymbolAddress((void**)&p_as1, g_as1);
    cudaGetSymbolAddress((void**)&p_ad1, g_ad1);
    cudaGetSymbolAddress((void**)&p_as2, g_as2);
    cudaGetSymbolAddress((void**)&p_ad2, g_ad2);
    cudaGetSymbolAddress((void**)&p_xs, g_xs);
    cudaGetSymbolAddress((void**)&p_o1s, g_o1s);
    cudaGetSymbolAddress((void**)&p_w1t, g_w1t);
    cudaGetSymbolAddress((void**)&p_w2t, g_w2t);

    cudaFuncSetAttribute(mma_gemm_kernel,
                         cudaFuncAttributeMaxDynamicSharedMemorySize, GEMM_SMEM);

    // (1-3) converts (+ g_deg zero); launch #4 = layer1 GEMM (profiled)
    conv_act_kernel<<<(NN * (KDIM / 4) + 255) / 256, 256>>>(x, p_xs, NN);
    conv_w_kernel<<<(KDIM * HID1 + 255) / 256, 256>>>(W1, p_w1t, HID1);
    conv_w_kernel<<<(KDIM * OUTC + 255) / 256, 256>>>(W2, p_w2t, OUTC);

    // (4) layer1 GEMM + fused alpha1
    mma_gemm_kernel<<<dim3(HID1 / BN, (NN + BM - 1) / BM), 256, GEMM_SMEM>>>(
        p_xs, p_w1t, p_h1, NN, HID1, KDIM, as1, ad1, p_as1, p_ad1, 8);

    // (5-7) CSR build (+ alpha2 accumulator zero)
    deg_kernel<<<(NTOT + 255) / 256, 256>>>(ei);
    scan_kernel<<<1, 1024>>>();
    scatter_kernel<<<(NTOT + 255) / 256, 256>>>(ei);

    // (8) layer1 aggregation
    agg1_kernel<<<NN, 256>>>(b1);

    // (9) layer2 GEMM + fused alpha2
    mma_gemm_kernel<<<dim3(OUTC / BN, (NN + BM - 1) / BM), 256, GEMM_SMEM>>>(
        p_o1s, p_w2t, p_h2, NN, OUTC, KDIM, as2, ad2, p_as2, p_ad2, 1);

    // (10) layer2 aggregation + log-softmax
    agg2_kernel<<<NN, 256>>>(b2, out);
}